// round 12
// baseline (speedup 1.0000x reference)
#include <cuda_runtime.h>
#include <cuda_bf16.h>
#include <math.h>
#include <stdint.h>

#define Nn 65536
#define Ee 262144
#define Kk 8
#define NMPc 2
#define DEPTHc 2
#define Hh 4
#define Dd 256
#define PHp 64
#define EDd 64

// ---------------- scratch (device globals; no allocation allowed) ----------------
__device__ __align__(16) float g_x    [(size_t)Nn * Dd];
__device__ __align__(16) float g_Y    [(size_t)2 * Nn * Dd];        // per-mp
__device__ __align__(16) float g_NP   [(size_t)Nn * Dd];
__device__ __align__(16) float g_EW2  [(size_t)2 * 2 * Ee * Dd];    // per-mp: [0]=EW, [1]=EWnb0
__device__ __align__(16) float g_eB   [(size_t)Ee * Dd];
__device__ __align__(16) float g_nag  [(size_t)Hh * Nn * Dd];
// per-mp doubled small state
__device__ __align__(16) float g_pn   [(size_t)2 * Nn * Hh];
__device__ __align__(16) float g_be   [(size_t)2 * Ee * Hh];   // be (L0), then qe1 (L1)
__device__ __align__(16) float g_ps   [(size_t)2 * Nn * Hh];
__device__ __align__(16) float g_qe   [(size_t)2 * Ee * Hh];   // qe0
__device__ __align__(16) float g_WpT  [2 * Dd * Dd];           // [0]=Wp0^T, [1]=Wp1^T
__device__ __align__(16) float g_Bt5  [2 * 5 * Dd * Dd];
__device__ __align__(16) float g_WfYS [2 * 2 * Dd * Dd];       // per-mp [0]=WfY, [1]=WfS
__device__ __align__(16) float g_Wc   [2 * 2 * Dd * EDd];
__device__ __align__(16) float g_avf  [2 * 2 * Hh * EDd];
__device__ __align__(16) float g_av256[2 * 2 * Hh * Dd];

// ---------------- side stream + events (static init: before harness mem checkpoints) ----------------
namespace {
struct SideStream {
    cudaStream_t s;
    cudaEvent_t evWpT, evF1, evRD0, evRD1, evG1;
    SideStream() {
        cudaStreamCreateWithFlags(&s, cudaStreamNonBlocking);
        cudaEventCreateWithFlags(&evWpT, cudaEventDisableTiming);
        cudaEventCreateWithFlags(&evF1,  cudaEventDisableTiming);
        cudaEventCreateWithFlags(&evRD0, cudaEventDisableTiming);
        cudaEventCreateWithFlags(&evRD1, cudaEventDisableTiming);
        cudaEventCreateWithFlags(&evG1,  cudaEventDisableTiming);
    }
};
SideStream g_ss;
}

// ---------------- HMMA helper ----------------
__device__ __forceinline__ void mma16816(float* c, const uint32_t* a, uint32_t b0, uint32_t b1) {
    asm volatile("mma.sync.aligned.m16n8k16.row.col.f32.bf16.bf16.f32 "
                 "{%0,%1,%2,%3}, {%4,%5,%6,%7}, {%8,%9}, {%0,%1,%2,%3};"
                 : "+f"(c[0]), "+f"(c[1]), "+f"(c[2]), "+f"(c[3])
                 : "r"(a[0]), "r"(a[1]), "r"(a[2]), "r"(a[3]), "r"(b0), "r"(b1));
}

__device__ __forceinline__ void split4(float4 v, uint2& hi, uint2& lo) {
    __nv_bfloat16 h0 = __float2bfloat16(v.x), h1 = __float2bfloat16(v.y);
    __nv_bfloat16 h2 = __float2bfloat16(v.z), h3 = __float2bfloat16(v.w);
    __nv_bfloat16 l0 = __float2bfloat16(v.x - __bfloat162float(h0));
    __nv_bfloat16 l1 = __float2bfloat16(v.y - __bfloat162float(h1));
    __nv_bfloat16 l2 = __float2bfloat16(v.z - __bfloat162float(h2));
    __nv_bfloat16 l3 = __float2bfloat16(v.w - __bfloat162float(h3));
    union { __nv_bfloat162 b[2]; uint2 u; } ph, pl;
    ph.b[0] = __nv_bfloat162(h0, h1); ph.b[1] = __nv_bfloat162(h2, h3);
    pl.b[0] = __nv_bfloat162(l0, l1); pl.b[1] = __nv_bfloat162(l2, l3);
    hi = ph.u; lo = pl.u;
}

__device__ __forceinline__ float elu1(float x) { return x > 0.f ? x : expm1f(x); }

// ---------------- pipelined bf16-split HMMA GEMM with optional node-combine epilogues ----------------
template <int BN, int EPI>
__global__ __launch_bounds__(256) void gemm_mma(const float* __restrict__ A,
                                                const float* __restrict__ Bt,
                                                float* __restrict__ C,
                                                int K, int ldc,
                                                size_t sAz, size_t sBz, size_t sCz,
                                                const float* __restrict__ a1v,
                                                const float* __restrict__ NPp,
                                                float* __restrict__ outp,
                                                float* __restrict__ xoutp,
                                                float* __restrict__ psout)
{
    constexpr int NT  = BN / 16;
    constexpr int NB  = BN / 32;
    constexpr int ASZ = 128 * 40;
    constexpr int BSZ = BN * 40;
    constexpr int BUFE = 2 * ASZ + 2 * BSZ;
    extern __shared__ uint16_t sm[];

    A  += blockIdx.z * sAz;
    Bt += blockIdx.z * sBz;
    C  += blockIdx.z * sCz;

    int t = threadIdx.x, wid = t >> 5, lane = t & 31;
    int g = lane >> 2, tg = lane & 3;
    int wm = (wid >> 1) * 32;
    int wn = (wid & 1) * (BN / 2);
    size_t m0 = (size_t)blockIdx.x * 128;
    size_t n0 = (size_t)blockIdx.y * BN;
    const float* Abase = A + m0 * K;
    const float* Bbase = Bt + n0 * K;

    float acc[2][NT][4];
    #pragma unroll
    for (int mt = 0; mt < 2; mt++)
        #pragma unroll
        for (int nt = 0; nt < NT; nt++)
            #pragma unroll
            for (int j = 0; j < 4; j++) acc[mt][nt][j] = 0.f;

    float4 pa[4], pb[NB];
    auto ldAB = [&](int kb) {
        #pragma unroll
        for (int i = 0; i < 4; i++) {
            int id = t + 256 * i, r = id >> 3, c4 = id & 7;
            pa[i] = *(const float4*)(Abase + (size_t)r * K + kb * 32 + c4 * 4);
        }
        #pragma unroll
        for (int i = 0; i < NB; i++) {
            int id = t + 256 * i, r = id >> 3, c4 = id & 7;
            pb[i] = *(const float4*)(Bbase + (size_t)r * K + kb * 32 + c4 * 4);
        }
    };
    auto stAB = [&](int buf) {
        uint16_t* bAh = sm + buf * BUFE;
        uint16_t* bAl = bAh + ASZ;
        uint16_t* bBh = bAl + ASZ;
        uint16_t* bBl = bBh + BSZ;
        #pragma unroll
        for (int i = 0; i < 4; i++) {
            int id = t + 256 * i, r = id >> 3, c4 = id & 7;
            uint2 hi, lo; split4(pa[i], hi, lo);
            *(uint2*)&bAh[r * 40 + c4 * 4] = hi;
            *(uint2*)&bAl[r * 40 + c4 * 4] = lo;
        }
        #pragma unroll
        for (int i = 0; i < NB; i++) {
            int id = t + 256 * i, r = id >> 3, c4 = id & 7;
            uint2 hi, lo; split4(pb[i], hi, lo);
            *(uint2*)&bBh[r * 40 + c4 * 4] = hi;
            *(uint2*)&bBl[r * 40 + c4 * 4] = lo;
        }
    };
    auto domma = [&](int buf) {
        const uint16_t* bAh = sm + buf * BUFE;
        const uint16_t* bAl = bAh + ASZ;
        const uint16_t* bBh = bAl + ASZ;
        const uint16_t* bBl = bBh + BSZ;
        #pragma unroll
        for (int ks = 0; ks < 2; ks++) {
            int kc = ks * 16 + tg * 2;
            uint32_t ah[2][4], al_[2][4];
            #pragma unroll
            for (int mt = 0; mt < 2; mt++) {
                int row = wm + mt * 16 + g;
                ah[mt][0]  = *(const uint32_t*)&bAh[row * 40 + kc];
                ah[mt][1]  = *(const uint32_t*)&bAh[(row + 8) * 40 + kc];
                ah[mt][2]  = *(const uint32_t*)&bAh[row * 40 + kc + 8];
                ah[mt][3]  = *(const uint32_t*)&bAh[(row + 8) * 40 + kc + 8];
                al_[mt][0] = *(const uint32_t*)&bAl[row * 40 + kc];
                al_[mt][1] = *(const uint32_t*)&bAl[(row + 8) * 40 + kc];
                al_[mt][2] = *(const uint32_t*)&bAl[row * 40 + kc + 8];
                al_[mt][3] = *(const uint32_t*)&bAl[(row + 8) * 40 + kc + 8];
            }
            #pragma unroll
            for (int nt = 0; nt < NT; nt++) {
                int col = wn + nt * 8 + g;
                uint32_t bh0 = *(const uint32_t*)&bBh[col * 40 + kc];
                uint32_t bh1 = *(const uint32_t*)&bBh[col * 40 + kc + 8];
                uint32_t bl0 = *(const uint32_t*)&bBl[col * 40 + kc];
                uint32_t bl1 = *(const uint32_t*)&bBl[col * 40 + kc + 8];
                #pragma unroll
                for (int mt = 0; mt < 2; mt++) {
                    mma16816(acc[mt][nt], ah[mt],  bh0, bh1);
                    mma16816(acc[mt][nt], al_[mt], bh0, bh1);
                    mma16816(acc[mt][nt], ah[mt],  bl0, bl1);
                }
            }
        }
    };

    int nkb = K >> 5;
    ldAB(0);
    stAB(0);
    __syncthreads();
    for (int kb = 0; kb < nkb; kb++) {
        int cur = kb & 1;
        if (kb + 1 < nkb) ldAB(kb + 1);
        domma(cur);
        if (kb + 1 < nkb) stAB(cur ^ 1);
        __syncthreads();
    }

    if (EPI == 0) {
        #pragma unroll
        for (int mt = 0; mt < 2; mt++) {
            size_t row = m0 + wm + mt * 16 + g;
            #pragma unroll
            for (int nt = 0; nt < NT; nt++) {
                size_t col = n0 + wn + nt * 8 + tg * 2;
                *(float2*)(C + row * ldc + col)       = make_float2(acc[mt][nt][0], acc[mt][nt][1]);
                *(float2*)(C + (row + 8) * ldc + col) = make_float2(acc[mt][nt][2], acc[mt][nt][3]);
            }
        }
    } else {
        constexpr int Lofs = (EPI == 3) ? 0 : Dd;
        float* sa1 = (float*)sm;
        if (EPI == 3) {
            for (int i = t; i < 512; i += 256) {
                int h = i >> 7, c = i & 127;
                sa1[i] = a1v[(size_t)h * Dd + n0 + c];
            }
            __syncthreads();
        }
        float qp[4][Hh];
        if (EPI == 3) {
            #pragma unroll
            for (int j = 0; j < 4; j++)
                #pragma unroll
                for (int h = 0; h < Hh; h++) qp[j][h] = 0.f;
        }
        #pragma unroll
        for (int mt = 0; mt < 2; mt++) {
            #pragma unroll
            for (int rp = 0; rp < 2; rp++) {
                size_t grow = m0 + wm + mt * 16 + g + rp * 8;
                #pragma unroll
                for (int nt = 0; nt < NT; nt++) {
                    int cloc = wn + nt * 8 + tg * 2;
                    size_t gc = n0 + cloc;
                    float2 np = *(const float2*)(NPp + grow * Dd + gc);
                    float r0 = elu1(acc[mt][nt][rp * 2 + 0] + np.x);
                    float r1 = elu1(acc[mt][nt][rp * 2 + 1] + np.y);
                    *(float2*)(outp + grow * (DEPTHc * Dd) + Lofs + gc) = make_float2(r0, r1);
                    if (EPI == 3) {
                        *(float2*)(xoutp + grow * Dd + gc) = make_float2(r0, r1);
                        #pragma unroll
                        for (int h = 0; h < Hh; h++)
                            qp[mt * 2 + rp][h] += r0 * sa1[h * 128 + cloc] + r1 * sa1[h * 128 + cloc + 1];
                    }
                }
            }
        }
        if (EPI == 3) {
            #pragma unroll
            for (int j = 0; j < 4; j++)
                #pragma unroll
                for (int h = 0; h < Hh; h++) {
                    qp[j][h] += __shfl_xor_sync(0xffffffffu, qp[j][h], 1);
                    qp[j][h] += __shfl_xor_sync(0xffffffffu, qp[j][h], 2);
                }
            if (tg == 0) {
                #pragma unroll
                for (int mt = 0; mt < 2; mt++)
                    #pragma unroll
                    for (int rp = 0; rp < 2; rp++) {
                        size_t grow = m0 + wm + mt * 16 + g + rp * 8;
                        #pragma unroll
                        for (int h = 0; h < Hh; h++)
                            atomicAdd(&psout[grow * Hh + h], qp[mt * 2 + rp][h]);
                    }
            }
        }
    }
}

// ---------------- packing / folding ----------------
__global__ void pack2d2(const float* __restrict__ s0, const float* __restrict__ s1,
                        float* __restrict__ dst) {
    int z = blockIdx.z;
    const float* src = z ? s1 : s0;
    int id = blockIdx.x * 256 + threadIdx.x;
    int c = id % Dd, k = id / Dd;
    dst[(size_t)z * Dd * Dd + (size_t)c * Dd + k] = src[id];
}

__global__ void pack_hdp5(const float* __restrict__ s0, const float* __restrict__ s1,
                          const float* __restrict__ s2, const float* __restrict__ s3,
                          const float* __restrict__ s4, float* __restrict__ dst) {
    int z = blockIdx.z;
    const float* src = (z == 0) ? s0 : (z == 1) ? s1 : (z == 2) ? s2 : (z == 3) ? s3 : s4;
    int id = blockIdx.x * 256 + threadIdx.x;
    int p = id % PHp, d = (id / PHp) % Dd, h = id / (PHp * Dd);
    dst[(size_t)z * Dd * Dd + (size_t)(h * PHp + p) * Dd + d] = src[id];
}

__global__ __launch_bounds__(256) void foldW2(const float* __restrict__ Wep,
                                              const float* __restrict__ Bt5,
                                              float* __restrict__ Wc)
{
    __shared__ float sb[256];
    __shared__ float sred[4][64];
    int z = blockIdx.z;
    const float* BtW = Bt5 + (size_t)(z == 0 ? 0 : 2) * Dd * Dd;
    float* dst = Wc + (size_t)z * Dd * EDd;
    int c = blockIdx.x, t = threadIdx.x;
    sb[t] = BtW[(size_t)c * 256 + t];
    __syncthreads();
    int j = t & 63, q = t >> 6;
    const float* wr  = Wep + (size_t)j * 256 + q * 64;
    const float* sbp = sb + q * 64;
    float acc = 0.f;
    #pragma unroll 16
    for (int d = 0; d < 64; d++) acc += wr[d] * sbp[d];
    sred[q][j] = acc;
    __syncthreads();
    if (t < 64) dst[(size_t)c * 64 + t] = sred[0][t] + sred[1][t] + sred[2][t] + sred[3][t];
}

__global__ __launch_bounds__(256) void foldW256_2(const float* __restrict__ WpT,
                                                  const float* __restrict__ Bt5,
                                                  float* __restrict__ Wf)
{
    __shared__ float sb[256];
    int z = blockIdx.z;
    const float* WpTz = WpT + (size_t)(z == 0 ? 1 : 0) * Dd * Dd;
    const float* BtW = Bt5 + (size_t)z * Dd * Dd;
    float* dst = Wf + (size_t)z * Dd * Dd;
    int c = blockIdx.x, d = threadIdx.x;
    sb[d] = BtW[(size_t)c * 256 + d];
    __syncthreads();
    float acc = 0.f;
    #pragma unroll 4
    for (int dp = 0; dp < 256; dp++) acc += WpTz[(size_t)dp * 256 + d] * sb[dp];
    dst[(size_t)c * 256 + d] = acc;
}

__global__ __launch_bounds__(256) void foldA256_2(const float* __restrict__ WpT,
                                                  const float* __restrict__ an,
                                                  const float* __restrict__ as,
                                                  float* __restrict__ outp)
{
    __shared__ float sa[256];
    int z = blockIdx.z;
    const float* WpTz = WpT + (size_t)(z == 0 ? 1 : 0) * Dd * Dd;
    const float* a = (z == 0) ? an : as;
    int h = blockIdx.x, d = threadIdx.x;
    sa[d] = a[(size_t)h * 256 + d];
    __syncthreads();
    float acc = 0.f;
    #pragma unroll 4
    for (int dp = 0; dp < 256; dp++) acc += WpTz[(size_t)dp * 256 + d] * sa[dp];
    outp[(size_t)z * Hh * Dd + (size_t)h * 256 + d] = acc;
}

__global__ __launch_bounds__(256) void foldA2p(const float* __restrict__ Wep,
                                               const float* __restrict__ a1,
                                               const float* __restrict__ a2,
                                               float* __restrict__ outp)
{
    __shared__ float s1[256], s2[256];
    __shared__ float r1[4][64], r2[4][64];
    int h = blockIdx.x, t = threadIdx.x;
    s1[t] = a1[(size_t)h * 256 + t];
    s2[t] = a2[(size_t)h * 256 + t];
    __syncthreads();
    int j = t & 63, q = t >> 6;
    const float* wr = Wep + (size_t)j * 256 + q * 64;
    float A = 0.f, B = 0.f;
    #pragma unroll 16
    for (int d = 0; d < 64; d++) { float w = wr[d]; A += w * s1[q * 64 + d]; B += w * s2[q * 64 + d]; }
    r1[q][j] = A; r2[q][j] = B;
    __syncthreads();
    if (t < 64) outp[h * 64 + t] = r1[0][t] + r1[1][t] + r1[2][t] + r1[3][t];
    else if (t < 128) {
        int j2 = t - 64;
        outp[Hh * 64 + h * 64 + j2] = r2[0][j2] + r2[1][j2] + r2[2][j2] + r2[3][j2];
    }
}

// ---------------- dual row-dot (D=256) ----------------
__global__ __launch_bounds__(256) void rowdot2(const float* __restrict__ X,
                                               const float* __restrict__ avec1,
                                               const float* __restrict__ avec2,
                                               float* __restrict__ P1,
                                               float* __restrict__ P2)
{
    __shared__ float sa[2 * Hh * Dd];
    int t = threadIdx.x;
    for (int i = t; i < Hh * Dd; i += 256) { sa[i] = avec1[i]; sa[Hh * Dd + i] = avec2[i]; }
    __syncthreads();
    int row = blockIdx.x * 8 + (t >> 5);
    int lane = t & 31;
    const float* xr = X + (size_t)row * Dd;
    float a1[Hh] = {}, a2[Hh] = {};
    #pragma unroll
    for (int j = 0; j < 8; j++) {
        float xv = xr[lane + 32 * j];
        #pragma unroll
        for (int h = 0; h < Hh; h++) {
            a1[h] += sa[h * Dd + lane + 32 * j] * xv;
            a2[h] += sa[Hh * Dd + h * Dd + lane + 32 * j] * xv;
        }
    }
    #pragma unroll
    for (int h = 0; h < Hh; h++) {
        #pragma unroll
        for (int o = 16; o > 0; o >>= 1) {
            a1[h] += __shfl_down_sync(0xffffffffu, a1[h], o);
            a2[h] += __shfl_down_sync(0xffffffffu, a2[h], o);
        }
    }
    if (lane == 0) {
        #pragma unroll
        for (int h = 0; h < Hh; h++) {
            P1[(size_t)row * Hh + h] = a1[h];
            P2[(size_t)row * Hh + h] = a2[h];
        }
    }
}

// ---------------- dual row-dot over D=64 rows (edge_emb) ----------------
__global__ __launch_bounds__(256) void rowdot2_64(const float* __restrict__ X,
                                                  const float* __restrict__ avf,
                                                  float* __restrict__ P1,
                                                  float* __restrict__ P2)
{
    __shared__ float sa[2 * Hh * 64];
    int t = threadIdx.x;
    for (int i = t; i < 2 * Hh * 64; i += 256) sa[i] = avf[i];
    __syncthreads();
    int row = blockIdx.x * 8 + (t >> 5);
    int lane = t & 31;
    const float* xr = X + (size_t)row * 64;
    float x0 = xr[lane], x1 = xr[lane + 32];
    float a1[Hh], a2[Hh];
    #pragma unroll
    for (int h = 0; h < Hh; h++) {
        a1[h] = sa[h * 64 + lane] * x0 + sa[h * 64 + lane + 32] * x1;
        a2[h] = sa[256 + h * 64 + lane] * x0 + sa[256 + h * 64 + lane + 32] * x1;
    }
    #pragma unroll
    for (int h = 0; h < Hh; h++) {
        #pragma unroll
        for (int o = 16; o > 0; o >>= 1) {
            a1[h] += __shfl_down_sync(0xffffffffu, a1[h], o);
            a2[h] += __shfl_down_sync(0xffffffffu, a2[h], o);
        }
    }
    if (lane == 0) {
        #pragma unroll
        for (int h = 0; h < Hh; h++) {
            P1[(size_t)row * Hh + h] = a1[h];
            P2[(size_t)row * Hh + h] = a2[h];
        }
    }
}

// ---------------- edge combine + fused qe1 ----------------
__global__ __launch_bounds__(256) void edge_comb_q(const int* __restrict__ ena,
                                                   const float* __restrict__ pn,
                                                   const float* __restrict__ be,
                                                   const float* __restrict__ EW,
                                                   const float* __restrict__ Y,
                                                   const float* __restrict__ a1v,
                                                   float* __restrict__ eout,
                                                   float* __restrict__ qe1)
{
    __shared__ float sa1[Hh * Dd];
    __shared__ float sred[4][2][Hh];
    int t = threadIdx.x;
    for (int i = t; i < Hh * Dd; i += 256) sa1[i] = a1v[i];
    __syncthreads();

    int e0 = blockIdx.x * 4;
    int el = t >> 6, c4 = t & 63, h = c4 >> 4;
    int e = e0 + el;
    int u = ena[2 * e], v = ena[2 * e + 1];
    float b = be[(size_t)e * Hh + h];
    float s0 = pn[(size_t)u * Hh + h] + b;
    float s1 = pn[(size_t)v * Hh + h] + b;
    s0 = s0 > 0.f ? s0 : 0.2f * s0;
    s1 = s1 > 0.f ? s1 : 0.2f * s1;
    float m = fmaxf(s0, s1);
    float x0 = __expf(s0 - m), x1 = __expf(s1 - m);
    float inv = 1.f / (x0 + x1);
    float al0 = x0 * inv, al1 = x1 * inv;
    float4 ew = *(const float4*)(EW + (size_t)e * Dd + c4 * 4);
    float4 yu = *(const float4*)(Y + (size_t)u * Dd + c4 * 4);
    float4 yv = *(const float4*)(Y + (size_t)v * Dd + c4 * 4);
    float4 r;
    r.x = elu1(ew.x + al0 * yu.x + al1 * yv.x);
    r.y = elu1(ew.y + al0 * yu.y + al1 * yv.y);
    r.z = elu1(ew.z + al0 * yu.z + al1 * yv.z);
    r.w = elu1(ew.w + al0 * yu.w + al1 * yv.w);
    *(float4*)(eout + (size_t)e * Dd + c4 * 4) = r;

    float p[Hh];
    #pragma unroll
    for (int hh = 0; hh < Hh; hh++) {
        const float* av = sa1 + hh * Dd + c4 * 4;
        p[hh] = r.x * av[0] + r.y * av[1] + r.z * av[2] + r.w * av[3];
    }
    #pragma unroll
    for (int hh = 0; hh < Hh; hh++) {
        #pragma unroll
        for (int o = 16; o > 0; o >>= 1) p[hh] += __shfl_down_sync(0xffffffffu, p[hh], o);
    }
    int wl = t & 31, whalf = (t >> 5) & 1;
    if (wl == 0) {
        #pragma unroll
        for (int hh = 0; hh < Hh; hh++) sred[el][whalf][hh] = p[hh];
    }
    __syncthreads();
    if (t < 16) {
        int ee = t >> 2, hh = t & 3;
        qe1[(size_t)(e0 + ee) * Hh + hh] = sred[ee][0][hh] + sred[ee][1][hh];
    }
}

// ---------------- L0 node agg, projected ----------------
__global__ __launch_bounds__(256) void nagp_kernel(const int* __restrict__ n2e,
                                                   const float* __restrict__ ps,
                                                   const float* __restrict__ qe,
                                                   const float* __restrict__ EWnb,
                                                   float* __restrict__ NP)
{
    int t = threadIdx.x, w = t >> 5, lane = t & 31;
    int n = blockIdx.x * 8 + w;
    int idx[Kk];
    #pragma unroll
    for (int k = 0; k < Kk; k++) idx[k] = n2e[(size_t)n * Kk + k];
    float al[Hh][Kk];
    #pragma unroll
    for (int h = 0; h < Hh; h++) {
        float bs = ps[(size_t)n * Hh + h];
        float s[Kk]; float m = -1e30f;
        #pragma unroll
        for (int k = 0; k < Kk; k++) {
            float sv = bs + qe[(size_t)idx[k] * Hh + h];
            sv = sv > 0.f ? sv : 0.2f * sv;
            s[k] = sv; m = fmaxf(m, sv);
        }
        float sum = 0.f;
        #pragma unroll
        for (int k = 0; k < Kk; k++) { s[k] = __expf(s[k] - m); sum += s[k]; }
        float inv = 1.f / sum;
        #pragma unroll
        for (int k = 0; k < Kk; k++) al[h][k] = s[k] * inv;
    }
    int h0 = lane >> 4, h1 = 2 + (lane >> 4);
    float4 a0 = make_float4(0.f, 0.f, 0.f, 0.f), a1 = a0;
    #pragma unroll
    for (int k = 0; k < Kk; k++) {
        const float4* er = (const float4*)(EWnb + (size_t)idx[k] * Dd);
        float4 ea = er[lane], eb = er[32 + lane];
        float w0 = al[h0][k], w1 = al[h1][k];
        a0.x += w0 * ea.x; a0.y += w0 * ea.y; a0.z += w0 * ea.z; a0.w += w0 * ea.w;
        a1.x += w1 * eb.x; a1.y += w1 * eb.y; a1.z += w1 * eb.z; a1.w += w1 * eb.w;
    }
    *(float4*)(NP + (size_t)n * Dd + lane * 4)       = a0;
    *(float4*)(NP + (size_t)n * Dd + 128 + lane * 4) = a1;
}

// ---------------- L1 node aggregation (full) ----------------
__global__ __launch_bounds__(256) void nag_kernel(const int* __restrict__ n2e,
                                                  const float* __restrict__ ps,
                                                  const float* __restrict__ qe,
                                                  const float* __restrict__ edges,
                                                  float* __restrict__ nag)
{
    int t = threadIdx.x, w = t >> 5, lane = t & 31;
    int n = blockIdx.x * 8 + w;
    int idx[Kk];
    #pragma unroll
    for (int k = 0; k < Kk; k++) idx[k] = n2e[(size_t)n * Kk + k];
    float al[Hh][Kk];
    #pragma unroll
    for (int h = 0; h < Hh; h++) {
        float bs = ps[(size_t)n * Hh + h];
        float s[Kk]; float m = -1e30f;
        #pragma unroll
        for (int k = 0; k < Kk; k++) {
            float sv = bs + qe[(size_t)idx[k] * Hh + h];
            sv = sv > 0.f ? sv : 0.2f * sv;
            s[k] = sv; m = fmaxf(m, sv);
        }
        float sum = 0.f;
        #pragma unroll
        for (int k = 0; k < Kk; k++) { s[k] = __expf(s[k] - m); sum += s[k]; }
        float inv = 1.f / sum;
        #pragma unroll
        for (int k = 0; k < Kk; k++) al[h][k] = s[k] * inv;
    }
    float4 a0[Hh] = {}, a1[Hh] = {};
    #pragma unroll
    for (int k = 0; k < Kk; k++) {
        const float4* er = (const float4*)(edges + (size_t)idx[k] * Dd);
        float4 ea = er[lane], eb = er[32 + lane];
        #pragma unroll
        for (int h = 0; h < Hh; h++) {
            float a = al[h][k];
            a0[h].x += a * ea.x; a0[h].y += a * ea.y; a0[h].z += a * ea.z; a0[h].w += a * ea.w;
            a1[h].x += a * eb.x; a1[h].y += a * eb.y; a1[h].z += a * eb.z; a1[h].w += a * eb.w;
        }
    }
    #pragma unroll
    for (int h = 0; h < Hh; h++) {
        float* dst = nag + ((size_t)h * Nn + n) * Dd;
        *(float4*)(dst + lane * 4) = a0[h];
        *(float4*)(dst + 128 + lane * 4) = a1[h];
    }
}

// ---------------- launcher ----------------
extern "C" void kernel_launch(void* const* d_in, const int* in_sizes, int n_in,
                              void* d_out, int out_size)
{
    (void)in_sizes; (void)n_in; (void)out_size;
    const float* feats    = (const float*)d_in[0];
    const float* edge_emb = (const float*)d_in[1];
    const int*   ena      = (const int*)d_in[2];
    const int*   n2e      = (const int*)d_in[3];
    const float* Wp0      = (const float*)d_in[4];
    const float* Wp1      = (const float*)d_in[5];
    const float* Wep      = (const float*)d_in[6];
    const float* a_e      = (const float*)d_in[7];
    const float* a_n      = (const float*)d_in[8];
    const float* W_e      = (const float*)d_in[9];
    const float* a_s      = (const float*)d_in[10];
    const float* a_edge   = (const float*)d_in[11];
    const float* W_self   = (const float*)d_in[12];
    const float* W_nb     = (const float*)d_in[13];
    float* out = (float*)d_out;

    float *xb, *YB, *NP, *EW2B, *eB, *nag, *pnB, *beB, *psB, *qeB;
    float *WpT, *Bt5B, *WfYSB, *WcB, *avfB, *av256B;
    cudaGetSymbolAddress((void**)&xb,     g_x);
    cudaGetSymbolAddress((void**)&YB,     g_Y);
    cudaGetSymbolAddress((void**)&NP,     g_NP);
    cudaGetSymbolAddress((void**)&EW2B,   g_EW2);
    cudaGetSymbolAddress((void**)&eB,     g_eB);
    cudaGetSymbolAddress((void**)&nag,    g_nag);
    cudaGetSymbolAddress((void**)&pnB,    g_pn);
    cudaGetSymbolAddress((void**)&beB,    g_be);
    cudaGetSymbolAddress((void**)&psB,    g_ps);
    cudaGetSymbolAddress((void**)&qeB,    g_qe);
    cudaGetSymbolAddress((void**)&WpT,    g_WpT);
    cudaGetSymbolAddress((void**)&Bt5B,   g_Bt5);
    cudaGetSymbolAddress((void**)&WfYSB,  g_WfYS);
    cudaGetSymbolAddress((void**)&WcB,    g_Wc);
    cudaGetSymbolAddress((void**)&avfB,   g_avf);
    cudaGetSymbolAddress((void**)&av256B, g_av256);

    constexpr int SM128 = 2 * (2 * 128 * 40 + 2 * 128 * 40) * 2;
    constexpr int SM64  = 2 * (2 * 128 * 40 + 2 * 64 * 40) * 2;
    cudaFuncSetAttribute(gemm_mma<128, 0>, cudaFuncAttributeMaxDynamicSharedMemorySize, SM128);
    cudaFuncSetAttribute(gemm_mma<128, 2>, cudaFuncAttributeMaxDynamicSharedMemorySize, SM128);
    cudaFuncSetAttribute(gemm_mma<128, 3>, cudaFuncAttributeMaxDynamicSharedMemorySize, SM128);
    cudaFuncSetAttribute(gemm_mma<64, 0>,  cudaFuncAttributeMaxDynamicSharedMemorySize, SM64);

    dim3 blk(256);
    dim3 gN(Nn / 128, 2);
    dim3 gE2(Ee / 128, 2, 2);
    dim3 gH(Nn / 128, 1, Hh);

    cudaStream_t ms = 0;
    cudaStream_t s2 = g_ss.s;

    auto Bt5_   = [&](int mp) { return Bt5B   + (size_t)mp * 5 * Dd * Dd; };
    auto Wc_    = [&](int mp) { return WcB    + (size_t)mp * 2 * Dd * EDd; };
    auto WfYS_  = [&](int mp) { return WfYSB  + (size_t)mp * 2 * Dd * Dd; };
    auto avf_   = [&](int mp) { return avfB   + (size_t)mp * 2 * Hh * EDd; };
    auto av256_ = [&](int mp) { return av256B + (size_t)mp * 2 * Hh * Dd; };
    auto pn_    = [&](int mp) { return pnB + (size_t)mp * Nn * Hh; };
    auto ps_    = [&](int mp) { return psB + (size_t)mp * Nn * Hh; };
    auto be_    = [&](int mp) { return beB + (size_t)mp * Ee * Hh; };
    auto qe_    = [&](int mp) { return qeB + (size_t)mp * Ee * Hh; };
    auto Y_     = [&](int mp) { return YB + (size_t)mp * Nn * Dd; };
    auto EW2_   = [&](int mp) { return EW2B + (size_t)mp * 2 * Ee * Dd; };

    // ---- s2: input-only folds first (no deps) ----
    for (int mp = 0; mp < NMPc; mp++) {
        size_t pl0 = (size_t)(mp * DEPTHc + 0);
        foldA2p<<<Hh, blk, 0, s2>>>(Wep + (size_t)mp * EDd * Dd,
                                    a_e + pl0 * Hh * Dd, a_edge + pl0 * Hh * Dd, avf_(mp));
    }

    // ---- ms: WpT -> mp0 weight folds (minimal critical path) ----
    pack2d2<<<dim3(256, 1, 2), blk, 0, ms>>>(Wp0, Wp1, WpT);
    cudaEventRecord(g_ss.evWpT, ms);

    pack_hdp5<<<dim3(256, 1, 5), blk, 0, ms>>>(W_e    + 0 * Hh * Dd * PHp,
                                               W_self + 0 * Hh * Dd * PHp,
                                               W_nb   + 0 * Hh * Dd * PHp,
                                               W_self + 1 * Hh * Dd * PHp,
                                               W_nb   + 1 * Hh * Dd * PHp, Bt5_(0));
    foldW256_2<<<dim3(256, 1, 2), blk, 0, ms>>>(WpT, Bt5_(0), WfYS_(0));
    foldW2<<<dim3(256, 1, 2), blk, 0, ms>>>(Wep, Bt5_(0), Wc_(0));

    // ---- s2: attention-vector folds + rowdots + mp1 weight folds + mp1 front GEMMs ----
    cudaStreamWaitEvent(s2, g_ss.evWpT, 0);
    {
        size_t pl0m0 = 0, pl0m1 = (size_t)DEPTHc;
        foldA256_2<<<dim3(Hh, 1, 2), blk, 0, s2>>>(WpT, a_n + pl0m0 * Hh * Dd, a_s + pl0m0 * Hh * Dd, av256_(0));
        rowdot2<<<Nn / 8, blk, 0, s2>>>(feats, av256_(0), av256_(0) + Hh * Dd, pn_(0), ps_(0));
        rowdot2_64<<<Ee / 8, blk, 0, s2>>>(edge_emb, avf_(0), be_(0), qe_(0));
        cudaEventRecord(g_ss.evRD0, s2);

        foldA256_2<<<dim3(Hh, 1, 2), blk, 0, s2>>>(WpT, a_n + pl0m1 * Hh * Dd, a_s + pl0m1 * Hh * Dd, av256_(1));
        rowdot2<<<Nn / 8, blk, 0, s2>>>(feats, av256_(1), av256_(1) + Hh * Dd, pn_(1), ps_(1));
        rowdot2_64<<<Ee / 8, blk, 0, s2>>>(edge_emb + (size_t)Ee * EDd, avf_(1), be_(1), qe_(1));
        cudaEventRecord(g_ss.evRD1, s2);

        size_t pl0 = (size_t)DEPTHc, pl1 = (size_t)DEPTHc + 1;
        pack_hdp5<<<dim3(256, 1, 5), blk, 0, s2>>>(W_e    + pl0 * Hh * Dd * PHp,
                                                   W_self + pl0 * Hh * Dd * PHp,
                                                   W_nb   + pl0 * Hh * Dd * PHp,
                                                   W_self + pl1 * Hh * Dd * PHp,
                                                   W_nb   + pl1 * Hh * Dd * PHp, Bt5_(1));
        foldW256_2<<<dim3(256, 1, 2), blk, 0, s2>>>(WpT, Bt5_(1), WfYS_(1));
        foldW2<<<dim3(256, 1, 2), blk, 0, s2>>>(Wep + (size_t)EDd * Dd, Bt5_(1), Wc_(1));
        cudaEventRecord(g_ss.evF1, s2);

        // mp1 front GEMMs on s2: overlap with mp0's memory-bound tail on ms
        gemm_mma<128, 0><<<gN, blk, SM128, s2>>>(feats, WfYS_(1), Y_(1), Dd, Dd, 0, 0, 0,
                                                 nullptr, nullptr, nullptr, nullptr, nullptr);
        gemm_mma<128, 0><<<gE2, blk, SM128, s2>>>(edge_emb + (size_t)Ee * EDd, Wc_(1), EW2_(1), EDd, Dd,
                                                  0, (size_t)Dd * EDd, (size_t)Ee * Dd,
                                                  nullptr, nullptr, nullptr, nullptr, nullptr);
        cudaEventRecord(g_ss.evG1, s2);
    }

    for (int mp = 0; mp < NMPc; mp++) {
        const int*   ena_mp = ena + (size_t)mp * Ee * 2;
        const int*   n2e_mp = n2e + (size_t)mp * Nn * Kk;
        const float* emb_mp = edge_emb + (size_t)mp * Ee * EDd;
        float* outmp = out + (size_t)mp * Nn * DEPTHc * Dd;
        size_t pl1 = (size_t)(mp * DEPTHc + 1);
        float* EW    = EW2_(mp);
        float* EWnb0 = EW2_(mp) + (size_t)Ee * Dd;

        if (mp == 0) {
            // ---- Y0 = feats @ WfY0 ----
            gemm_mma<128, 0><<<gN, blk, SM128, ms>>>(feats, WfYS_(0), Y_(0), Dd, Dd, 0, 0, 0,
                                                     nullptr, nullptr, nullptr, nullptr, nullptr);
            // ---- EW0 + EWnb0_0 (z=2) ----
            gemm_mma<128, 0><<<gE2, blk, SM128, ms>>>(emb_mp, Wc_(0), EW2_(0), EDd, Dd,
                                                      0, (size_t)Dd * EDd, (size_t)Ee * Dd,
                                                      nullptr, nullptr, nullptr, nullptr, nullptr);
            cudaStreamWaitEvent(ms, g_ss.evRD0, 0);
        } else {
            cudaStreamWaitEvent(ms, g_ss.evG1, 0);   // Y1/EW1 computed on s2 (rowdots done before them)
        }

        // ---- edge combine (+ fused qe1 into be_(mp)) ----
        edge_comb_q<<<Ee / 4, blk, 0, ms>>>(ena_mp, pn_(mp), be_(mp), EW, Y_(mp),
                                            a_edge + pl1 * Hh * Dd, eB, be_(mp));

        // ---- L0 node aggregator (projected) ----
        nagp_kernel<<<Nn / 8, blk, 0, ms>>>(n2e_mp, ps_(mp), qe_(mp), EWnb0, NP);

        // ---- fused S GEMM: elu(feats@WfS + NP) -> out, xb; ps_L1 atomics ----
        cudaMemsetAsync(ps_(mp), 0, (size_t)Nn * Hh * sizeof(float), ms);
        gemm_mma<128, 3><<<gN, blk, SM128, ms>>>(feats, WfYS_(mp) + Dd * Dd, nullptr, Dd, Dd, 0, 0, 0,
                                                 a_s + pl1 * Hh * Dd, NP, outmp, xb, ps_(mp));

        // ---- L1 node aggregator ----
        nag_kernel<<<Nn / 8, blk, 0, ms>>>(n2e_mp, ps_(mp), be_(mp), eB, nag);
        gemm_mma<64, 0><<<gH, blk, SM64, ms>>>(nag, Bt5_(mp) + (size_t)4 * Dd * Dd, NP, Dd, Dd,
                                               (size_t)Nn * Dd, (size_t)PHp * Dd, (size_t)PHp,
                                               nullptr, nullptr, nullptr, nullptr, nullptr);

        // ---- fused final GEMM: elu(xb@Wself1 + NP) -> out[:, Dd:] ----
        gemm_mma<128, 2><<<gN, blk, SM128, ms>>>(xb, Bt5_(mp) + (size_t)3 * Dd * Dd, nullptr, Dd, Dd, 0, 0, 0,
                                                 nullptr, NP, outmp, nullptr, nullptr);
    }
}

// round 14
// speedup vs baseline: 1.0179x; 1.0179x over previous
#include <cuda_runtime.h>
#include <cuda_bf16.h>
#include <math.h>
#include <stdint.h>

#define Nn 65536
#define Ee 262144
#define Kk 8
#define NMPc 2
#define DEPTHc 2
#define Hh 4
#define Dd 256
#define PHp 64
#define EDd 64

// ---------------- scratch (device globals; no allocation allowed) ----------------
__device__ __align__(16) float g_x    [(size_t)Nn * Dd];
__device__ __align__(16) float g_Y    [(size_t)2 * Nn * Dd];        // per-mp
__device__ __align__(16) float g_NP   [(size_t)Nn * Dd];
__device__ __align__(16) float g_EW2  [(size_t)2 * 2 * Ee * Dd];    // per-mp: [0]=EW, [1]=EWnb0
__device__ __align__(16) float g_eB   [(size_t)Ee * Dd];
__device__ __align__(16) float g_nag  [(size_t)Hh * Nn * Dd];
// per-mp doubled small state
__device__ __align__(16) float g_pn   [(size_t)2 * Nn * Hh];
__device__ __align__(16) float g_be   [(size_t)2 * Ee * Hh];   // be (L0), then qe1 (L1)
__device__ __align__(16) float g_ps   [(size_t)2 * Nn * Hh];
__device__ __align__(16) float g_qe   [(size_t)2 * Ee * Hh];   // qe0
__device__ __align__(16) float g_WpT  [2 * Dd * Dd];           // [0]=Wp0^T, [1]=Wp1^T
__device__ __align__(16) float g_Bt5  [2 * 5 * Dd * Dd];
__device__ __align__(16) float g_WfYS [2 * 2 * Dd * Dd];       // per-mp [0]=WfY, [1]=WfS
__device__ __align__(16) float g_Wc   [2 * 2 * Dd * EDd];
__device__ __align__(16) float g_avf  [2 * 2 * Hh * EDd];
__device__ __align__(16) float g_av256[2 * 2 * Hh * Dd];

// ---------------- side stream + events (static init: before harness mem checkpoints) ----------------
namespace {
struct SideStream {
    cudaStream_t s;
    cudaEvent_t evWpT, evRD0, evG1, evMS0;
    SideStream() {
        cudaStreamCreateWithFlags(&s, cudaStreamNonBlocking);
        cudaEventCreateWithFlags(&evWpT, cudaEventDisableTiming);
        cudaEventCreateWithFlags(&evRD0, cudaEventDisableTiming);
        cudaEventCreateWithFlags(&evG1,  cudaEventDisableTiming);
        cudaEventCreateWithFlags(&evMS0, cudaEventDisableTiming);
    }
};
SideStream g_ss;
}

// ---------------- HMMA helper ----------------
__device__ __forceinline__ void mma16816(float* c, const uint32_t* a, uint32_t b0, uint32_t b1) {
    asm volatile("mma.sync.aligned.m16n8k16.row.col.f32.bf16.bf16.f32 "
                 "{%0,%1,%2,%3}, {%4,%5,%6,%7}, {%8,%9}, {%0,%1,%2,%3};"
                 : "+f"(c[0]), "+f"(c[1]), "+f"(c[2]), "+f"(c[3])
                 : "r"(a[0]), "r"(a[1]), "r"(a[2]), "r"(a[3]), "r"(b0), "r"(b1));
}

__device__ __forceinline__ void split4(float4 v, uint2& hi, uint2& lo) {
    __nv_bfloat16 h0 = __float2bfloat16(v.x), h1 = __float2bfloat16(v.y);
    __nv_bfloat16 h2 = __float2bfloat16(v.z), h3 = __float2bfloat16(v.w);
    __nv_bfloat16 l0 = __float2bfloat16(v.x - __bfloat162float(h0));
    __nv_bfloat16 l1 = __float2bfloat16(v.y - __bfloat162float(h1));
    __nv_bfloat16 l2 = __float2bfloat16(v.z - __bfloat162float(h2));
    __nv_bfloat16 l3 = __float2bfloat16(v.w - __bfloat162float(h3));
    union { __nv_bfloat162 b[2]; uint2 u; } ph, pl;
    ph.b[0] = __nv_bfloat162(h0, h1); ph.b[1] = __nv_bfloat162(h2, h3);
    pl.b[0] = __nv_bfloat162(l0, l1); pl.b[1] = __nv_bfloat162(l2, l3);
    hi = ph.u; lo = pl.u;
}

__device__ __forceinline__ float elu1(float x) { return x > 0.f ? x : expm1f(x); }

// ---------------- pipelined bf16-split HMMA GEMM with optional node-combine epilogues ----------------
template <int BN, int EPI>
__global__ __launch_bounds__(256) void gemm_mma(const float* __restrict__ A,
                                                const float* __restrict__ Bt,
                                                float* __restrict__ C,
                                                int K, int ldc,
                                                size_t sAz, size_t sBz, size_t sCz,
                                                const float* __restrict__ a1v,
                                                const float* __restrict__ NPp,
                                                float* __restrict__ outp,
                                                float* __restrict__ xoutp,
                                                float* __restrict__ psout)
{
    constexpr int NT  = BN / 16;
    constexpr int NB  = BN / 32;
    constexpr int ASZ = 128 * 40;
    constexpr int BSZ = BN * 40;
    constexpr int BUFE = 2 * ASZ + 2 * BSZ;
    extern __shared__ uint16_t sm[];

    A  += blockIdx.z * sAz;
    Bt += blockIdx.z * sBz;
    C  += blockIdx.z * sCz;

    int t = threadIdx.x, wid = t >> 5, lane = t & 31;
    int g = lane >> 2, tg = lane & 3;
    int wm = (wid >> 1) * 32;
    int wn = (wid & 1) * (BN / 2);
    size_t m0 = (size_t)blockIdx.x * 128;
    size_t n0 = (size_t)blockIdx.y * BN;
    const float* Abase = A + m0 * K;
    const float* Bbase = Bt + n0 * K;

    float acc[2][NT][4];
    #pragma unroll
    for (int mt = 0; mt < 2; mt++)
        #pragma unroll
        for (int nt = 0; nt < NT; nt++)
            #pragma unroll
            for (int j = 0; j < 4; j++) acc[mt][nt][j] = 0.f;

    float4 pa[4], pb[NB];
    auto ldAB = [&](int kb) {
        #pragma unroll
        for (int i = 0; i < 4; i++) {
            int id = t + 256 * i, r = id >> 3, c4 = id & 7;
            pa[i] = *(const float4*)(Abase + (size_t)r * K + kb * 32 + c4 * 4);
        }
        #pragma unroll
        for (int i = 0; i < NB; i++) {
            int id = t + 256 * i, r = id >> 3, c4 = id & 7;
            pb[i] = *(const float4*)(Bbase + (size_t)r * K + kb * 32 + c4 * 4);
        }
    };
    auto stAB = [&](int buf) {
        uint16_t* bAh = sm + buf * BUFE;
        uint16_t* bAl = bAh + ASZ;
        uint16_t* bBh = bAl + ASZ;
        uint16_t* bBl = bBh + BSZ;
        #pragma unroll
        for (int i = 0; i < 4; i++) {
            int id = t + 256 * i, r = id >> 3, c4 = id & 7;
            uint2 hi, lo; split4(pa[i], hi, lo);
            *(uint2*)&bAh[r * 40 + c4 * 4] = hi;
            *(uint2*)&bAl[r * 40 + c4 * 4] = lo;
        }
        #pragma unroll
        for (int i = 0; i < NB; i++) {
            int id = t + 256 * i, r = id >> 3, c4 = id & 7;
            uint2 hi, lo; split4(pb[i], hi, lo);
            *(uint2*)&bBh[r * 40 + c4 * 4] = hi;
            *(uint2*)&bBl[r * 40 + c4 * 4] = lo;
        }
    };
    auto domma = [&](int buf) {
        const uint16_t* bAh = sm + buf * BUFE;
        const uint16_t* bAl = bAh + ASZ;
        const uint16_t* bBh = bAl + ASZ;
        const uint16_t* bBl = bBh + BSZ;
        #pragma unroll
        for (int ks = 0; ks < 2; ks++) {
            int kc = ks * 16 + tg * 2;
            uint32_t ah[2][4], al_[2][4];
            #pragma unroll
            for (int mt = 0; mt < 2; mt++) {
                int row = wm + mt * 16 + g;
                ah[mt][0]  = *(const uint32_t*)&bAh[row * 40 + kc];
                ah[mt][1]  = *(const uint32_t*)&bAh[(row + 8) * 40 + kc];
                ah[mt][2]  = *(const uint32_t*)&bAh[row * 40 + kc + 8];
                ah[mt][3]  = *(const uint32_t*)&bAh[(row + 8) * 40 + kc + 8];
                al_[mt][0] = *(const uint32_t*)&bAl[row * 40 + kc];
                al_[mt][1] = *(const uint32_t*)&bAl[(row + 8) * 40 + kc];
                al_[mt][2] = *(const uint32_t*)&bAl[row * 40 + kc + 8];
                al_[mt][3] = *(const uint32_t*)&bAl[(row + 8) * 40 + kc + 8];
            }
            #pragma unroll
            for (int nt = 0; nt < NT; nt++) {
                int col = wn + nt * 8 + g;
                uint32_t bh0 = *(const uint32_t*)&bBh[col * 40 + kc];
                uint32_t bh1 = *(const uint32_t*)&bBh[col * 40 + kc + 8];
                uint32_t bl0 = *(const uint32_t*)&bBl[col * 40 + kc];
                uint32_t bl1 = *(const uint32_t*)&bBl[col * 40 + kc + 8];
                #pragma unroll
                for (int mt = 0; mt < 2; mt++) {
                    mma16816(acc[mt][nt], ah[mt],  bh0, bh1);
                    mma16816(acc[mt][nt], al_[mt], bh0, bh1);
                    mma16816(acc[mt][nt], ah[mt],  bl0, bl1);
                }
            }
        }
    };

    int nkb = K >> 5;
    ldAB(0);
    stAB(0);
    __syncthreads();
    for (int kb = 0; kb < nkb; kb++) {
        int cur = kb & 1;
        if (kb + 1 < nkb) ldAB(kb + 1);
        domma(cur);
        if (kb + 1 < nkb) stAB(cur ^ 1);
        __syncthreads();
    }

    if (EPI == 0) {
        #pragma unroll
        for (int mt = 0; mt < 2; mt++) {
            size_t row = m0 + wm + mt * 16 + g;
            #pragma unroll
            for (int nt = 0; nt < NT; nt++) {
                size_t col = n0 + wn + nt * 8 + tg * 2;
                *(float2*)(C + row * ldc + col)       = make_float2(acc[mt][nt][0], acc[mt][nt][1]);
                *(float2*)(C + (row + 8) * ldc + col) = make_float2(acc[mt][nt][2], acc[mt][nt][3]);
            }
        }
    } else {
        constexpr int Lofs = (EPI == 3) ? 0 : Dd;
        float* sa1 = (float*)sm;
        if (EPI == 3) {
            for (int i = t; i < 512; i += 256) {
                int h = i >> 7, c = i & 127;
                sa1[i] = a1v[(size_t)h * Dd + n0 + c];
            }
            __syncthreads();
        }
        float qp[4][Hh];
        if (EPI == 3) {
            #pragma unroll
            for (int j = 0; j < 4; j++)
                #pragma unroll
                for (int h = 0; h < Hh; h++) qp[j][h] = 0.f;
        }
        #pragma unroll
        for (int mt = 0; mt < 2; mt++) {
            #pragma unroll
            for (int rp = 0; rp < 2; rp++) {
                size_t grow = m0 + wm + mt * 16 + g + rp * 8;
                #pragma unroll
                for (int nt = 0; nt < NT; nt++) {
                    int cloc = wn + nt * 8 + tg * 2;
                    size_t gc = n0 + cloc;
                    float2 np = *(const float2*)(NPp + grow * Dd + gc);
                    float r0 = elu1(acc[mt][nt][rp * 2 + 0] + np.x);
                    float r1 = elu1(acc[mt][nt][rp * 2 + 1] + np.y);
                    *(float2*)(outp + grow * (DEPTHc * Dd) + Lofs + gc) = make_float2(r0, r1);
                    if (EPI == 3) {
                        *(float2*)(xoutp + grow * Dd + gc) = make_float2(r0, r1);
                        #pragma unroll
                        for (int h = 0; h < Hh; h++)
                            qp[mt * 2 + rp][h] += r0 * sa1[h * 128 + cloc] + r1 * sa1[h * 128 + cloc + 1];
                    }
                }
            }
        }
        if (EPI == 3) {
            #pragma unroll
            for (int j = 0; j < 4; j++)
                #pragma unroll
                for (int h = 0; h < Hh; h++) {
                    qp[j][h] += __shfl_xor_sync(0xffffffffu, qp[j][h], 1);
                    qp[j][h] += __shfl_xor_sync(0xffffffffu, qp[j][h], 2);
                }
            if (tg == 0) {
                #pragma unroll
                for (int mt = 0; mt < 2; mt++)
                    #pragma unroll
                    for (int rp = 0; rp < 2; rp++) {
                        size_t grow = m0 + wm + mt * 16 + g + rp * 8;
                        #pragma unroll
                        for (int h = 0; h < Hh; h++)
                            atomicAdd(&psout[grow * Hh + h], qp[mt * 2 + rp][h]);
                    }
            }
        }
    }
}

// ---------------- packing / folding ----------------
__global__ void pack2d2(const float* __restrict__ s0, const float* __restrict__ s1,
                        float* __restrict__ dst) {
    int z = blockIdx.z;
    const float* src = z ? s1 : s0;
    int id = blockIdx.x * 256 + threadIdx.x;
    int c = id % Dd, k = id / Dd;
    dst[(size_t)z * Dd * Dd + (size_t)c * Dd + k] = src[id];
}

__global__ void pack_hdp5(const float* __restrict__ s0, const float* __restrict__ s1,
                          const float* __restrict__ s2, const float* __restrict__ s3,
                          const float* __restrict__ s4, float* __restrict__ dst) {
    int z = blockIdx.z;
    const float* src = (z == 0) ? s0 : (z == 1) ? s1 : (z == 2) ? s2 : (z == 3) ? s3 : s4;
    int id = blockIdx.x * 256 + threadIdx.x;
    int p = id % PHp, d = (id / PHp) % Dd, h = id / (PHp * Dd);
    dst[(size_t)z * Dd * Dd + (size_t)(h * PHp + p) * Dd + d] = src[id];
}

__global__ __launch_bounds__(256) void foldW2(const float* __restrict__ Wep,
                                              const float* __restrict__ Bt5,
                                              float* __restrict__ Wc)
{
    __shared__ float sb[256];
    __shared__ float sred[4][64];
    int z = blockIdx.z;
    const float* BtW = Bt5 + (size_t)(z == 0 ? 0 : 2) * Dd * Dd;
    float* dst = Wc + (size_t)z * Dd * EDd;
    int c = blockIdx.x, t = threadIdx.x;
    sb[t] = BtW[(size_t)c * 256 + t];
    __syncthreads();
    int j = t & 63, q = t >> 6;
    const float* wr  = Wep + (size_t)j * 256 + q * 64;
    const float* sbp = sb + q * 64;
    float acc = 0.f;
    #pragma unroll 16
    for (int d = 0; d < 64; d++) acc += wr[d] * sbp[d];
    sred[q][j] = acc;
    __syncthreads();
    if (t < 64) dst[(size_t)c * 64 + t] = sred[0][t] + sred[1][t] + sred[2][t] + sred[3][t];
}

__global__ __launch_bounds__(256) void foldW256_2(const float* __restrict__ WpT,
                                                  const float* __restrict__ Bt5,
                                                  float* __restrict__ Wf)
{
    __shared__ float sb[256];
    int z = blockIdx.z;
    const float* WpTz = WpT + (size_t)(z == 0 ? 1 : 0) * Dd * Dd;
    const float* BtW = Bt5 + (size_t)z * Dd * Dd;
    float* dst = Wf + (size_t)z * Dd * Dd;
    int c = blockIdx.x, d = threadIdx.x;
    sb[d] = BtW[(size_t)c * 256 + d];
    __syncthreads();
    float acc = 0.f;
    #pragma unroll 4
    for (int dp = 0; dp < 256; dp++) acc += WpTz[(size_t)dp * 256 + d] * sb[dp];
    dst[(size_t)c * 256 + d] = acc;
}

__global__ __launch_bounds__(256) void foldA256_2(const float* __restrict__ WpT,
                                                  const float* __restrict__ an,
                                                  const float* __restrict__ as,
                                                  float* __restrict__ outp)
{
    __shared__ float sa[256];
    int z = blockIdx.z;
    const float* WpTz = WpT + (size_t)(z == 0 ? 1 : 0) * Dd * Dd;
    const float* a = (z == 0) ? an : as;
    int h = blockIdx.x, d = threadIdx.x;
    sa[d] = a[(size_t)h * 256 + d];
    __syncthreads();
    float acc = 0.f;
    #pragma unroll 4
    for (int dp = 0; dp < 256; dp++) acc += WpTz[(size_t)dp * 256 + d] * sa[dp];
    outp[(size_t)z * Hh * Dd + (size_t)h * 256 + d] = acc;
}

__global__ __launch_bounds__(256) void foldA2p(const float* __restrict__ Wep,
                                               const float* __restrict__ a1,
                                               const float* __restrict__ a2,
                                               float* __restrict__ outp)
{
    __shared__ float s1[256], s2[256];
    __shared__ float r1[4][64], r2[4][64];
    int h = blockIdx.x, t = threadIdx.x;
    s1[t] = a1[(size_t)h * 256 + t];
    s2[t] = a2[(size_t)h * 256 + t];
    __syncthreads();
    int j = t & 63, q = t >> 6;
    const float* wr = Wep + (size_t)j * 256 + q * 64;
    float A = 0.f, B = 0.f;
    #pragma unroll 16
    for (int d = 0; d < 64; d++) { float w = wr[d]; A += w * s1[q * 64 + d]; B += w * s2[q * 64 + d]; }
    r1[q][j] = A; r2[q][j] = B;
    __syncthreads();
    if (t < 64) outp[h * 64 + t] = r1[0][t] + r1[1][t] + r1[2][t] + r1[3][t];
    else if (t < 128) {
        int j2 = t - 64;
        outp[Hh * 64 + h * 64 + j2] = r2[0][j2] + r2[1][j2] + r2[2][j2] + r2[3][j2];
    }
}

// ---------------- dual row-dot (D=256) ----------------
__global__ __launch_bounds__(256) void rowdot2(const float* __restrict__ X,
                                               const float* __restrict__ avec1,
                                               const float* __restrict__ avec2,
                                               float* __restrict__ P1,
                                               float* __restrict__ P2)
{
    __shared__ float sa[2 * Hh * Dd];
    int t = threadIdx.x;
    for (int i = t; i < Hh * Dd; i += 256) { sa[i] = avec1[i]; sa[Hh * Dd + i] = avec2[i]; }
    __syncthreads();
    int row = blockIdx.x * 8 + (t >> 5);
    int lane = t & 31;
    const float* xr = X + (size_t)row * Dd;
    float a1[Hh] = {}, a2[Hh] = {};
    #pragma unroll
    for (int j = 0; j < 8; j++) {
        float xv = xr[lane + 32 * j];
        #pragma unroll
        for (int h = 0; h < Hh; h++) {
            a1[h] += sa[h * Dd + lane + 32 * j] * xv;
            a2[h] += sa[Hh * Dd + h * Dd + lane + 32 * j] * xv;
        }
    }
    #pragma unroll
    for (int h = 0; h < Hh; h++) {
        #pragma unroll
        for (int o = 16; o > 0; o >>= 1) {
            a1[h] += __shfl_down_sync(0xffffffffu, a1[h], o);
            a2[h] += __shfl_down_sync(0xffffffffu, a2[h], o);
        }
    }
    if (lane == 0) {
        #pragma unroll
        for (int h = 0; h < Hh; h++) {
            P1[(size_t)row * Hh + h] = a1[h];
            P2[(size_t)row * Hh + h] = a2[h];
        }
    }
}

// ---------------- dual row-dot over D=64 rows (edge_emb) ----------------
__global__ __launch_bounds__(256) void rowdot2_64(const float* __restrict__ X,
                                                  const float* __restrict__ avf,
                                                  float* __restrict__ P1,
                                                  float* __restrict__ P2)
{
    __shared__ float sa[2 * Hh * 64];
    int t = threadIdx.x;
    for (int i = t; i < 2 * Hh * 64; i += 256) sa[i] = avf[i];
    __syncthreads();
    int row = blockIdx.x * 8 + (t >> 5);
    int lane = t & 31;
    const float* xr = X + (size_t)row * 64;
    float x0 = xr[lane], x1 = xr[lane + 32];
    float a1[Hh], a2[Hh];
    #pragma unroll
    for (int h = 0; h < Hh; h++) {
        a1[h] = sa[h * 64 + lane] * x0 + sa[h * 64 + lane + 32] * x1;
        a2[h] = sa[256 + h * 64 + lane] * x0 + sa[256 + h * 64 + lane + 32] * x1;
    }
    #pragma unroll
    for (int h = 0; h < Hh; h++) {
        #pragma unroll
        for (int o = 16; o > 0; o >>= 1) {
            a1[h] += __shfl_down_sync(0xffffffffu, a1[h], o);
            a2[h] += __shfl_down_sync(0xffffffffu, a2[h], o);
        }
    }
    if (lane == 0) {
        #pragma unroll
        for (int h = 0; h < Hh; h++) {
            P1[(size_t)row * Hh + h] = a1[h];
            P2[(size_t)row * Hh + h] = a2[h];
        }
    }
}

// ---------------- edge combine + fused qe1 ----------------
__global__ __launch_bounds__(256) void edge_comb_q(const int* __restrict__ ena,
                                                   const float* __restrict__ pn,
                                                   const float* __restrict__ be,
                                                   const float* __restrict__ EW,
                                                   const float* __restrict__ Y,
                                                   const float* __restrict__ a1v,
                                                   float* __restrict__ eout,
                                                   float* __restrict__ qe1)
{
    __shared__ float sa1[Hh * Dd];
    __shared__ float sred[4][2][Hh];
    int t = threadIdx.x;
    for (int i = t; i < Hh * Dd; i += 256) sa1[i] = a1v[i];
    __syncthreads();

    int e0 = blockIdx.x * 4;
    int el = t >> 6, c4 = t & 63, h = c4 >> 4;
    int e = e0 + el;
    int u = ena[2 * e], v = ena[2 * e + 1];
    float b = be[(size_t)e * Hh + h];
    float s0 = pn[(size_t)u * Hh + h] + b;
    float s1 = pn[(size_t)v * Hh + h] + b;
    s0 = s0 > 0.f ? s0 : 0.2f * s0;
    s1 = s1 > 0.f ? s1 : 0.2f * s1;
    float m = fmaxf(s0, s1);
    float x0 = __expf(s0 - m), x1 = __expf(s1 - m);
    float inv = 1.f / (x0 + x1);
    float al0 = x0 * inv, al1 = x1 * inv;
    float4 ew = *(const float4*)(EW + (size_t)e * Dd + c4 * 4);
    float4 yu = *(const float4*)(Y + (size_t)u * Dd + c4 * 4);
    float4 yv = *(const float4*)(Y + (size_t)v * Dd + c4 * 4);
    float4 r;
    r.x = elu1(ew.x + al0 * yu.x + al1 * yv.x);
    r.y = elu1(ew.y + al0 * yu.y + al1 * yv.y);
    r.z = elu1(ew.z + al0 * yu.z + al1 * yv.z);
    r.w = elu1(ew.w + al0 * yu.w + al1 * yv.w);
    *(float4*)(eout + (size_t)e * Dd + c4 * 4) = r;

    float p[Hh];
    #pragma unroll
    for (int hh = 0; hh < Hh; hh++) {
        const float* av = sa1 + hh * Dd + c4 * 4;
        p[hh] = r.x * av[0] + r.y * av[1] + r.z * av[2] + r.w * av[3];
    }
    #pragma unroll
    for (int hh = 0; hh < Hh; hh++) {
        #pragma unroll
        for (int o = 16; o > 0; o >>= 1) p[hh] += __shfl_down_sync(0xffffffffu, p[hh], o);
    }
    int wl = t & 31, whalf = (t >> 5) & 1;
    if (wl == 0) {
        #pragma unroll
        for (int hh = 0; hh < Hh; hh++) sred[el][whalf][hh] = p[hh];
    }
    __syncthreads();
    if (t < 16) {
        int ee = t >> 2, hh = t & 3;
        qe1[(size_t)(e0 + ee) * Hh + hh] = sred[ee][0][hh] + sred[ee][1][hh];
    }
}

// ---------------- L0 node agg, projected ----------------
__global__ __launch_bounds__(256) void nagp_kernel(const int* __restrict__ n2e,
                                                   const float* __restrict__ ps,
                                                   const float* __restrict__ qe,
                                                   const float* __restrict__ EWnb,
                                                   float* __restrict__ NP)
{
    int t = threadIdx.x, w = t >> 5, lane = t & 31;
    int n = blockIdx.x * 8 + w;
    int idx[Kk];
    #pragma unroll
    for (int k = 0; k < Kk; k++) idx[k] = n2e[(size_t)n * Kk + k];
    float al[Hh][Kk];
    #pragma unroll
    for (int h = 0; h < Hh; h++) {
        float bs = ps[(size_t)n * Hh + h];
        float s[Kk]; float m = -1e30f;
        #pragma unroll
        for (int k = 0; k < Kk; k++) {
            float sv = bs + qe[(size_t)idx[k] * Hh + h];
            sv = sv > 0.f ? sv : 0.2f * sv;
            s[k] = sv; m = fmaxf(m, sv);
        }
        float sum = 0.f;
        #pragma unroll
        for (int k = 0; k < Kk; k++) { s[k] = __expf(s[k] - m); sum += s[k]; }
        float inv = 1.f / sum;
        #pragma unroll
        for (int k = 0; k < Kk; k++) al[h][k] = s[k] * inv;
    }
    int h0 = lane >> 4, h1 = 2 + (lane >> 4);
    float4 a0 = make_float4(0.f, 0.f, 0.f, 0.f), a1 = a0;
    #pragma unroll
    for (int k = 0; k < Kk; k++) {
        const float4* er = (const float4*)(EWnb + (size_t)idx[k] * Dd);
        float4 ea = er[lane], eb = er[32 + lane];
        float w0 = al[h0][k], w1 = al[h1][k];
        a0.x += w0 * ea.x; a0.y += w0 * ea.y; a0.z += w0 * ea.z; a0.w += w0 * ea.w;
        a1.x += w1 * eb.x; a1.y += w1 * eb.y; a1.z += w1 * eb.z; a1.w += w1 * eb.w;
    }
    *(float4*)(NP + (size_t)n * Dd + lane * 4)       = a0;
    *(float4*)(NP + (size_t)n * Dd + 128 + lane * 4) = a1;
}

// ---------------- L1 node aggregation (full) ----------------
__global__ __launch_bounds__(256) void nag_kernel(const int* __restrict__ n2e,
                                                  const float* __restrict__ ps,
                                                  const float* __restrict__ qe,
                                                  const float* __restrict__ edges,
                                                  float* __restrict__ nag)
{
    int t = threadIdx.x, w = t >> 5, lane = t & 31;
    int n = blockIdx.x * 8 + w;
    int idx[Kk];
    #pragma unroll
    for (int k = 0; k < Kk; k++) idx[k] = n2e[(size_t)n * Kk + k];
    float al[Hh][Kk];
    #pragma unroll
    for (int h = 0; h < Hh; h++) {
        float bs = ps[(size_t)n * Hh + h];
        float s[Kk]; float m = -1e30f;
        #pragma unroll
        for (int k = 0; k < Kk; k++) {
            float sv = bs + qe[(size_t)idx[k] * Hh + h];
            sv = sv > 0.f ? sv : 0.2f * sv;
            s[k] = sv; m = fmaxf(m, sv);
        }
        float sum = 0.f;
        #pragma unroll
        for (int k = 0; k < Kk; k++) { s[k] = __expf(s[k] - m); sum += s[k]; }
        float inv = 1.f / sum;
        #pragma unroll
        for (int k = 0; k < Kk; k++) al[h][k] = s[k] * inv;
    }
    float4 a0[Hh] = {}, a1[Hh] = {};
    #pragma unroll
    for (int k = 0; k < Kk; k++) {
        const float4* er = (const float4*)(edges + (size_t)idx[k] * Dd);
        float4 ea = er[lane], eb = er[32 + lane];
        #pragma unroll
        for (int h = 0; h < Hh; h++) {
            float a = al[h][k];
            a0[h].x += a * ea.x; a0[h].y += a * ea.y; a0[h].z += a * ea.z; a0[h].w += a * ea.w;
            a1[h].x += a * eb.x; a1[h].y += a * eb.y; a1[h].z += a * eb.z; a1[h].w += a * eb.w;
        }
    }
    #pragma unroll
    for (int h = 0; h < Hh; h++) {
        float* dst = nag + ((size_t)h * Nn + n) * Dd;
        *(float4*)(dst + lane * 4) = a0[h];
        *(float4*)(dst + 128 + lane * 4) = a1[h];
    }
}

// ---------------- launcher ----------------
extern "C" void kernel_launch(void* const* d_in, const int* in_sizes, int n_in,
                              void* d_out, int out_size)
{
    (void)in_sizes; (void)n_in; (void)out_size;
    const float* feats    = (const float*)d_in[0];
    const float* edge_emb = (const float*)d_in[1];
    const int*   ena      = (const int*)d_in[2];
    const int*   n2e      = (const int*)d_in[3];
    const float* Wp0      = (const float*)d_in[4];
    const float* Wp1      = (const float*)d_in[5];
    const float* Wep      = (const float*)d_in[6];
    const float* a_e      = (const float*)d_in[7];
    const float* a_n      = (const float*)d_in[8];
    const float* W_e      = (const float*)d_in[9];
    const float* a_s      = (const float*)d_in[10];
    const float* a_edge   = (const float*)d_in[11];
    const float* W_self   = (const float*)d_in[12];
    const float* W_nb     = (const float*)d_in[13];
    float* out = (float*)d_out;

    float *xb, *YB, *NP, *EW2B, *eB, *nag, *pnB, *beB, *psB, *qeB;
    float *WpT, *Bt5B, *WfYSB, *WcB, *avfB, *av256B;
    cudaGetSymbolAddress((void**)&xb,     g_x);
    cudaGetSymbolAddress((void**)&YB,     g_Y);
    cudaGetSymbolAddress((void**)&NP,     g_NP);
    cudaGetSymbolAddress((void**)&EW2B,   g_EW2);
    cudaGetSymbolAddress((void**)&eB,     g_eB);
    cudaGetSymbolAddress((void**)&nag,    g_nag);
    cudaGetSymbolAddress((void**)&pnB,    g_pn);
    cudaGetSymbolAddress((void**)&beB,    g_be);
    cudaGetSymbolAddress((void**)&psB,    g_ps);
    cudaGetSymbolAddress((void**)&qeB,    g_qe);
    cudaGetSymbolAddress((void**)&WpT,    g_WpT);
    cudaGetSymbolAddress((void**)&Bt5B,   g_Bt5);
    cudaGetSymbolAddress((void**)&WfYSB,  g_WfYS);
    cudaGetSymbolAddress((void**)&WcB,    g_Wc);
    cudaGetSymbolAddress((void**)&avfB,   g_avf);
    cudaGetSymbolAddress((void**)&av256B, g_av256);

    constexpr int SM128 = 2 * (2 * 128 * 40 + 2 * 128 * 40) * 2;
    constexpr int SM64  = 2 * (2 * 128 * 40 + 2 * 64 * 40) * 2;
    cudaFuncSetAttribute(gemm_mma<128, 0>, cudaFuncAttributeMaxDynamicSharedMemorySize, SM128);
    cudaFuncSetAttribute(gemm_mma<128, 2>, cudaFuncAttributeMaxDynamicSharedMemorySize, SM128);
    cudaFuncSetAttribute(gemm_mma<128, 3>, cudaFuncAttributeMaxDynamicSharedMemorySize, SM128);
    cudaFuncSetAttribute(gemm_mma<64, 0>,  cudaFuncAttributeMaxDynamicSharedMemorySize, SM64);

    dim3 blk(256);
    dim3 gN(Nn / 128, 2);
    dim3 gE2(Ee / 128, 2, 2);
    dim3 gH(Nn / 128, 1, Hh);

    cudaStream_t ms = 0;
    cudaStream_t s2 = g_ss.s;

    auto Bt5_   = [&](int mp) { return Bt5B   + (size_t)mp * 5 * Dd * Dd; };
    auto Wc_    = [&](int mp) { return WcB    + (size_t)mp * 2 * Dd * EDd; };
    auto WfYS_  = [&](int mp) { return WfYSB  + (size_t)mp * 2 * Dd * Dd; };
    auto avf_   = [&](int mp) { return avfB   + (size_t)mp * 2 * Hh * EDd; };
    auto av256_ = [&](int mp) { return av256B + (size_t)mp * 2 * Hh * Dd; };
    auto pn_    = [&](int mp) { return pnB + (size_t)mp * Nn * Hh; };
    auto ps_    = [&](int mp) { return psB + (size_t)mp * Nn * Hh; };
    auto be_    = [&](int mp) { return beB + (size_t)mp * Ee * Hh; };
    auto qe_    = [&](int mp) { return qeB + (size_t)mp * Ee * Hh; };
    auto Y_     = [&](int mp) { return YB + (size_t)mp * Nn * Dd; };
    auto EW2_   = [&](int mp) { return EW2B + (size_t)mp * 2 * Ee * Dd; };

    // ---- s2: input-only folds first (no deps) ----
    for (int mp = 0; mp < NMPc; mp++) {
        size_t pl0 = (size_t)(mp * DEPTHc + 0);
        foldA2p<<<Hh, blk, 0, s2>>>(Wep + (size_t)mp * EDd * Dd,
                                    a_e + pl0 * Hh * Dd, a_edge + pl0 * Hh * Dd, avf_(mp));
    }

    // ---- ms: WpT -> mp0 weight folds -> mp0 front GEMMs (record evMS0 BEFORE any wait on it) ----
    pack2d2<<<dim3(256, 1, 2), blk, 0, ms>>>(Wp0, Wp1, WpT);
    cudaEventRecord(g_ss.evWpT, ms);

    pack_hdp5<<<dim3(256, 1, 5), blk, 0, ms>>>(W_e    + 0 * Hh * Dd * PHp,
                                               W_self + 0 * Hh * Dd * PHp,
                                               W_nb   + 0 * Hh * Dd * PHp,
                                               W_self + 1 * Hh * Dd * PHp,
                                               W_nb   + 1 * Hh * Dd * PHp, Bt5_(0));
    foldW256_2<<<dim3(256, 1, 2), blk, 0, ms>>>(WpT, Bt5_(0), WfYS_(0));
    foldW2<<<dim3(256, 1, 2), blk, 0, ms>>>(Wep, Bt5_(0), Wc_(0));

    // mp0 front GEMMs on ms
    gemm_mma<128, 0><<<gN, blk, SM128, ms>>>(feats, WfYS_(0), Y_(0), Dd, Dd, 0, 0, 0,
                                             nullptr, nullptr, nullptr, nullptr, nullptr);
    gemm_mma<128, 0><<<gE2, blk, SM128, ms>>>(edge_emb, Wc_(0), EW2_(0), EDd, Dd,
                                              0, (size_t)Dd * EDd, (size_t)Ee * Dd,
                                              nullptr, nullptr, nullptr, nullptr, nullptr);
    cudaEventRecord(g_ss.evMS0, ms);

    // ---- s2: attention-vector folds + rowdots + mp1 weight folds + (gated) mp1 front GEMMs ----
    cudaStreamWaitEvent(s2, g_ss.evWpT, 0);
    {
        size_t pl0m0 = 0, pl0m1 = (size_t)DEPTHc;
        foldA256_2<<<dim3(Hh, 1, 2), blk, 0, s2>>>(WpT, a_n + pl0m0 * Hh * Dd, a_s + pl0m0 * Hh * Dd, av256_(0));
        rowdot2<<<Nn / 8, blk, 0, s2>>>(feats, av256_(0), av256_(0) + Hh * Dd, pn_(0), ps_(0));
        rowdot2_64<<<Ee / 8, blk, 0, s2>>>(edge_emb, avf_(0), be_(0), qe_(0));
        cudaEventRecord(g_ss.evRD0, s2);

        foldA256_2<<<dim3(Hh, 1, 2), blk, 0, s2>>>(WpT, a_n + pl0m1 * Hh * Dd, a_s + pl0m1 * Hh * Dd, av256_(1));
        rowdot2<<<Nn / 8, blk, 0, s2>>>(feats, av256_(1), av256_(1) + Hh * Dd, pn_(1), ps_(1));
        rowdot2_64<<<Ee / 8, blk, 0, s2>>>(edge_emb + (size_t)Ee * EDd, avf_(1), be_(1), qe_(1));

        size_t pl0 = (size_t)DEPTHc, pl1 = (size_t)DEPTHc + 1;
        pack_hdp5<<<dim3(256, 1, 5), blk, 0, s2>>>(W_e    + pl0 * Hh * Dd * PHp,
                                                   W_self + pl0 * Hh * Dd * PHp,
                                                   W_nb   + pl0 * Hh * Dd * PHp,
                                                   W_self + pl1 * Hh * Dd * PHp,
                                                   W_nb   + pl1 * Hh * Dd * PHp, Bt5_(1));
        foldW256_2<<<dim3(256, 1, 2), blk, 0, s2>>>(WpT, Bt5_(1), WfYS_(1));
        foldW2<<<dim3(256, 1, 2), blk, 0, s2>>>(Wep + (size_t)EDd * Dd, Bt5_(1), Wc_(1));

        // mp1 front GEMMs on s2 — gated on mp0's front GEMMs (evMS0 recorded above, capture-legal),
        // so they overlap mp0's memory-bound tail instead of contending with mp0's GEMMs.
        cudaStreamWaitEvent(s2, g_ss.evMS0, 0);
        gemm_mma<128, 0><<<gN, blk, SM128, s2>>>(feats, WfYS_(1), Y_(1), Dd, Dd, 0, 0, 0,
                                                 nullptr, nullptr, nullptr, nullptr, nullptr);
        gemm_mma<128, 0><<<gE2, blk, SM128, s2>>>(edge_emb + (size_t)Ee * EDd, Wc_(1), EW2_(1), EDd, Dd,
                                                  0, (size_t)Dd * EDd, (size_t)Ee * Dd,
                                                  nullptr, nullptr, nullptr, nullptr, nullptr);
        cudaEventRecord(g_ss.evG1, s2);
    }

    for (int mp = 0; mp < NMPc; mp++) {
        const int*   ena_mp = ena + (size_t)mp * Ee * 2;
        const int*   n2e_mp = n2e + (size_t)mp * Nn * Kk;
        float* outmp = out + (size_t)mp * Nn * DEPTHc * Dd;
        size_t pl1 = (size_t)(mp * DEPTHc + 1);
        float* EW    = EW2_(mp);
        float* EWnb0 = EW2_(mp) + (size_t)Ee * Dd;

        if (mp == 0) {
            cudaStreamWaitEvent(ms, g_ss.evRD0, 0);  // rowdots for mp0
        } else {
            cudaStreamWaitEvent(ms, g_ss.evG1, 0);   // Y1/EW1 (and rowdots, ordered before on s2)
        }

        // ---- edge combine (+ fused qe1 into be_(mp)) ----
        edge_comb_q<<<Ee / 4, blk, 0, ms>>>(ena_mp, pn_(mp), be_(mp), EW, Y_(mp),
                                            a_edge + pl1 * Hh * Dd, eB, be_(mp));

        // ---- L0 node aggregator (projected) ----
        nagp_kernel<<<Nn / 8, blk, 0, ms>>>(n2e_mp, ps_(mp), qe_(mp), EWnb0, NP);

        // ---- fused S GEMM: elu(feats@WfS + NP) -> out, xb; ps_L1 atomics ----
        cudaMemsetAsync(ps_(mp), 0, (size_t)Nn * Hh * sizeof(float), ms);
        gemm_mma<128, 3><<<gN, blk, SM128, ms>>>(feats, WfYS_(mp) + Dd * Dd, nullptr, Dd, Dd, 0, 0, 0,
                                                 a_s + pl1 * Hh * Dd, NP, outmp, xb, ps_(mp));

        // ---- L1 node aggregator ----
        nag_kernel<<<Nn / 8, blk, 0, ms>>>(n2e_mp, ps_(mp), be_(mp), eB, nag);
        gemm_mma<64, 0><<<gH, blk, SM64, ms>>>(nag, Bt5_(mp) + (size_t)4 * Dd * Dd, NP, Dd, Dd,
                                               (size_t)Nn * Dd, (size_t)PHp * Dd, (size_t)PHp,
                                               nullptr, nullptr, nullptr, nullptr, nullptr);

        // ---- fused final GEMM: elu(xb@Wself1 + NP) -> out[:, Dd:] ----
        gemm_mma<128, 2><<<gN, blk, SM128, ms>>>(xb, Bt5_(mp) + (size_t)3 * Dd * Dd, nullptr, Dd, Dd, 0, 0, 0,
                                                 nullptr, NP, outmp, nullptr, nullptr);
    }
}

// round 15
// speedup vs baseline: 1.0338x; 1.0156x over previous
#include <cuda_runtime.h>
#include <cuda_bf16.h>
#include <math.h>
#include <stdint.h>

#define Nn 65536
#define Ee 262144
#define Kk 8
#define NMPc 2
#define DEPTHc 2
#define Hh 4
#define Dd 256
#define PHp 64
#define EDd 64

// ---------------- scratch (device globals; no allocation allowed) ----------------
__device__ __align__(16) float g_x    [(size_t)Nn * Dd];
__device__ __align__(16) float g_Y    [(size_t)2 * Nn * Dd];        // per-mp
__device__ __align__(16) float g_NP   [(size_t)Nn * Dd];
__device__ __align__(16) float g_EW2  [(size_t)2 * 2 * Ee * Dd];    // per-mp: [0]=EW, [1]=EWnb0
__device__ __align__(16) float g_eB   [(size_t)Ee * Dd];
__device__ __align__(16) float g_nag  [(size_t)Hh * Nn * Dd];
// per-mp doubled small state
__device__ __align__(16) float g_pn   [(size_t)2 * Nn * Hh];
__device__ __align__(16) float g_be   [(size_t)2 * Ee * Hh];   // be (L0), then qe1 (L1)
__device__ __align__(16) float g_ps   [(size_t)2 * Nn * Hh];
__device__ __align__(16) float g_qe   [(size_t)2 * Ee * Hh];   // qe0
__device__ __align__(16) float g_WpT  [2 * Dd * Dd];           // [0]=Wp0^T, [1]=Wp1^T
__device__ __align__(16) float g_Bt5  [2 * 5 * Dd * Dd];
__device__ __align__(16) float g_WfYS [2 * 2 * Dd * Dd];       // per-mp [0]=WfY, [1]=WfS
__device__ __align__(16) float g_Wc   [2 * 2 * Dd * EDd];
__device__ __align__(16) float g_avf  [2 * 2 * Hh * EDd];
__device__ __align__(16) float g_av256[2 * 2 * Hh * Dd];

// ---------------- side stream + events (static init: before harness mem checkpoints) ----------------
namespace {
struct SideStream {
    cudaStream_t s;
    cudaEvent_t evWpT, evRD0, evG1, evMS0;
    SideStream() {
        cudaStreamCreateWithFlags(&s, cudaStreamNonBlocking);
        cudaEventCreateWithFlags(&evWpT, cudaEventDisableTiming);
        cudaEventCreateWithFlags(&evRD0, cudaEventDisableTiming);
        cudaEventCreateWithFlags(&evG1,  cudaEventDisableTiming);
        cudaEventCreateWithFlags(&evMS0, cudaEventDisableTiming);
    }
};
SideStream g_ss;
}

// ---------------- HMMA helper ----------------
__device__ __forceinline__ void mma16816(float* c, const uint32_t* a, uint32_t b0, uint32_t b1) {
    asm volatile("mma.sync.aligned.m16n8k16.row.col.f32.bf16.bf16.f32 "
                 "{%0,%1,%2,%3}, {%4,%5,%6,%7}, {%8,%9}, {%0,%1,%2,%3};"
                 : "+f"(c[0]), "+f"(c[1]), "+f"(c[2]), "+f"(c[3])
                 : "r"(a[0]), "r"(a[1]), "r"(a[2]), "r"(a[3]), "r"(b0), "r"(b1));
}

__device__ __forceinline__ void split4(float4 v, uint2& hi, uint2& lo) {
    __nv_bfloat16 h0 = __float2bfloat16(v.x), h1 = __float2bfloat16(v.y);
    __nv_bfloat16 h2 = __float2bfloat16(v.z), h3 = __float2bfloat16(v.w);
    __nv_bfloat16 l0 = __float2bfloat16(v.x - __bfloat162float(h0));
    __nv_bfloat16 l1 = __float2bfloat16(v.y - __bfloat162float(h1));
    __nv_bfloat16 l2 = __float2bfloat16(v.z - __bfloat162float(h2));
    __nv_bfloat16 l3 = __float2bfloat16(v.w - __bfloat162float(h3));
    union { __nv_bfloat162 b[2]; uint2 u; } ph, pl;
    ph.b[0] = __nv_bfloat162(h0, h1); ph.b[1] = __nv_bfloat162(h2, h3);
    pl.b[0] = __nv_bfloat162(l0, l1); pl.b[1] = __nv_bfloat162(l2, l3);
    hi = ph.u; lo = pl.u;
}

__device__ __forceinline__ float elu1(float x) { return x > 0.f ? x : expm1f(x); }

// ---------------- pipelined bf16-split HMMA GEMM (BM x BN tile, 2 CTAs/SM at BM=64) ----------------
// EPI 0: plain store. EPI 2: out[.., Dd+c] = elu(acc+NP). EPI 3: out/xout = elu(acc+NP), ps atomics.
template <int BM, int BN, int EPI>
__global__ __launch_bounds__(256, 2) void gemm_mma(const float* __restrict__ A,
                                                   const float* __restrict__ Bt,
                                                   float* __restrict__ C,
                                                   int K, int ldc,
                                                   size_t sAz, size_t sBz, size_t sCz,
                                                   const float* __restrict__ a1v,
                                                   const float* __restrict__ NPp,
                                                   float* __restrict__ outp,
                                                   float* __restrict__ xoutp,
                                                   float* __restrict__ psout)
{
    constexpr int NWN = (BM == 64) ? 4 : 2;      // warps along N
    constexpr int NT  = BN / (8 * NWN);          // n8-tiles per warp
    constexpr int NA  = BM / 32;                 // A float4 loads per thread
    constexpr int NB  = BN / 32;
    constexpr int ASZ = BM * 40;
    constexpr int BSZ = BN * 40;
    constexpr int BUFE = 2 * ASZ + 2 * BSZ;
    extern __shared__ uint16_t sm[];

    A  += blockIdx.z * sAz;
    Bt += blockIdx.z * sBz;
    C  += blockIdx.z * sCz;

    int t = threadIdx.x, wid = t >> 5, lane = t & 31;
    int g = lane >> 2, tg = lane & 3;
    int wm = (wid / NWN) * 32;
    int wn = (wid % NWN) * (BN / NWN);
    size_t m0 = (size_t)blockIdx.x * BM;
    size_t n0 = (size_t)blockIdx.y * BN;
    const float* Abase = A + m0 * K;
    const float* Bbase = Bt + n0 * K;

    float acc[2][NT][4];
    #pragma unroll
    for (int mt = 0; mt < 2; mt++)
        #pragma unroll
        for (int nt = 0; nt < NT; nt++)
            #pragma unroll
            for (int j = 0; j < 4; j++) acc[mt][nt][j] = 0.f;

    float4 pa[NA], pb[NB];
    auto ldAB = [&](int kb) {
        #pragma unroll
        for (int i = 0; i < NA; i++) {
            int id = t + 256 * i, r = id >> 3, c4 = id & 7;
            pa[i] = *(const float4*)(Abase + (size_t)r * K + kb * 32 + c4 * 4);
        }
        #pragma unroll
        for (int i = 0; i < NB; i++) {
            int id = t + 256 * i, r = id >> 3, c4 = id & 7;
            pb[i] = *(const float4*)(Bbase + (size_t)r * K + kb * 32 + c4 * 4);
        }
    };
    auto stAB = [&](int buf) {
        uint16_t* bAh = sm + buf * BUFE;
        uint16_t* bAl = bAh + ASZ;
        uint16_t* bBh = bAl + ASZ;
        uint16_t* bBl = bBh + BSZ;
        #pragma unroll
        for (int i = 0; i < NA; i++) {
            int id = t + 256 * i, r = id >> 3, c4 = id & 7;
            uint2 hi, lo; split4(pa[i], hi, lo);
            *(uint2*)&bAh[r * 40 + c4 * 4] = hi;
            *(uint2*)&bAl[r * 40 + c4 * 4] = lo;
        }
        #pragma unroll
        for (int i = 0; i < NB; i++) {
            int id = t + 256 * i, r = id >> 3, c4 = id & 7;
            uint2 hi, lo; split4(pb[i], hi, lo);
            *(uint2*)&bBh[r * 40 + c4 * 4] = hi;
            *(uint2*)&bBl[r * 40 + c4 * 4] = lo;
        }
    };
    auto domma = [&](int buf) {
        const uint16_t* bAh = sm + buf * BUFE;
        const uint16_t* bAl = bAh + ASZ;
        const uint16_t* bBh = bAl + ASZ;
        const uint16_t* bBl = bBh + BSZ;
        #pragma unroll
        for (int ks = 0; ks < 2; ks++) {
            int kc = ks * 16 + tg * 2;
            uint32_t ah[2][4], al_[2][4];
            #pragma unroll
            for (int mt = 0; mt < 2; mt++) {
                int row = wm + mt * 16 + g;
                ah[mt][0]  = *(const uint32_t*)&bAh[row * 40 + kc];
                ah[mt][1]  = *(const uint32_t*)&bAh[(row + 8) * 40 + kc];
                ah[mt][2]  = *(const uint32_t*)&bAh[row * 40 + kc + 8];
                ah[mt][3]  = *(const uint32_t*)&bAh[(row + 8) * 40 + kc + 8];
                al_[mt][0] = *(const uint32_t*)&bAl[row * 40 + kc];
                al_[mt][1] = *(const uint32_t*)&bAl[(row + 8) * 40 + kc];
                al_[mt][2] = *(const uint32_t*)&bAl[row * 40 + kc + 8];
                al_[mt][3] = *(const uint32_t*)&bAl[(row + 8) * 40 + kc + 8];
            }
            #pragma unroll
            for (int nt = 0; nt < NT; nt++) {
                int col = wn + nt * 8 + g;
                uint32_t bh0 = *(const uint32_t*)&bBh[col * 40 + kc];
                uint32_t bh1 = *(const uint32_t*)&bBh[col * 40 + kc + 8];
                uint32_t bl0 = *(const uint32_t*)&bBl[col * 40 + kc];
                uint32_t bl1 = *(const uint32_t*)&bBl[col * 40 + kc + 8];
                #pragma unroll
                for (int mt = 0; mt < 2; mt++) {
                    mma16816(acc[mt][nt], ah[mt],  bh0, bh1);
                    mma16816(acc[mt][nt], al_[mt], bh0, bh1);
                    mma16816(acc[mt][nt], ah[mt],  bl0, bl1);
                }
            }
        }
    };

    int nkb = K >> 5;
    ldAB(0);
    stAB(0);
    __syncthreads();
    for (int kb = 0; kb < nkb; kb++) {
        int cur = kb & 1;
        if (kb + 1 < nkb) ldAB(kb + 1);
        domma(cur);
        if (kb + 1 < nkb) stAB(cur ^ 1);
        __syncthreads();
    }

    if (EPI == 0) {
        #pragma unroll
        for (int mt = 0; mt < 2; mt++) {
            size_t row = m0 + wm + mt * 16 + g;
            #pragma unroll
            for (int nt = 0; nt < NT; nt++) {
                size_t col = n0 + wn + nt * 8 + tg * 2;
                *(float2*)(C + row * ldc + col)       = make_float2(acc[mt][nt][0], acc[mt][nt][1]);
                *(float2*)(C + (row + 8) * ldc + col) = make_float2(acc[mt][nt][2], acc[mt][nt][3]);
            }
        }
    } else {
        constexpr int Lofs = (EPI == 3) ? 0 : Dd;
        float* sa1 = (float*)sm;
        if (EPI == 3) {
            for (int i = t; i < 4 * BN; i += 256) {
                int h = i / BN, c = i % BN;
                sa1[i] = a1v[(size_t)h * Dd + n0 + c];
            }
            __syncthreads();
        }
        float qp[4][Hh];
        if (EPI == 3) {
            #pragma unroll
            for (int j = 0; j < 4; j++)
                #pragma unroll
                for (int h = 0; h < Hh; h++) qp[j][h] = 0.f;
        }
        #pragma unroll
        for (int mt = 0; mt < 2; mt++) {
            #pragma unroll
            for (int rp = 0; rp < 2; rp++) {
                size_t grow = m0 + wm + mt * 16 + g + rp * 8;
                #pragma unroll
                for (int nt = 0; nt < NT; nt++) {
                    int cloc = wn + nt * 8 + tg * 2;
                    size_t gc = n0 + cloc;
                    float2 np = *(const float2*)(NPp + grow * Dd + gc);
                    float r0 = elu1(acc[mt][nt][rp * 2 + 0] + np.x);
                    float r1 = elu1(acc[mt][nt][rp * 2 + 1] + np.y);
                    *(float2*)(outp + grow * (DEPTHc * Dd) + Lofs + gc) = make_float2(r0, r1);
                    if (EPI == 3) {
                        *(float2*)(xoutp + grow * Dd + gc) = make_float2(r0, r1);
                        #pragma unroll
                        for (int h = 0; h < Hh; h++)
                            qp[mt * 2 + rp][h] += r0 * sa1[h * BN + cloc] + r1 * sa1[h * BN + cloc + 1];
                    }
                }
            }
        }
        if (EPI == 3) {
            #pragma unroll
            for (int j = 0; j < 4; j++)
                #pragma unroll
                for (int h = 0; h < Hh; h++) {
                    qp[j][h] += __shfl_xor_sync(0xffffffffu, qp[j][h], 1);
                    qp[j][h] += __shfl_xor_sync(0xffffffffu, qp[j][h], 2);
                }
            if (tg == 0) {
                #pragma unroll
                for (int mt = 0; mt < 2; mt++)
                    #pragma unroll
                    for (int rp = 0; rp < 2; rp++) {
                        size_t grow = m0 + wm + mt * 16 + g + rp * 8;
                        #pragma unroll
                        for (int h = 0; h < Hh; h++)
                            atomicAdd(&psout[grow * Hh + h], qp[mt * 2 + rp][h]);
                    }
            }
        }
    }
}

// ---------------- packing / folding ----------------
__global__ void pack2d2(const float* __restrict__ s0, const float* __restrict__ s1,
                        float* __restrict__ dst) {
    int z = blockIdx.z;
    const float* src = z ? s1 : s0;
    int id = blockIdx.x * 256 + threadIdx.x;
    int c = id % Dd, k = id / Dd;
    dst[(size_t)z * Dd * Dd + (size_t)c * Dd + k] = src[id];
}

__global__ void pack_hdp5(const float* __restrict__ s0, const float* __restrict__ s1,
                          const float* __restrict__ s2, const float* __restrict__ s3,
                          const float* __restrict__ s4, float* __restrict__ dst) {
    int z = blockIdx.z;
    const float* src = (z == 0) ? s0 : (z == 1) ? s1 : (z == 2) ? s2 : (z == 3) ? s3 : s4;
    int id = blockIdx.x * 256 + threadIdx.x;
    int p = id % PHp, d = (id / PHp) % Dd, h = id / (PHp * Dd);
    dst[(size_t)z * Dd * Dd + (size_t)(h * PHp + p) * Dd + d] = src[id];
}

__global__ __launch_bounds__(256) void foldW2(const float* __restrict__ Wep,
                                              const float* __restrict__ Bt5,
                                              float* __restrict__ Wc)
{
    __shared__ float sb[256];
    __shared__ float sred[4][64];
    int z = blockIdx.z;
    const float* BtW = Bt5 + (size_t)(z == 0 ? 0 : 2) * Dd * Dd;
    float* dst = Wc + (size_t)z * Dd * EDd;
    int c = blockIdx.x, t = threadIdx.x;
    sb[t] = BtW[(size_t)c * 256 + t];
    __syncthreads();
    int j = t & 63, q = t >> 6;
    const float* wr  = Wep + (size_t)j * 256 + q * 64;
    const float* sbp = sb + q * 64;
    float acc = 0.f;
    #pragma unroll 16
    for (int d = 0; d < 64; d++) acc += wr[d] * sbp[d];
    sred[q][j] = acc;
    __syncthreads();
    if (t < 64) dst[(size_t)c * 64 + t] = sred[0][t] + sred[1][t] + sred[2][t] + sred[3][t];
}

__global__ __launch_bounds__(256) void foldW256_2(const float* __restrict__ WpT,
                                                  const float* __restrict__ Bt5,
                                                  float* __restrict__ Wf)
{
    __shared__ float sb[256];
    int z = blockIdx.z;
    const float* WpTz = WpT + (size_t)(z == 0 ? 1 : 0) * Dd * Dd;
    const float* BtW = Bt5 + (size_t)z * Dd * Dd;
    float* dst = Wf + (size_t)z * Dd * Dd;
    int c = blockIdx.x, d = threadIdx.x;
    sb[d] = BtW[(size_t)c * 256 + d];
    __syncthreads();
    float acc = 0.f;
    #pragma unroll 4
    for (int dp = 0; dp < 256; dp++) acc += WpTz[(size_t)dp * 256 + d] * sb[dp];
    dst[(size_t)c * 256 + d] = acc;
}

__global__ __launch_bounds__(256) void foldA256_2(const float* __restrict__ WpT,
                                                  const float* __restrict__ an,
                                                  const float* __restrict__ as,
                                                  float* __restrict__ outp)
{
    __shared__ float sa[256];
    int z = blockIdx.z;
    const float* WpTz = WpT + (size_t)(z == 0 ? 1 : 0) * Dd * Dd;
    const float* a = (z == 0) ? an : as;
    int h = blockIdx.x, d = threadIdx.x;
    sa[d] = a[(size_t)h * 256 + d];
    __syncthreads();
    float acc = 0.f;
    #pragma unroll 4
    for (int dp = 0; dp < 256; dp++) acc += WpTz[(size_t)dp * 256 + d] * sa[dp];
    outp[(size_t)z * Hh * Dd + (size_t)h * 256 + d] = acc;
}

__global__ __launch_bounds__(256) void foldA2p(const float* __restrict__ Wep,
                                               const float* __restrict__ a1,
                                               const float* __restrict__ a2,
                                               float* __restrict__ outp)
{
    __shared__ float s1[256], s2[256];
    __shared__ float r1[4][64], r2[4][64];
    int h = blockIdx.x, t = threadIdx.x;
    s1[t] = a1[(size_t)h * 256 + t];
    s2[t] = a2[(size_t)h * 256 + t];
    __syncthreads();
    int j = t & 63, q = t >> 6;
    const float* wr = Wep + (size_t)j * 256 + q * 64;
    float A = 0.f, B = 0.f;
    #pragma unroll 16
    for (int d = 0; d < 64; d++) { float w = wr[d]; A += w * s1[q * 64 + d]; B += w * s2[q * 64 + d]; }
    r1[q][j] = A; r2[q][j] = B;
    __syncthreads();
    if (t < 64) outp[h * 64 + t] = r1[0][t] + r1[1][t] + r1[2][t] + r1[3][t];
    else if (t < 128) {
        int j2 = t - 64;
        outp[Hh * 64 + h * 64 + j2] = r2[0][j2] + r2[1][j2] + r2[2][j2] + r2[3][j2];
    }
}

// ---------------- dual row-dot (D=256) ----------------
__global__ __launch_bounds__(256) void rowdot2(const float* __restrict__ X,
                                               const float* __restrict__ avec1,
                                               const float* __restrict__ avec2,
                                               float* __restrict__ P1,
                                               float* __restrict__ P2)
{
    __shared__ float sa[2 * Hh * Dd];
    int t = threadIdx.x;
    for (int i = t; i < Hh * Dd; i += 256) { sa[i] = avec1[i]; sa[Hh * Dd + i] = avec2[i]; }
    __syncthreads();
    int row = blockIdx.x * 8 + (t >> 5);
    int lane = t & 31;
    const float* xr = X + (size_t)row * Dd;
    float a1[Hh] = {}, a2[Hh] = {};
    #pragma unroll
    for (int j = 0; j < 8; j++) {
        float xv = xr[lane + 32 * j];
        #pragma unroll
        for (int h = 0; h < Hh; h++) {
            a1[h] += sa[h * Dd + lane + 32 * j] * xv;
            a2[h] += sa[Hh * Dd + h * Dd + lane + 32 * j] * xv;
        }
    }
    #pragma unroll
    for (int h = 0; h < Hh; h++) {
        #pragma unroll
        for (int o = 16; o > 0; o >>= 1) {
            a1[h] += __shfl_down_sync(0xffffffffu, a1[h], o);
            a2[h] += __shfl_down_sync(0xffffffffu, a2[h], o);
        }
    }
    if (lane == 0) {
        #pragma unroll
        for (int h = 0; h < Hh; h++) {
            P1[(size_t)row * Hh + h] = a1[h];
            P2[(size_t)row * Hh + h] = a2[h];
        }
    }
}

// ---------------- dual row-dot over D=64 rows (edge_emb) ----------------
__global__ __launch_bounds__(256) void rowdot2_64(const float* __restrict__ X,
                                                  const float* __restrict__ avf,
                                                  float* __restrict__ P1,
                                                  float* __restrict__ P2)
{
    __shared__ float sa[2 * Hh * 64];
    int t = threadIdx.x;
    for (int i = t; i < 2 * Hh * 64; i += 256) sa[i] = avf[i];
    __syncthreads();
    int row = blockIdx.x * 8 + (t >> 5);
    int lane = t & 31;
    const float* xr = X + (size_t)row * 64;
    float x0 = xr[lane], x1 = xr[lane + 32];
    float a1[Hh], a2[Hh];
    #pragma unroll
    for (int h = 0; h < Hh; h++) {
        a1[h] = sa[h * 64 + lane] * x0 + sa[h * 64 + lane + 32] * x1;
        a2[h] = sa[256 + h * 64 + lane] * x0 + sa[256 + h * 64 + lane + 32] * x1;
    }
    #pragma unroll
    for (int h = 0; h < Hh; h++) {
        #pragma unroll
        for (int o = 16; o > 0; o >>= 1) {
            a1[h] += __shfl_down_sync(0xffffffffu, a1[h], o);
            a2[h] += __shfl_down_sync(0xffffffffu, a2[h], o);
        }
    }
    if (lane == 0) {
        #pragma unroll
        for (int h = 0; h < Hh; h++) {
            P1[(size_t)row * Hh + h] = a1[h];
            P2[(size_t)row * Hh + h] = a2[h];
        }
    }
}

// ---------------- edge combine + fused qe1 ----------------
__global__ __launch_bounds__(256) void edge_comb_q(const int* __restrict__ ena,
                                                   const float* __restrict__ pn,
                                                   const float* __restrict__ be,
                                                   const float* __restrict__ EW,
                                                   const float* __restrict__ Y,
                                                   const float* __restrict__ a1v,
                                                   float* __restrict__ eout,
                                                   float* __restrict__ qe1)
{
    __shared__ float sa1[Hh * Dd];
    __shared__ float sred[4][2][Hh];
    int t = threadIdx.x;
    for (int i = t; i < Hh * Dd; i += 256) sa1[i] = a1v[i];
    __syncthreads();

    int e0 = blockIdx.x * 4;
    int el = t >> 6, c4 = t & 63, h = c4 >> 4;
    int e = e0 + el;
    int u = ena[2 * e], v = ena[2 * e + 1];
    float b = be[(size_t)e * Hh + h];
    float s0 = pn[(size_t)u * Hh + h] + b;
    float s1 = pn[(size_t)v * Hh + h] + b;
    s0 = s0 > 0.f ? s0 : 0.2f * s0;
    s1 = s1 > 0.f ? s1 : 0.2f * s1;
    float m = fmaxf(s0, s1);
    float x0 = __expf(s0 - m), x1 = __expf(s1 - m);
    float inv = 1.f / (x0 + x1);
    float al0 = x0 * inv, al1 = x1 * inv;
    float4 ew = *(const float4*)(EW + (size_t)e * Dd + c4 * 4);
    float4 yu = *(const float4*)(Y + (size_t)u * Dd + c4 * 4);
    float4 yv = *(const float4*)(Y + (size_t)v * Dd + c4 * 4);
    float4 r;
    r.x = elu1(ew.x + al0 * yu.x + al1 * yv.x);
    r.y = elu1(ew.y + al0 * yu.y + al1 * yv.y);
    r.z = elu1(ew.z + al0 * yu.z + al1 * yv.z);
    r.w = elu1(ew.w + al0 * yu.w + al1 * yv.w);
    *(float4*)(eout + (size_t)e * Dd + c4 * 4) = r;

    float p[Hh];
    #pragma unroll
    for (int hh = 0; hh < Hh; hh++) {
        const float* av = sa1 + hh * Dd + c4 * 4;
        p[hh] = r.x * av[0] + r.y * av[1] + r.z * av[2] + r.w * av[3];
    }
    #pragma unroll
    for (int hh = 0; hh < Hh; hh++) {
        #pragma unroll
        for (int o = 16; o > 0; o >>= 1) p[hh] += __shfl_down_sync(0xffffffffu, p[hh], o);
    }
    int wl = t & 31, whalf = (t >> 5) & 1;
    if (wl == 0) {
        #pragma unroll
        for (int hh = 0; hh < Hh; hh++) sred[el][whalf][hh] = p[hh];
    }
    __syncthreads();
    if (t < 16) {
        int ee = t >> 2, hh = t & 3;
        qe1[(size_t)(e0 + ee) * Hh + hh] = sred[ee][0][hh] + sred[ee][1][hh];
    }
}

// ---------------- L0 node agg, projected ----------------
__global__ __launch_bounds__(256) void nagp_kernel(const int* __restrict__ n2e,
                                                   const float* __restrict__ ps,
                                                   const float* __restrict__ qe,
                                                   const float* __restrict__ EWnb,
                                                   float* __restrict__ NP)
{
    int t = threadIdx.x, w = t >> 5, lane = t & 31;
    int n = blockIdx.x * 8 + w;
    int idx[Kk];
    #pragma unroll
    for (int k = 0; k < Kk; k++) idx[k] = n2e[(size_t)n * Kk + k];
    float al[Hh][Kk];
    #pragma unroll
    for (int h = 0; h < Hh; h++) {
        float bs = ps[(size_t)n * Hh + h];
        float s[Kk]; float m = -1e30f;
        #pragma unroll
        for (int k = 0; k < Kk; k++) {
            float sv = bs + qe[(size_t)idx[k] * Hh + h];
            sv = sv > 0.f ? sv : 0.2f * sv;
            s[k] = sv; m = fmaxf(m, sv);
        }
        float sum = 0.f;
        #pragma unroll
        for (int k = 0; k < Kk; k++) { s[k] = __expf(s[k] - m); sum += s[k]; }
        float inv = 1.f / sum;
        #pragma unroll
        for (int k = 0; k < Kk; k++) al[h][k] = s[k] * inv;
    }
    int h0 = lane >> 4, h1 = 2 + (lane >> 4);
    float4 a0 = make_float4(0.f, 0.f, 0.f, 0.f), a1 = a0;
    #pragma unroll
    for (int k = 0; k < Kk; k++) {
        const float4* er = (const float4*)(EWnb + (size_t)idx[k] * Dd);
        float4 ea = er[lane], eb = er[32 + lane];
        float w0 = al[h0][k], w1 = al[h1][k];
        a0.x += w0 * ea.x; a0.y += w0 * ea.y; a0.z += w0 * ea.z; a0.w += w0 * ea.w;
        a1.x += w1 * eb.x; a1.y += w1 * eb.y; a1.z += w1 * eb.z; a1.w += w1 * eb.w;
    }
    *(float4*)(NP + (size_t)n * Dd + lane * 4)       = a0;
    *(float4*)(NP + (size_t)n * Dd + 128 + lane * 4) = a1;
}

// ---------------- L1 node aggregation (full) ----------------
__global__ __launch_bounds__(256) void nag_kernel(const int* __restrict__ n2e,
                                                  const float* __restrict__ ps,
                                                  const float* __restrict__ qe,
                                                  const float* __restrict__ edges,
                                                  float* __restrict__ nag)
{
    int t = threadIdx.x, w = t >> 5, lane = t & 31;
    int n = blockIdx.x * 8 + w;
    int idx[Kk];
    #pragma unroll
    for (int k = 0; k < Kk; k++) idx[k] = n2e[(size_t)n * Kk + k];
    float al[Hh][Kk];
    #pragma unroll
    for (int h = 0; h < Hh; h++) {
        float bs = ps[(size_t)n * Hh + h];
        float s[Kk]; float m = -1e30f;
        #pragma unroll
        for (int k = 0; k < Kk; k++) {
            float sv = bs + qe[(size_t)idx[k] * Hh + h];
            sv = sv > 0.f ? sv : 0.2f * sv;
            s[k] = sv; m = fmaxf(m, sv);
        }
        float sum = 0.f;
        #pragma unroll
        for (int k = 0; k < Kk; k++) { s[k] = __expf(s[k] - m); sum += s[k]; }
        float inv = 1.f / sum;
        #pragma unroll
        for (int k = 0; k < Kk; k++) al[h][k] = s[k] * inv;
    }
    float4 a0[Hh] = {}, a1[Hh] = {};
    #pragma unroll
    for (int k = 0; k < Kk; k++) {
        const float4* er = (const float4*)(edges + (size_t)idx[k] * Dd);
        float4 ea = er[lane], eb = er[32 + lane];
        #pragma unroll
        for (int h = 0; h < Hh; h++) {
            float a = al[h][k];
            a0[h].x += a * ea.x; a0[h].y += a * ea.y; a0[h].z += a * ea.z; a0[h].w += a * ea.w;
            a1[h].x += a * eb.x; a1[h].y += a * eb.y; a1[h].z += a * eb.z; a1[h].w += a * eb.w;
        }
    }
    #pragma unroll
    for (int h = 0; h < Hh; h++) {
        float* dst = nag + ((size_t)h * Nn + n) * Dd;
        *(float4*)(dst + lane * 4) = a0[h];
        *(float4*)(dst + 128 + lane * 4) = a1[h];
    }
}

// ---------------- launcher ----------------
extern "C" void kernel_launch(void* const* d_in, const int* in_sizes, int n_in,
                              void* d_out, int out_size)
{
    (void)in_sizes; (void)n_in; (void)out_size;
    const float* feats    = (const float*)d_in[0];
    const float* edge_emb = (const float*)d_in[1];
    const int*   ena      = (const int*)d_in[2];
    const int*   n2e      = (const int*)d_in[3];
    const float* Wp0      = (const float*)d_in[4];
    const float* Wp1      = (const float*)d_in[5];
    const float* Wep      = (const float*)d_in[6];
    const float* a_e      = (const float*)d_in[7];
    const float* a_n      = (const float*)d_in[8];
    const float* W_e      = (const float*)d_in[9];
    const float* a_s      = (const float*)d_in[10];
    const float* a_edge   = (const float*)d_in[11];
    const float* W_self   = (const float*)d_in[12];
    const float* W_nb     = (const float*)d_in[13];
    float* out = (float*)d_out;

    float *xb, *YB, *NP, *EW2B, *eB, *nag, *pnB, *beB, *psB, *qeB;
    float *WpT, *Bt5B, *WfYSB, *WcB, *avfB, *av256B;
    cudaGetSymbolAddress((void**)&xb,     g_x);
    cudaGetSymbolAddress((void**)&YB,     g_Y);
    cudaGetSymbolAddress((void**)&NP,     g_NP);
    cudaGetSymbolAddress((void**)&EW2B,   g_EW2);
    cudaGetSymbolAddress((void**)&eB,     g_eB);
    cudaGetSymbolAddress((void**)&nag,    g_nag);
    cudaGetSymbolAddress((void**)&pnB,    g_pn);
    cudaGetSymbolAddress((void**)&beB,    g_be);
    cudaGetSymbolAddress((void**)&psB,    g_ps);
    cudaGetSymbolAddress((void**)&qeB,    g_qe);
    cudaGetSymbolAddress((void**)&WpT,    g_WpT);
    cudaGetSymbolAddress((void**)&Bt5B,   g_Bt5);
    cudaGetSymbolAddress((void**)&WfYSB,  g_WfYS);
    cudaGetSymbolAddress((void**)&WcB,    g_Wc);
    cudaGetSymbolAddress((void**)&avfB,   g_avf);
    cudaGetSymbolAddress((void**)&av256B, g_av256);

    // smem sizes: (2*ASZ + 2*BSZ) * 2 buffers * 2 bytes
    constexpr int SM_64_128 = (2 * 64 * 40 + 2 * 128 * 40) * 2 * 2;  // 61440
    constexpr int SM_64_64  = (2 * 64 * 40 + 2 * 64 * 40) * 2 * 2;   // 40960
    cudaFuncSetAttribute((void*)gemm_mma<64, 128, 0>, cudaFuncAttributeMaxDynamicSharedMemorySize, SM_64_128);
    cudaFuncSetAttribute((void*)gemm_mma<64, 128, 2>, cudaFuncAttributeMaxDynamicSharedMemorySize, SM_64_128);
    cudaFuncSetAttribute((void*)gemm_mma<64, 128, 3>, cudaFuncAttributeMaxDynamicSharedMemorySize, SM_64_128);
    cudaFuncSetAttribute((void*)gemm_mma<64, 64, 0>,  cudaFuncAttributeMaxDynamicSharedMemorySize, SM_64_64);

    dim3 blk(256);
    dim3 gN(Nn / 64, 2);
    dim3 gE2(Ee / 64, 2, 2);
    dim3 gH(Nn / 64, 1, Hh);

    cudaStream_t ms = 0;
    cudaStream_t s2 = g_ss.s;

    auto Bt5_   = [&](int mp) { return Bt5B   + (size_t)mp * 5 * Dd * Dd; };
    auto Wc_    = [&](int mp) { return WcB    + (size_t)mp * 2 * Dd * EDd; };
    auto WfYS_  = [&](int mp) { return WfYSB  + (size_t)mp * 2 * Dd * Dd; };
    auto avf_   = [&](int mp) { return avfB   + (size_t)mp * 2 * Hh * EDd; };
    auto av256_ = [&](int mp) { return av256B + (size_t)mp * 2 * Hh * Dd; };
    auto pn_    = [&](int mp) { return pnB + (size_t)mp * Nn * Hh; };
    auto ps_    = [&](int mp) { return psB + (size_t)mp * Nn * Hh; };
    auto be_    = [&](int mp) { return beB + (size_t)mp * Ee * Hh; };
    auto qe_    = [&](int mp) { return qeB + (size_t)mp * Ee * Hh; };
    auto Y_     = [&](int mp) { return YB + (size_t)mp * Nn * Dd; };
    auto EW2_   = [&](int mp) { return EW2B + (size_t)mp * 2 * Ee * Dd; };

    // ---- s2: input-only folds first (no deps) ----
    for (int mp = 0; mp < NMPc; mp++) {
        size_t pl0 = (size_t)(mp * DEPTHc + 0);
        foldA2p<<<Hh, blk, 0, s2>>>(Wep + (size_t)mp * EDd * Dd,
                                    a_e + pl0 * Hh * Dd, a_edge + pl0 * Hh * Dd, avf_(mp));
    }

    // ---- ms: WpT -> mp0 weight folds -> mp0 front GEMMs ----
    pack2d2<<<dim3(256, 1, 2), blk, 0, ms>>>(Wp0, Wp1, WpT);
    cudaEventRecord(g_ss.evWpT, ms);

    pack_hdp5<<<dim3(256, 1, 5), blk, 0, ms>>>(W_e    + 0 * Hh * Dd * PHp,
                                               W_self + 0 * Hh * Dd * PHp,
                                               W_nb   + 0 * Hh * Dd * PHp,
                                               W_self + 1 * Hh * Dd * PHp,
                                               W_nb   + 1 * Hh * Dd * PHp, Bt5_(0));
    foldW256_2<<<dim3(256, 1, 2), blk, 0, ms>>>(WpT, Bt5_(0), WfYS_(0));
    foldW2<<<dim3(256, 1, 2), blk, 0, ms>>>(Wep, Bt5_(0), Wc_(0));

    gemm_mma<64, 128, 0><<<gN, blk, SM_64_128, ms>>>(feats, WfYS_(0), Y_(0), Dd, Dd, 0, 0, 0,
                                                     nullptr, nullptr, nullptr, nullptr, nullptr);
    gemm_mma<64, 128, 0><<<gE2, blk, SM_64_128, ms>>>(edge_emb, Wc_(0), EW2_(0), EDd, Dd,
                                                      0, (size_t)Dd * EDd, (size_t)Ee * Dd,
                                                      nullptr, nullptr, nullptr, nullptr, nullptr);
    cudaEventRecord(g_ss.evMS0, ms);

    // ---- s2: attention-vector folds + rowdots + mp1 weight folds + (gated) mp1 front GEMMs ----
    cudaStreamWaitEvent(s2, g_ss.evWpT, 0);
    {
        size_t pl0m0 = 0, pl0m1 = (size_t)DEPTHc;
        foldA256_2<<<dim3(Hh, 1, 2), blk, 0, s2>>>(WpT, a_n + pl0m0 * Hh * Dd, a_s + pl0m0 * Hh * Dd, av256_(0));
        rowdot2<<<Nn / 8, blk, 0, s2>>>(feats, av256_(0), av256_(0) + Hh * Dd, pn_(0), ps_(0));
        rowdot2_64<<<Ee / 8, blk, 0, s2>>>(edge_emb, avf_(0), be_(0), qe_(0));
        cudaEventRecord(g_ss.evRD0, s2);

        foldA256_2<<<dim3(Hh, 1, 2), blk, 0, s2>>>(WpT, a_n + pl0m1 * Hh * Dd, a_s + pl0m1 * Hh * Dd, av256_(1));
        rowdot2<<<Nn / 8, blk, 0, s2>>>(feats, av256_(1), av256_(1) + Hh * Dd, pn_(1), ps_(1));
        rowdot2_64<<<Ee / 8, blk, 0, s2>>>(edge_emb + (size_t)Ee * EDd, avf_(1), be_(1), qe_(1));

        size_t pl0 = (size_t)DEPTHc, pl1 = (size_t)DEPTHc + 1;
        pack_hdp5<<<dim3(256, 1, 5), blk, 0, s2>>>(W_e    + pl0 * Hh * Dd * PHp,
                                                   W_self + pl0 * Hh * Dd * PHp,
                                                   W_nb   + pl0 * Hh * Dd * PHp,
                                                   W_self + pl1 * Hh * Dd * PHp,
                                                   W_nb   + pl1 * Hh * Dd * PHp, Bt5_(1));
        foldW256_2<<<dim3(256, 1, 2), blk, 0, s2>>>(WpT, Bt5_(1), WfYS_(1));
        foldW2<<<dim3(256, 1, 2), blk, 0, s2>>>(Wep + (size_t)EDd * Dd, Bt5_(1), Wc_(1));

        cudaStreamWaitEvent(s2, g_ss.evMS0, 0);
        gemm_mma<64, 128, 0><<<gN, blk, SM_64_128, s2>>>(feats, WfYS_(1), Y_(1), Dd, Dd, 0, 0, 0,
                                                         nullptr, nullptr, nullptr, nullptr, nullptr);
        gemm_mma<64, 128, 0><<<gE2, blk, SM_64_128, s2>>>(edge_emb + (size_t)Ee * EDd, Wc_(1), EW2_(1), EDd, Dd,
                                                          0, (size_t)Dd * EDd, (size_t)Ee * Dd,
                                                          nullptr, nullptr, nullptr, nullptr, nullptr);
        cudaEventRecord(g_ss.evG1, s2);
    }

    for (int mp = 0; mp < NMPc; mp++) {
        const int*   ena_mp = ena + (size_t)mp * Ee * 2;
        const int*   n2e_mp = n2e + (size_t)mp * Nn * Kk;
        float* outmp = out + (size_t)mp * Nn * DEPTHc * Dd;
        size_t pl1 = (size_t)(mp * DEPTHc + 1);
        float* EW    = EW2_(mp);
        float* EWnb0 = EW2_(mp) + (size_t)Ee * Dd;

        if (mp == 0) {
            cudaStreamWaitEvent(ms, g_ss.evRD0, 0);
        } else {
            cudaStreamWaitEvent(ms, g_ss.evG1, 0);
        }

        // ---- edge combine (+ fused qe1 into be_(mp)) ----
        edge_comb_q<<<Ee / 4, blk, 0, ms>>>(ena_mp, pn_(mp), be_(mp), EW, Y_(mp),
                                            a_edge + pl1 * Hh * Dd, eB, be_(mp));

        // ---- L0 node aggregator (projected) ----
        nagp_kernel<<<Nn / 8, blk, 0, ms>>>(n2e_mp, ps_(mp), qe_(mp), EWnb0, NP);

        // ---- fused S GEMM: elu(feats@WfS + NP) -> out, xb; ps_L1 atomics ----
        cudaMemsetAsync(ps_(mp), 0, (size_t)Nn * Hh * sizeof(float), ms);
        gemm_mma<64, 128, 3><<<gN, blk, SM_64_128, ms>>>(feats, WfYS_(mp) + Dd * Dd, nullptr, Dd, Dd, 0, 0, 0,
                                                         a_s + pl1 * Hh * Dd, NP, outmp, xb, ps_(mp));

        // ---- L1 node aggregator ----
        nag_kernel<<<Nn / 8, blk, 0, ms>>>(n2e_mp, ps_(mp), be_(mp), eB, nag);
        gemm_mma<64, 64, 0><<<gH, blk, SM_64_64, ms>>>(nag, Bt5_(mp) + (size_t)4 * Dd * Dd, NP, Dd, Dd,
                                                       (size_t)Nn * Dd, (size_t)PHp * Dd, (size_t)PHp,
                                                       nullptr, nullptr, nullptr, nullptr, nullptr);

        // ---- fused final GEMM: elu(xb@Wself1 + NP) -> out[:, Dd:] ----
        gemm_mma<64, 128, 2><<<gN, blk, SM_64_128, ms>>>(xb, Bt5_(mp) + (size_t)3 * Dd * Dd, nullptr, Dd, Dd, 0, 0, 0,
                                                         nullptr, NP, outmp, nullptr, nullptr);
    }
}

// round 16
// speedup vs baseline: 1.0351x; 1.0013x over previous
#include <cuda_runtime.h>
#include <cuda_bf16.h>
#include <math.h>
#include <stdint.h>

#define Nn 65536
#define Ee 262144
#define Kk 8
#define NMPc 2
#define DEPTHc 2
#define Hh 4
#define Dd 256
#define PHp 64
#define EDd 64

// ---------------- scratch (device globals; no allocation allowed) ----------------
__device__ __align__(16) float g_x    [(size_t)2 * Nn * Dd];        // per-mp
__device__ __align__(16) float g_Y    [(size_t)2 * Nn * Dd];        // per-mp
__device__ __align__(16) float g_NP   [(size_t)2 * Nn * Dd];        // per-mp
__device__ __align__(16) float g_EW2  [(size_t)2 * 2 * Ee * Dd];    // per-mp: [0]=EW, [1]=EWnb0
__device__ __align__(16) float g_eB   [(size_t)2 * Ee * Dd];        // per-mp
__device__ __align__(16) float g_nag  [(size_t)2 * Hh * Nn * Dd];   // per-mp
// per-mp doubled small state
__device__ __align__(16) float g_pn   [(size_t)2 * Nn * Hh];
__device__ __align__(16) float g_be   [(size_t)2 * Ee * Hh];   // be (L0), then qe1 (L1)
__device__ __align__(16) float g_ps   [(size_t)2 * Nn * Hh];
__device__ __align__(16) float g_qe   [(size_t)2 * Ee * Hh];   // qe0
__device__ __align__(16) float g_WpT  [2 * Dd * Dd];           // [0]=Wp0^T, [1]=Wp1^T
__device__ __align__(16) float g_Bt5  [2 * 5 * Dd * Dd];
__device__ __align__(16) float g_WfYS [2 * 2 * Dd * Dd];       // per-mp [0]=WfY, [1]=WfS
__device__ __align__(16) float g_Wc   [2 * 2 * Dd * EDd];
__device__ __align__(16) float g_avf  [2 * 2 * Hh * EDd];
__device__ __align__(16) float g_av256[2 * 2 * Hh * Dd];

// ---------------- side stream + events (static init: before harness mem checkpoints) ----------------
namespace {
struct SideStream {
    cudaStream_t s;
    cudaEvent_t evWpT, evRD0, evMS0, evEnd;
    SideStream() {
        cudaStreamCreateWithFlags(&s, cudaStreamNonBlocking);
        cudaEventCreateWithFlags(&evWpT, cudaEventDisableTiming);
        cudaEventCreateWithFlags(&evRD0, cudaEventDisableTiming);
        cudaEventCreateWithFlags(&evMS0, cudaEventDisableTiming);
        cudaEventCreateWithFlags(&evEnd, cudaEventDisableTiming);
    }
};
SideStream g_ss;
}

// ---------------- HMMA helper ----------------
__device__ __forceinline__ void mma16816(float* c, const uint32_t* a, uint32_t b0, uint32_t b1) {
    asm volatile("mma.sync.aligned.m16n8k16.row.col.f32.bf16.bf16.f32 "
                 "{%0,%1,%2,%3}, {%4,%5,%6,%7}, {%8,%9}, {%0,%1,%2,%3};"
                 : "+f"(c[0]), "+f"(c[1]), "+f"(c[2]), "+f"(c[3])
                 : "r"(a[0]), "r"(a[1]), "r"(a[2]), "r"(a[3]), "r"(b0), "r"(b1));
}

__device__ __forceinline__ void split4(float4 v, uint2& hi, uint2& lo) {
    __nv_bfloat16 h0 = __float2bfloat16(v.x), h1 = __float2bfloat16(v.y);
    __nv_bfloat16 h2 = __float2bfloat16(v.z), h3 = __float2bfloat16(v.w);
    __nv_bfloat16 l0 = __float2bfloat16(v.x - __bfloat162float(h0));
    __nv_bfloat16 l1 = __float2bfloat16(v.y - __bfloat162float(h1));
    __nv_bfloat16 l2 = __float2bfloat16(v.z - __bfloat162float(h2));
    __nv_bfloat16 l3 = __float2bfloat16(v.w - __bfloat162float(h3));
    union { __nv_bfloat162 b[2]; uint2 u; } ph, pl;
    ph.b[0] = __nv_bfloat162(h0, h1); ph.b[1] = __nv_bfloat162(h2, h3);
    pl.b[0] = __nv_bfloat162(l0, l1); pl.b[1] = __nv_bfloat162(l2, l3);
    hi = ph.u; lo = pl.u;
}

__device__ __forceinline__ float elu1(float x) { return x > 0.f ? x : expm1f(x); }

// ---------------- pipelined bf16-split HMMA GEMM (BM x BN tile, 2 CTAs/SM at BM=64) ----------------
template <int BM, int BN, int EPI>
__global__ __launch_bounds__(256, 2) void gemm_mma(const float* __restrict__ A,
                                                   const float* __restrict__ Bt,
                                                   float* __restrict__ C,
                                                   int K, int ldc,
                                                   size_t sAz, size_t sBz, size_t sCz,
                                                   const float* __restrict__ a1v,
                                                   const float* __restrict__ NPp,
                                                   float* __restrict__ outp,
                                                   float* __restrict__ xoutp,
                                                   float* __restrict__ psout)
{
    constexpr int NWN = (BM == 64) ? 4 : 2;
    constexpr int NT  = BN / (8 * NWN);
    constexpr int NA  = BM / 32;
    constexpr int NB  = BN / 32;
    constexpr int ASZ = BM * 40;
    constexpr int BSZ = BN * 40;
    constexpr int BUFE = 2 * ASZ + 2 * BSZ;
    extern __shared__ uint16_t sm[];

    A  += blockIdx.z * sAz;
    Bt += blockIdx.z * sBz;
    C  += blockIdx.z * sCz;

    int t = threadIdx.x, wid = t >> 5, lane = t & 31;
    int g = lane >> 2, tg = lane & 3;
    int wm = (wid / NWN) * 32;
    int wn = (wid % NWN) * (BN / NWN);
    size_t m0 = (size_t)blockIdx.x * BM;
    size_t n0 = (size_t)blockIdx.y * BN;
    const float* Abase = A + m0 * K;
    const float* Bbase = Bt + n0 * K;

    float acc[2][NT][4];
    #pragma unroll
    for (int mt = 0; mt < 2; mt++)
        #pragma unroll
        for (int nt = 0; nt < NT; nt++)
            #pragma unroll
            for (int j = 0; j < 4; j++) acc[mt][nt][j] = 0.f;

    float4 pa[NA], pb[NB];
    auto ldAB = [&](int kb) {
        #pragma unroll
        for (int i = 0; i < NA; i++) {
            int id = t + 256 * i, r = id >> 3, c4 = id & 7;
            pa[i] = *(const float4*)(Abase + (size_t)r * K + kb * 32 + c4 * 4);
        }
        #pragma unroll
        for (int i = 0; i < NB; i++) {
            int id = t + 256 * i, r = id >> 3, c4 = id & 7;
            pb[i] = *(const float4*)(Bbase + (size_t)r * K + kb * 32 + c4 * 4);
        }
    };
    auto stAB = [&](int buf) {
        uint16_t* bAh = sm + buf * BUFE;
        uint16_t* bAl = bAh + ASZ;
        uint16_t* bBh = bAl + ASZ;
        uint16_t* bBl = bBh + BSZ;
        #pragma unroll
        for (int i = 0; i < NA; i++) {
            int id = t + 256 * i, r = id >> 3, c4 = id & 7;
            uint2 hi, lo; split4(pa[i], hi, lo);
            *(uint2*)&bAh[r * 40 + c4 * 4] = hi;
            *(uint2*)&bAl[r * 40 + c4 * 4] = lo;
        }
        #pragma unroll
        for (int i = 0; i < NB; i++) {
            int id = t + 256 * i, r = id >> 3, c4 = id & 7;
            uint2 hi, lo; split4(pb[i], hi, lo);
            *(uint2*)&bBh[r * 40 + c4 * 4] = hi;
            *(uint2*)&bBl[r * 40 + c4 * 4] = lo;
        }
    };
    auto domma = [&](int buf) {
        const uint16_t* bAh = sm + buf * BUFE;
        const uint16_t* bAl = bAh + ASZ;
        const uint16_t* bBh = bAl + ASZ;
        const uint16_t* bBl = bBh + BSZ;
        #pragma unroll
        for (int ks = 0; ks < 2; ks++) {
            int kc = ks * 16 + tg * 2;
            uint32_t ah[2][4], al_[2][4];
            #pragma unroll
            for (int mt = 0; mt < 2; mt++) {
                int row = wm + mt * 16 + g;
                ah[mt][0]  = *(const uint32_t*)&bAh[row * 40 + kc];
                ah[mt][1]  = *(const uint32_t*)&bAh[(row + 8) * 40 + kc];
                ah[mt][2]  = *(const uint32_t*)&bAh[row * 40 + kc + 8];
                ah[mt][3]  = *(const uint32_t*)&bAh[(row + 8) * 40 + kc + 8];
                al_[mt][0] = *(const uint32_t*)&bAl[row * 40 + kc];
                al_[mt][1] = *(const uint32_t*)&bAl[(row + 8) * 40 + kc];
                al_[mt][2] = *(const uint32_t*)&bAl[row * 40 + kc + 8];
                al_[mt][3] = *(const uint32_t*)&bAl[(row + 8) * 40 + kc + 8];
            }
            #pragma unroll
            for (int nt = 0; nt < NT; nt++) {
                int col = wn + nt * 8 + g;
                uint32_t bh0 = *(const uint32_t*)&bBh[col * 40 + kc];
                uint32_t bh1 = *(const uint32_t*)&bBh[col * 40 + kc + 8];
                uint32_t bl0 = *(const uint32_t*)&bBl[col * 40 + kc];
                uint32_t bl1 = *(const uint32_t*)&bBl[col * 40 + kc + 8];
                #pragma unroll
                for (int mt = 0; mt < 2; mt++) {
                    mma16816(acc[mt][nt], ah[mt],  bh0, bh1);
                    mma16816(acc[mt][nt], al_[mt], bh0, bh1);
                    mma16816(acc[mt][nt], ah[mt],  bl0, bl1);
                }
            }
        }
    };

    int nkb = K >> 5;
    ldAB(0);
    stAB(0);
    __syncthreads();
    for (int kb = 0; kb < nkb; kb++) {
        int cur = kb & 1;
        if (kb + 1 < nkb) ldAB(kb + 1);
        domma(cur);
        if (kb + 1 < nkb) stAB(cur ^ 1);
        __syncthreads();
    }

    if (EPI == 0) {
        #pragma unroll
        for (int mt = 0; mt < 2; mt++) {
            size_t row = m0 + wm + mt * 16 + g;
            #pragma unroll
            for (int nt = 0; nt < NT; nt++) {
                size_t col = n0 + wn + nt * 8 + tg * 2;
                *(float2*)(C + row * ldc + col)       = make_float2(acc[mt][nt][0], acc[mt][nt][1]);
                *(float2*)(C + (row + 8) * ldc + col) = make_float2(acc[mt][nt][2], acc[mt][nt][3]);
            }
        }
    } else {
        constexpr int Lofs = (EPI == 3) ? 0 : Dd;
        float* sa1 = (float*)sm;
        if (EPI == 3) {
            for (int i = t; i < 4 * BN; i += 256) {
                int h = i / BN, c = i % BN;
                sa1[i] = a1v[(size_t)h * Dd + n0 + c];
            }
            __syncthreads();
        }
        float qp[4][Hh];
        if (EPI == 3) {
            #pragma unroll
            for (int j = 0; j < 4; j++)
                #pragma unroll
                for (int h = 0; h < Hh; h++) qp[j][h] = 0.f;
        }
        #pragma unroll
        for (int mt = 0; mt < 2; mt++) {
            #pragma unroll
            for (int rp = 0; rp < 2; rp++) {
                size_t grow = m0 + wm + mt * 16 + g + rp * 8;
                #pragma unroll
                for (int nt = 0; nt < NT; nt++) {
                    int cloc = wn + nt * 8 + tg * 2;
                    size_t gc = n0 + cloc;
                    float2 np = *(const float2*)(NPp + grow * Dd + gc);
                    float r0 = elu1(acc[mt][nt][rp * 2 + 0] + np.x);
                    float r1 = elu1(acc[mt][nt][rp * 2 + 1] + np.y);
                    *(float2*)(outp + grow * (DEPTHc * Dd) + Lofs + gc) = make_float2(r0, r1);
                    if (EPI == 3) {
                        *(float2*)(xoutp + grow * Dd + gc) = make_float2(r0, r1);
                        #pragma unroll
                        for (int h = 0; h < Hh; h++)
                            qp[mt * 2 + rp][h] += r0 * sa1[h * BN + cloc] + r1 * sa1[h * BN + cloc + 1];
                    }
                }
            }
        }
        if (EPI == 3) {
            #pragma unroll
            for (int j = 0; j < 4; j++)
                #pragma unroll
                for (int h = 0; h < Hh; h++) {
                    qp[j][h] += __shfl_xor_sync(0xffffffffu, qp[j][h], 1);
                    qp[j][h] += __shfl_xor_sync(0xffffffffu, qp[j][h], 2);
                }
            if (tg == 0) {
                #pragma unroll
                for (int mt = 0; mt < 2; mt++)
                    #pragma unroll
                    for (int rp = 0; rp < 2; rp++) {
                        size_t grow = m0 + wm + mt * 16 + g + rp * 8;
                        #pragma unroll
                        for (int h = 0; h < Hh; h++)
                            atomicAdd(&psout[grow * Hh + h], qp[mt * 2 + rp][h]);
                    }
            }
        }
    }
}

// ---------------- packing / folding ----------------
__global__ void pack2d2(const float* __restrict__ s0, const float* __restrict__ s1,
                        float* __restrict__ dst) {
    int z = blockIdx.z;
    const float* src = z ? s1 : s0;
    int id = blockIdx.x * 256 + threadIdx.x;
    int c = id % Dd, k = id / Dd;
    dst[(size_t)z * Dd * Dd + (size_t)c * Dd + k] = src[id];
}

__global__ void pack_hdp5(const float* __restrict__ s0, const float* __restrict__ s1,
                          const float* __restrict__ s2, const float* __restrict__ s3,
                          const float* __restrict__ s4, float* __restrict__ dst) {
    int z = blockIdx.z;
    const float* src = (z == 0) ? s0 : (z == 1) ? s1 : (z == 2) ? s2 : (z == 3) ? s3 : s4;
    int id = blockIdx.x * 256 + threadIdx.x;
    int p = id % PHp, d = (id / PHp) % Dd, h = id / (PHp * Dd);
    dst[(size_t)z * Dd * Dd + (size_t)(h * PHp + p) * Dd + d] = src[id];
}

__global__ __launch_bounds__(256) void foldW2(const float* __restrict__ Wep,
                                              const float* __restrict__ Bt5,
                                              float* __restrict__ Wc)
{
    __shared__ float sb[256];
    __shared__ float sred[4][64];
    int z = blockIdx.z;
    const float* BtW = Bt5 + (size_t)(z == 0 ? 0 : 2) * Dd * Dd;
    float* dst = Wc + (size_t)z * Dd * EDd;
    int c = blockIdx.x, t = threadIdx.x;
    sb[t] = BtW[(size_t)c * 256 + t];
    __syncthreads();
    int j = t & 63, q = t >> 6;
    const float* wr  = Wep + (size_t)j * 256 + q * 64;
    const float* sbp = sb + q * 64;
    float acc = 0.f;
    #pragma unroll 16
    for (int d = 0; d < 64; d++) acc += wr[d] * sbp[d];
    sred[q][j] = acc;
    __syncthreads();
    if (t < 64) dst[(size_t)c * 64 + t] = sred[0][t] + sred[1][t] + sred[2][t] + sred[3][t];
}

__global__ __launch_bounds__(256) void foldW256_2(const float* __restrict__ WpT,
                                                  const float* __restrict__ Bt5,
                                                  float* __restrict__ Wf)
{
    __shared__ float sb[256];
    int z = blockIdx.z;
    const float* WpTz = WpT + (size_t)(z == 0 ? 1 : 0) * Dd * Dd;
    const float* BtW = Bt5 + (size_t)z * Dd * Dd;
    float* dst = Wf + (size_t)z * Dd * Dd;
    int c = blockIdx.x, d = threadIdx.x;
    sb[d] = BtW[(size_t)c * 256 + d];
    __syncthreads();
    float acc = 0.f;
    #pragma unroll 4
    for (int dp = 0; dp < 256; dp++) acc += WpTz[(size_t)dp * 256 + d] * sb[dp];
    dst[(size_t)c * 256 + d] = acc;
}

__global__ __launch_bounds__(256) void foldA256_2(const float* __restrict__ WpT,
                                                  const float* __restrict__ an,
                                                  const float* __restrict__ as,
                                                  float* __restrict__ outp)
{
    __shared__ float sa[256];
    int z = blockIdx.z;
    const float* WpTz = WpT + (size_t)(z == 0 ? 1 : 0) * Dd * Dd;
    const float* a = (z == 0) ? an : as;
    int h = blockIdx.x, d = threadIdx.x;
    sa[d] = a[(size_t)h * 256 + d];
    __syncthreads();
    float acc = 0.f;
    #pragma unroll 4
    for (int dp = 0; dp < 256; dp++) acc += WpTz[(size_t)dp * 256 + d] * sa[dp];
    outp[(size_t)z * Hh * Dd + (size_t)h * 256 + d] = acc;
}

__global__ __launch_bounds__(256) void foldA2p(const float* __restrict__ Wep,
                                               const float* __restrict__ a1,
                                               const float* __restrict__ a2,
                                               float* __restrict__ outp)
{
    __shared__ float s1[256], s2[256];
    __shared__ float r1[4][64], r2[4][64];
    int h = blockIdx.x, t = threadIdx.x;
    s1[t] = a1[(size_t)h * 256 + t];
    s2[t] = a2[(size_t)h * 256 + t];
    __syncthreads();
    int j = t & 63, q = t >> 6;
    const float* wr = Wep + (size_t)j * 256 + q * 64;
    float A = 0.f, B = 0.f;
    #pragma unroll 16
    for (int d = 0; d < 64; d++) { float w = wr[d]; A += w * s1[q * 64 + d]; B += w * s2[q * 64 + d]; }
    r1[q][j] = A; r2[q][j] = B;
    __syncthreads();
    if (t < 64) outp[h * 64 + t] = r1[0][t] + r1[1][t] + r1[2][t] + r1[3][t];
    else if (t < 128) {
        int j2 = t - 64;
        outp[Hh * 64 + h * 64 + j2] = r2[0][j2] + r2[1][j2] + r2[2][j2] + r2[3][j2];
    }
}

// ---------------- dual row-dot (D=256) ----------------
__global__ __launch_bounds__(256) void rowdot2(const float* __restrict__ X,
                                               const float* __restrict__ avec1,
                                               const float* __restrict__ avec2,
                                               float* __restrict__ P1,
                                               float* __restrict__ P2)
{
    __shared__ float sa[2 * Hh * Dd];
    int t = threadIdx.x;
    for (int i = t; i < Hh * Dd; i += 256) { sa[i] = avec1[i]; sa[Hh * Dd + i] = avec2[i]; }
    __syncthreads();
    int row = blockIdx.x * 8 + (t >> 5);
    int lane = t & 31;
    const float* xr = X + (size_t)row * Dd;
    float a1[Hh] = {}, a2[Hh] = {};
    #pragma unroll
    for (int j = 0; j < 8; j++) {
        float xv = xr[lane + 32 * j];
        #pragma unroll
        for (int h = 0; h < Hh; h++) {
            a1[h] += sa[h * Dd + lane + 32 * j] * xv;
            a2[h] += sa[Hh * Dd + h * Dd + lane + 32 * j] * xv;
        }
    }
    #pragma unroll
    for (int h = 0; h < Hh; h++) {
        #pragma unroll
        for (int o = 16; o > 0; o >>= 1) {
            a1[h] += __shfl_down_sync(0xffffffffu, a1[h], o);
            a2[h] += __shfl_down_sync(0xffffffffu, a2[h], o);
        }
    }
    if (lane == 0) {
        #pragma unroll
        for (int h = 0; h < Hh; h++) {
            P1[(size_t)row * Hh + h] = a1[h];
            P2[(size_t)row * Hh + h] = a2[h];
        }
    }
}

// ---------------- dual row-dot over D=64 rows (edge_emb) ----------------
__global__ __launch_bounds__(256) void rowdot2_64(const float* __restrict__ X,
                                                  const float* __restrict__ avf,
                                                  float* __restrict__ P1,
                                                  float* __restrict__ P2)
{
    __shared__ float sa[2 * Hh * 64];
    int t = threadIdx.x;
    for (int i = t; i < 2 * Hh * 64; i += 256) sa[i] = avf[i];
    __syncthreads();
    int row = blockIdx.x * 8 + (t >> 5);
    int lane = t & 31;
    const float* xr = X + (size_t)row * 64;
    float x0 = xr[lane], x1 = xr[lane + 32];
    float a1[Hh], a2[Hh];
    #pragma unroll
    for (int h = 0; h < Hh; h++) {
        a1[h] = sa[h * 64 + lane] * x0 + sa[h * 64 + lane + 32] * x1;
        a2[h] = sa[256 + h * 64 + lane] * x0 + sa[256 + h * 64 + lane + 32] * x1;
    }
    #pragma unroll
    for (int h = 0; h < Hh; h++) {
        #pragma unroll
        for (int o = 16; o > 0; o >>= 1) {
            a1[h] += __shfl_down_sync(0xffffffffu, a1[h], o);
            a2[h] += __shfl_down_sync(0xffffffffu, a2[h], o);
        }
    }
    if (lane == 0) {
        #pragma unroll
        for (int h = 0; h < Hh; h++) {
            P1[(size_t)row * Hh + h] = a1[h];
            P2[(size_t)row * Hh + h] = a2[h];
        }
    }
}

// ---------------- edge combine + fused qe1 ----------------
__global__ __launch_bounds__(256) void edge_comb_q(const int* __restrict__ ena,
                                                   const float* __restrict__ pn,
                                                   const float* __restrict__ be,
                                                   const float* __restrict__ EW,
                                                   const float* __restrict__ Y,
                                                   const float* __restrict__ a1v,
                                                   float* __restrict__ eout,
                                                   float* __restrict__ qe1)
{
    __shared__ float sa1[Hh * Dd];
    __shared__ float sred[4][2][Hh];
    int t = threadIdx.x;
    for (int i = t; i < Hh * Dd; i += 256) sa1[i] = a1v[i];
    __syncthreads();

    int e0 = blockIdx.x * 4;
    int el = t >> 6, c4 = t & 63, h = c4 >> 4;
    int e = e0 + el;
    int u = ena[2 * e], v = ena[2 * e + 1];
    float b = be[(size_t)e * Hh + h];
    float s0 = pn[(size_t)u * Hh + h] + b;
    float s1 = pn[(size_t)v * Hh + h] + b;
    s0 = s0 > 0.f ? s0 : 0.2f * s0;
    s1 = s1 > 0.f ? s1 : 0.2f * s1;
    float m = fmaxf(s0, s1);
    float x0 = __expf(s0 - m), x1 = __expf(s1 - m);
    float inv = 1.f / (x0 + x1);
    float al0 = x0 * inv, al1 = x1 * inv;
    float4 ew = *(const float4*)(EW + (size_t)e * Dd + c4 * 4);
    float4 yu = *(const float4*)(Y + (size_t)u * Dd + c4 * 4);
    float4 yv = *(const float4*)(Y + (size_t)v * Dd + c4 * 4);
    float4 r;
    r.x = elu1(ew.x + al0 * yu.x + al1 * yv.x);
    r.y = elu1(ew.y + al0 * yu.y + al1 * yv.y);
    r.z = elu1(ew.z + al0 * yu.z + al1 * yv.z);
    r.w = elu1(ew.w + al0 * yu.w + al1 * yv.w);
    *(float4*)(eout + (size_t)e * Dd + c4 * 4) = r;

    float p[Hh];
    #pragma unroll
    for (int hh = 0; hh < Hh; hh++) {
        const float* av = sa1 + hh * Dd + c4 * 4;
        p[hh] = r.x * av[0] + r.y * av[1] + r.z * av[2] + r.w * av[3];
    }
    #pragma unroll
    for (int hh = 0; hh < Hh; hh++) {
        #pragma unroll
        for (int o = 16; o > 0; o >>= 1) p[hh] += __shfl_down_sync(0xffffffffu, p[hh], o);
    }
    int wl = t & 31, whalf = (t >> 5) & 1;
    if (wl == 0) {
        #pragma unroll
        for (int hh = 0; hh < Hh; hh++) sred[el][whalf][hh] = p[hh];
    }
    __syncthreads();
    if (t < 16) {
        int ee = t >> 2, hh = t & 3;
        qe1[(size_t)(e0 + ee) * Hh + hh] = sred[ee][0][hh] + sred[ee][1][hh];
    }
}

// ---------------- L0 node agg, projected ----------------
__global__ __launch_bounds__(256) void nagp_kernel(const int* __restrict__ n2e,
                                                   const float* __restrict__ ps,
                                                   const float* __restrict__ qe,
                                                   const float* __restrict__ EWnb,
                                                   float* __restrict__ NP)
{
    int t = threadIdx.x, w = t >> 5, lane = t & 31;
    int n = blockIdx.x * 8 + w;
    int idx[Kk];
    #pragma unroll
    for (int k = 0; k < Kk; k++) idx[k] = n2e[(size_t)n * Kk + k];
    float al[Hh][Kk];
    #pragma unroll
    for (int h = 0; h < Hh; h++) {
        float bs = ps[(size_t)n * Hh + h];
        float s[Kk]; float m = -1e30f;
        #pragma unroll
        for (int k = 0; k < Kk; k++) {
            float sv = bs + qe[(size_t)idx[k] * Hh + h];
            sv = sv > 0.f ? sv : 0.2f * sv;
            s[k] = sv; m = fmaxf(m, sv);
        }
        float sum = 0.f;
        #pragma unroll
        for (int k = 0; k < Kk; k++) { s[k] = __expf(s[k] - m); sum += s[k]; }
        float inv = 1.f / sum;
        #pragma unroll
        for (int k = 0; k < Kk; k++) al[h][k] = s[k] * inv;
    }
    int h0 = lane >> 4, h1 = 2 + (lane >> 4);
    float4 a0 = make_float4(0.f, 0.f, 0.f, 0.f), a1 = a0;
    #pragma unroll
    for (int k = 0; k < Kk; k++) {
        const float4* er = (const float4*)(EWnb + (size_t)idx[k] * Dd);
        float4 ea = er[lane], eb = er[32 + lane];
        float w0 = al[h0][k], w1 = al[h1][k];
        a0.x += w0 * ea.x; a0.y += w0 * ea.y; a0.z += w0 * ea.z; a0.w += w0 * ea.w;
        a1.x += w1 * eb.x; a1.y += w1 * eb.y; a1.z += w1 * eb.z; a1.w += w1 * eb.w;
    }
    *(float4*)(NP + (size_t)n * Dd + lane * 4)       = a0;
    *(float4*)(NP + (size_t)n * Dd + 128 + lane * 4) = a1;
}

// ---------------- L1 node aggregation (full) ----------------
__global__ __launch_bounds__(256) void nag_kernel(const int* __restrict__ n2e,
                                                  const float* __restrict__ ps,
                                                  const float* __restrict__ qe,
                                                  const float* __restrict__ edges,
                                                  float* __restrict__ nag)
{
    int t = threadIdx.x, w = t >> 5, lane = t & 31;
    int n = blockIdx.x * 8 + w;
    int idx[Kk];
    #pragma unroll
    for (int k = 0; k < Kk; k++) idx[k] = n2e[(size_t)n * Kk + k];
    float al[Hh][Kk];
    #pragma unroll
    for (int h = 0; h < Hh; h++) {
        float bs = ps[(size_t)n * Hh + h];
        float s[Kk]; float m = -1e30f;
        #pragma unroll
        for (int k = 0; k < Kk; k++) {
            float sv = bs + qe[(size_t)idx[k] * Hh + h];
            sv = sv > 0.f ? sv : 0.2f * sv;
            s[k] = sv; m = fmaxf(m, sv);
        }
        float sum = 0.f;
        #pragma unroll
        for (int k = 0; k < Kk; k++) { s[k] = __expf(s[k] - m); sum += s[k]; }
        float inv = 1.f / sum;
        #pragma unroll
        for (int k = 0; k < Kk; k++) al[h][k] = s[k] * inv;
    }
    float4 a0[Hh] = {}, a1[Hh] = {};
    #pragma unroll
    for (int k = 0; k < Kk; k++) {
        const float4* er = (const float4*)(edges + (size_t)idx[k] * Dd);
        float4 ea = er[lane], eb = er[32 + lane];
        #pragma unroll
        for (int h = 0; h < Hh; h++) {
            float a = al[h][k];
            a0[h].x += a * ea.x; a0[h].y += a * ea.y; a0[h].z += a * ea.z; a0[h].w += a * ea.w;
            a1[h].x += a * eb.x; a1[h].y += a * eb.y; a1[h].z += a * eb.z; a1[h].w += a * eb.w;
        }
    }
    #pragma unroll
    for (int h = 0; h < Hh; h++) {
        float* dst = nag + ((size_t)h * Nn + n) * Dd;
        *(float4*)(dst + lane * 4) = a0[h];
        *(float4*)(dst + 128 + lane * 4) = a1[h];
    }
}

// ---------------- launcher ----------------
extern "C" void kernel_launch(void* const* d_in, const int* in_sizes, int n_in,
                              void* d_out, int out_size)
{
    (void)in_sizes; (void)n_in; (void)out_size;
    const float* feats    = (const float*)d_in[0];
    const float* edge_emb = (const float*)d_in[1];
    const int*   ena      = (const int*)d_in[2];
    const int*   n2e      = (const int*)d_in[3];
    const float* Wp0      = (const float*)d_in[4];
    const float* Wp1      = (const float*)d_in[5];
    const float* Wep      = (const float*)d_in[6];
    const float* a_e      = (const float*)d_in[7];
    const float* a_n      = (const float*)d_in[8];
    const float* W_e      = (const float*)d_in[9];
    const float* a_s      = (const float*)d_in[10];
    const float* a_edge   = (const float*)d_in[11];
    const float* W_self   = (const float*)d_in[12];
    const float* W_nb     = (const float*)d_in[13];
    float* out = (float*)d_out;

    float *xB, *YB, *NPB, *EW2B, *eBB, *nagB, *pnB, *beB, *psB, *qeB;
    float *WpT, *Bt5B, *WfYSB, *WcB, *avfB, *av256B;
    cudaGetSymbolAddress((void**)&xB,     g_x);
    cudaGetSymbolAddress((void**)&YB,     g_Y);
    cudaGetSymbolAddress((void**)&NPB,    g_NP);
    cudaGetSymbolAddress((void**)&EW2B,   g_EW2);
    cudaGetSymbolAddress((void**)&eBB,    g_eB);
    cudaGetSymbolAddress((void**)&nagB,   g_nag);
    cudaGetSymbolAddress((void**)&pnB,    g_pn);
    cudaGetSymbolAddress((void**)&beB,    g_be);
    cudaGetSymbolAddress((void**)&psB,    g_ps);
    cudaGetSymbolAddress((void**)&qeB,    g_qe);
    cudaGetSymbolAddress((void**)&WpT,    g_WpT);
    cudaGetSymbolAddress((void**)&Bt5B,   g_Bt5);
    cudaGetSymbolAddress((void**)&WfYSB,  g_WfYS);
    cudaGetSymbolAddress((void**)&WcB,    g_Wc);
    cudaGetSymbolAddress((void**)&avfB,   g_avf);
    cudaGetSymbolAddress((void**)&av256B, g_av256);

    constexpr int SM_64_128 = (2 * 64 * 40 + 2 * 128 * 40) * 2 * 2;  // 61440
    constexpr int SM_64_64  = (2 * 64 * 40 + 2 * 64 * 40) * 2 * 2;   // 40960
    cudaFuncSetAttribute((void*)gemm_mma<64, 128, 0>, cudaFuncAttributeMaxDynamicSharedMemorySize, SM_64_128);
    cudaFuncSetAttribute((void*)gemm_mma<64, 128, 2>, cudaFuncAttributeMaxDynamicSharedMemorySize, SM_64_128);
    cudaFuncSetAttribute((void*)gemm_mma<64, 128, 3>, cudaFuncAttributeMaxDynamicSharedMemorySize, SM_64_128);
    cudaFuncSetAttribute((void*)gemm_mma<64, 64, 0>,  cudaFuncAttributeMaxDynamicSharedMemorySize, SM_64_64);

    dim3 blk(256);
    dim3 gN(Nn / 64, 2);
    dim3 gE2(Ee / 64, 2, 2);
    dim3 gH(Nn / 64, 1, Hh);

    cudaStream_t ms = 0;
    cudaStream_t s2 = g_ss.s;

    auto Bt5_   = [&](int mp) { return Bt5B   + (size_t)mp * 5 * Dd * Dd; };
    auto Wc_    = [&](int mp) { return WcB    + (size_t)mp * 2 * Dd * EDd; };
    auto WfYS_  = [&](int mp) { return WfYSB  + (size_t)mp * 2 * Dd * Dd; };
    auto avf_   = [&](int mp) { return avfB   + (size_t)mp * 2 * Hh * EDd; };
    auto av256_ = [&](int mp) { return av256B + (size_t)mp * 2 * Hh * Dd; };
    auto pn_    = [&](int mp) { return pnB + (size_t)mp * Nn * Hh; };
    auto ps_    = [&](int mp) { return psB + (size_t)mp * Nn * Hh; };
    auto be_    = [&](int mp) { return beB + (size_t)mp * Ee * Hh; };
    auto qe_    = [&](int mp) { return qeB + (size_t)mp * Ee * Hh; };
    auto Y_     = [&](int mp) { return YB + (size_t)mp * Nn * Dd; };
    auto EW2_   = [&](int mp) { return EW2B + (size_t)mp * 2 * Ee * Dd; };
    auto eB_    = [&](int mp) { return eBB + (size_t)mp * Ee * Dd; };
    auto nag_   = [&](int mp) { return nagB + (size_t)mp * Hh * Nn * Dd; };
    auto NP_    = [&](int mp) { return NPB + (size_t)mp * Nn * Dd; };
    auto xb_    = [&](int mp) { return xB + (size_t)mp * Nn * Dd; };

    // full per-mp tail chain (eB/nag/NP/xb per-mp => chains are independent)
    auto chain = [&](int mp, cudaStream_t st) {
        const int* ena_mp = ena + (size_t)mp * Ee * 2;
        const int* n2e_mp = n2e + (size_t)mp * Nn * Kk;
        float* outmp = out + (size_t)mp * Nn * DEPTHc * Dd;
        size_t pl1 = (size_t)(mp * DEPTHc + 1);
        float* EW    = EW2_(mp);
        float* EWnb0 = EW2_(mp) + (size_t)Ee * Dd;

        edge_comb_q<<<Ee / 4, blk, 0, st>>>(ena_mp, pn_(mp), be_(mp), EW, Y_(mp),
                                            a_edge + pl1 * Hh * Dd, eB_(mp), be_(mp));
        nagp_kernel<<<Nn / 8, blk, 0, st>>>(n2e_mp, ps_(mp), qe_(mp), EWnb0, NP_(mp));
        cudaMemsetAsync(ps_(mp), 0, (size_t)Nn * Hh * sizeof(float), st);
        gemm_mma<64, 128, 3><<<gN, blk, SM_64_128, st>>>(feats, WfYS_(mp) + Dd * Dd, nullptr, Dd, Dd, 0, 0, 0,
                                                         a_s + pl1 * Hh * Dd, NP_(mp), outmp, xb_(mp), ps_(mp));
        nag_kernel<<<Nn / 8, blk, 0, st>>>(n2e_mp, ps_(mp), be_(mp), eB_(mp), nag_(mp));
        gemm_mma<64, 64, 0><<<gH, blk, SM_64_64, st>>>(nag_(mp), Bt5_(mp) + (size_t)4 * Dd * Dd, NP_(mp), Dd, Dd,
                                                       (size_t)Nn * Dd, (size_t)PHp * Dd, (size_t)PHp,
                                                       nullptr, nullptr, nullptr, nullptr, nullptr);
        gemm_mma<64, 128, 2><<<gN, blk, SM_64_128, st>>>(xb_(mp), Bt5_(mp) + (size_t)3 * Dd * Dd, nullptr, Dd, Dd, 0, 0, 0,
                                                         nullptr, NP_(mp), outmp, nullptr, nullptr);
    };

    // ---- s2: input-only folds first (no deps) ----
    for (int mp = 0; mp < NMPc; mp++) {
        size_t pl0 = (size_t)(mp * DEPTHc + 0);
        foldA2p<<<Hh, blk, 0, s2>>>(Wep + (size_t)mp * EDd * Dd,
                                    a_e + pl0 * Hh * Dd, a_edge + pl0 * Hh * Dd, avf_(mp));
    }

    // ---- ms: WpT -> mp0 weight folds -> mp0 front GEMMs ----
    pack2d2<<<dim3(256, 1, 2), blk, 0, ms>>>(Wp0, Wp1, WpT);
    cudaEventRecord(g_ss.evWpT, ms);

    pack_hdp5<<<dim3(256, 1, 5), blk, 0, ms>>>(W_e    + 0 * Hh * Dd * PHp,
                                               W_self + 0 * Hh * Dd * PHp,
                                               W_nb   + 0 * Hh * Dd * PHp,
                                               W_self + 1 * Hh * Dd * PHp,
                                               W_nb   + 1 * Hh * Dd * PHp, Bt5_(0));
    foldW256_2<<<dim3(256, 1, 2), blk, 0, ms>>>(WpT, Bt5_(0), WfYS_(0));
    foldW2<<<dim3(256, 1, 2), blk, 0, ms>>>(Wep, Bt5_(0), Wc_(0));

    gemm_mma<64, 128, 0><<<gN, blk, SM_64_128, ms>>>(feats, WfYS_(0), Y_(0), Dd, Dd, 0, 0, 0,
                                                     nullptr, nullptr, nullptr, nullptr, nullptr);
    gemm_mma<64, 128, 0><<<gE2, blk, SM_64_128, ms>>>(edge_emb, Wc_(0), EW2_(0), EDd, Dd,
                                                      0, (size_t)Dd * EDd, (size_t)Ee * Dd,
                                                      nullptr, nullptr, nullptr, nullptr, nullptr);
    cudaEventRecord(g_ss.evMS0, ms);

    // ---- s2: attention-vector folds + rowdots + mp1 weight folds + mp1 front GEMMs + mp1 chain ----
    cudaStreamWaitEvent(s2, g_ss.evWpT, 0);
    {
        size_t pl0m0 = 0, pl0m1 = (size_t)DEPTHc;
        foldA256_2<<<dim3(Hh, 1, 2), blk, 0, s2>>>(WpT, a_n + pl0m0 * Hh * Dd, a_s + pl0m0 * Hh * Dd, av256_(0));
        rowdot2<<<Nn / 8, blk, 0, s2>>>(feats, av256_(0), av256_(0) + Hh * Dd, pn_(0), ps_(0));
        rowdot2_64<<<Ee / 8, blk, 0, s2>>>(edge_emb, avf_(0), be_(0), qe_(0));
        cudaEventRecord(g_ss.evRD0, s2);

        foldA256_2<<<dim3(Hh, 1, 2), blk, 0, s2>>>(WpT, a_n + pl0m1 * Hh * Dd, a_s + pl0m1 * Hh * Dd, av256_(1));
        rowdot2<<<Nn / 8, blk, 0, s2>>>(feats, av256_(1), av256_(1) + Hh * Dd, pn_(1), ps_(1));
        rowdot2_64<<<Ee / 8, blk, 0, s2>>>(edge_emb + (size_t)Ee * EDd, avf_(1), be_(1), qe_(1));

        size_t pl0 = (size_t)DEPTHc, pl1 = (size_t)DEPTHc + 1;
        pack_hdp5<<<dim3(256, 1, 5), blk, 0, s2>>>(W_e    + pl0 * Hh * Dd * PHp,
                                                   W_self + pl0 * Hh * Dd * PHp,
                                                   W_nb   + pl0 * Hh * Dd * PHp,
                                                   W_self + pl1 * Hh * Dd * PHp,
                                                   W_nb   + pl1 * Hh * Dd * PHp, Bt5_(1));
        foldW256_2<<<dim3(256, 1, 2), blk, 0, s2>>>(WpT, Bt5_(1), WfYS_(1));
        foldW2<<<dim3(256, 1, 2), blk, 0, s2>>>(Wep + (size_t)EDd * Dd, Bt5_(1), Wc_(1));

        cudaStreamWaitEvent(s2, g_ss.evMS0, 0);
        gemm_mma<64, 128, 0><<<gN, blk, SM_64_128, s2>>>(feats, WfYS_(1), Y_(1), Dd, Dd, 0, 0, 0,
                                                         nullptr, nullptr, nullptr, nullptr, nullptr);
        gemm_mma<64, 128, 0><<<gE2, blk, SM_64_128, s2>>>(edge_emb + (size_t)Ee * EDd, Wc_(1), EW2_(1), EDd, Dd,
                                                          0, (size_t)Dd * EDd, (size_t)Ee * Dd,
                                                          nullptr, nullptr, nullptr, nullptr, nullptr);
        // entire mp1 tail on s2 (co-runs with mp0 tail on ms)
        chain(1, s2);
        cudaEventRecord(g_ss.evEnd, s2);
    }

    // ---- ms: mp0 tail ----
    cudaStreamWaitEvent(ms, g_ss.evRD0, 0);
    chain(0, ms);

    // join s2 back into ms before capture ends
    cudaStreamWaitEvent(ms, g_ss.evEnd, 0);
}

// round 17
// speedup vs baseline: 1.1417x; 1.1030x over previous
#include <cuda_runtime.h>
#include <cuda_bf16.h>
#include <math.h>
#include <stdint.h>

#define Nn 65536
#define Ee 262144
#define Kk 8
#define NMPc 2
#define DEPTHc 2
#define Hh 4
#define Dd 256
#define PHp 64
#define EDd 64

// ---------------- scratch (device globals; no allocation allowed) ----------------
__device__ __align__(16) float g_x    [(size_t)2 * Nn * Dd];        // per-mp
__device__ __align__(16) float g_Y    [(size_t)2 * Nn * Dd];        // per-mp
__device__ __align__(16) float g_NP   [(size_t)2 * Nn * Dd];        // per-mp
__device__ __align__(16) float g_nagE [(size_t)2 * Nn * Dd];        // per-mp [N, H*64]
__device__ __align__(16) float g_EW   [(size_t)2 * Ee * Dd];        // per-mp (EW only)
__device__ __align__(16) float g_eB   [(size_t)2 * Ee * Dd];        // per-mp
__device__ __align__(16) float g_nag  [(size_t)2 * Hh * Nn * Dd];   // per-mp (L1)
// per-mp doubled small state
__device__ __align__(16) float g_pn   [(size_t)2 * Nn * Hh];
__device__ __align__(16) float g_be   [(size_t)2 * Ee * Hh];   // be (L0), then qe1 (L1)
__device__ __align__(16) float g_ps   [(size_t)2 * Nn * Hh];
__device__ __align__(16) float g_qe   [(size_t)2 * Ee * Hh];   // qe0
__device__ __align__(16) float g_WpT  [2 * Dd * Dd];           // [0]=Wp0^T, [1]=Wp1^T
__device__ __align__(16) float g_Bt5  [2 * 5 * Dd * Dd];
__device__ __align__(16) float g_WfYS [2 * 2 * Dd * Dd];       // per-mp [0]=WfY, [1]=WfS
__device__ __align__(16) float g_Wc   [2 * 2 * Dd * EDd];      // per-mp [0]=Wc_e, [1]=Wc_nb
__device__ __align__(16) float g_avf  [2 * 2 * Hh * EDd];
__device__ __align__(16) float g_av256[2 * 2 * Hh * Dd];

// ---------------- side stream + events (static init: before harness mem checkpoints) ----------------
namespace {
struct SideStream {
    cudaStream_t s;
    cudaEvent_t evWpT, evRD0, evMS0, evEnd;
    SideStream() {
        cudaStreamCreateWithFlags(&s, cudaStreamNonBlocking);
        cudaEventCreateWithFlags(&evWpT, cudaEventDisableTiming);
        cudaEventCreateWithFlags(&evRD0, cudaEventDisableTiming);
        cudaEventCreateWithFlags(&evMS0, cudaEventDisableTiming);
        cudaEventCreateWithFlags(&evEnd, cudaEventDisableTiming);
    }
};
SideStream g_ss;
}

// ---------------- HMMA helper ----------------
__device__ __forceinline__ void mma16816(float* c, const uint32_t* a, uint32_t b0, uint32_t b1) {
    asm volatile("mma.sync.aligned.m16n8k16.row.col.f32.bf16.bf16.f32 "
                 "{%0,%1,%2,%3}, {%4,%5,%6,%7}, {%8,%9}, {%0,%1,%2,%3};"
                 : "+f"(c[0]), "+f"(c[1]), "+f"(c[2]), "+f"(c[3])
                 : "r"(a[0]), "r"(a[1]), "r"(a[2]), "r"(a[3]), "r"(b0), "r"(b1));
}

__device__ __forceinline__ void split4(float4 v, uint2& hi, uint2& lo) {
    __nv_bfloat16 h0 = __float2bfloat16(v.x), h1 = __float2bfloat16(v.y);
    __nv_bfloat16 h2 = __float2bfloat16(v.z), h3 = __float2bfloat16(v.w);
    __nv_bfloat16 l0 = __float2bfloat16(v.x - __bfloat162float(h0));
    __nv_bfloat16 l1 = __float2bfloat16(v.y - __bfloat162float(h1));
    __nv_bfloat16 l2 = __float2bfloat16(v.z - __bfloat162float(h2));
    __nv_bfloat16 l3 = __float2bfloat16(v.w - __bfloat162float(h3));
    union { __nv_bfloat162 b[2]; uint2 u; } ph, pl;
    ph.b[0] = __nv_bfloat162(h0, h1); ph.b[1] = __nv_bfloat162(h2, h3);
    pl.b[0] = __nv_bfloat162(l0, l1); pl.b[1] = __nv_bfloat162(l2, l3);
    hi = ph.u; lo = pl.u;
}

__device__ __forceinline__ float elu1(float x) { return x > 0.f ? x : expm1f(x); }

// ---------------- pipelined bf16-split HMMA GEMM (BM x BN tile, 2 CTAs/SM at BM=64) ----------------
// lda decoupled from K (for strided A slices).
template <int BM, int BN, int EPI>
__global__ __launch_bounds__(256, 2) void gemm_mma(const float* __restrict__ A,
                                                   const float* __restrict__ Bt,
                                                   float* __restrict__ C,
                                                   int K, int lda, int ldc,
                                                   size_t sAz, size_t sBz, size_t sCz,
                                                   const float* __restrict__ a1v,
                                                   const float* __restrict__ NPp,
                                                   float* __restrict__ outp,
                                                   float* __restrict__ xoutp,
                                                   float* __restrict__ psout)
{
    constexpr int NWN = (BM == 64) ? 4 : 2;
    constexpr int NT  = BN / (8 * NWN);
    constexpr int NA  = BM / 32;
    constexpr int NB  = BN / 32;
    constexpr int ASZ = BM * 40;
    constexpr int BSZ = BN * 40;
    constexpr int BUFE = 2 * ASZ + 2 * BSZ;
    extern __shared__ uint16_t sm[];

    A  += blockIdx.z * sAz;
    Bt += blockIdx.z * sBz;
    C  += blockIdx.z * sCz;

    int t = threadIdx.x, wid = t >> 5, lane = t & 31;
    int g = lane >> 2, tg = lane & 3;
    int wm = (wid / NWN) * 32;
    int wn = (wid % NWN) * (BN / NWN);
    size_t m0 = (size_t)blockIdx.x * BM;
    size_t n0 = (size_t)blockIdx.y * BN;
    const float* Abase = A + m0 * lda;
    const float* Bbase = Bt + n0 * K;

    float acc[2][NT][4];
    #pragma unroll
    for (int mt = 0; mt < 2; mt++)
        #pragma unroll
        for (int nt = 0; nt < NT; nt++)
            #pragma unroll
            for (int j = 0; j < 4; j++) acc[mt][nt][j] = 0.f;

    float4 pa[NA], pb[NB];
    auto ldAB = [&](int kb) {
        #pragma unroll
        for (int i = 0; i < NA; i++) {
            int id = t + 256 * i, r = id >> 3, c4 = id & 7;
            pa[i] = *(const float4*)(Abase + (size_t)r * lda + kb * 32 + c4 * 4);
        }
        #pragma unroll
        for (int i = 0; i < NB; i++) {
            int id = t + 256 * i, r = id >> 3, c4 = id & 7;
            pb[i] = *(const float4*)(Bbase + (size_t)r * K + kb * 32 + c4 * 4);
        }
    };
    auto stAB = [&](int buf) {
        uint16_t* bAh = sm + buf * BUFE;
        uint16_t* bAl = bAh + ASZ;
        uint16_t* bBh = bAl + ASZ;
        uint16_t* bBl = bBh + BSZ;
        #pragma unroll
        for (int i = 0; i < NA; i++) {
            int id = t + 256 * i, r = id >> 3, c4 = id & 7;
            uint2 hi, lo; split4(pa[i], hi, lo);
            *(uint2*)&bAh[r * 40 + c4 * 4] = hi;
            *(uint2*)&bAl[r * 40 + c4 * 4] = lo;
        }
        #pragma unroll
        for (int i = 0; i < NB; i++) {
            int id = t + 256 * i, r = id >> 3, c4 = id & 7;
            uint2 hi, lo; split4(pb[i], hi, lo);
            *(uint2*)&bBh[r * 40 + c4 * 4] = hi;
            *(uint2*)&bBl[r * 40 + c4 * 4] = lo;
        }
    };
    auto domma = [&](int buf) {
        const uint16_t* bAh = sm + buf * BUFE;
        const uint16_t* bAl = bAh + ASZ;
        const uint16_t* bBh = bAl + ASZ;
        const uint16_t* bBl = bBh + BSZ;
        #pragma unroll
        for (int ks = 0; ks < 2; ks++) {
            int kc = ks * 16 + tg * 2;
            uint32_t ah[2][4], al_[2][4];
            #pragma unroll
            for (int mt = 0; mt < 2; mt++) {
                int row = wm + mt * 16 + g;
                ah[mt][0]  = *(const uint32_t*)&bAh[row * 40 + kc];
                ah[mt][1]  = *(const uint32_t*)&bAh[(row + 8) * 40 + kc];
                ah[mt][2]  = *(const uint32_t*)&bAh[row * 40 + kc + 8];
                ah[mt][3]  = *(const uint32_t*)&bAh[(row + 8) * 40 + kc + 8];
                al_[mt][0] = *(const uint32_t*)&bAl[row * 40 + kc];
                al_[mt][1] = *(const uint32_t*)&bAl[(row + 8) * 40 + kc];
                al_[mt][2] = *(const uint32_t*)&bAl[row * 40 + kc + 8];
                al_[mt][3] = *(const uint32_t*)&bAl[(row + 8) * 40 + kc + 8];
            }
            #pragma unroll
            for (int nt = 0; nt < NT; nt++) {
                int col = wn + nt * 8 + g;
                uint32_t bh0 = *(const uint32_t*)&bBh[col * 40 + kc];
                uint32_t bh1 = *(const uint32_t*)&bBh[col * 40 + kc + 8];
                uint32_t bl0 = *(const uint32_t*)&bBl[col * 40 + kc];
                uint32_t bl1 = *(const uint32_t*)&bBl[col * 40 + kc + 8];
                #pragma unroll
                for (int mt = 0; mt < 2; mt++) {
                    mma16816(acc[mt][nt], ah[mt],  bh0, bh1);
                    mma16816(acc[mt][nt], al_[mt], bh0, bh1);
                    mma16816(acc[mt][nt], ah[mt],  bl0, bl1);
                }
            }
        }
    };

    int nkb = K >> 5;
    ldAB(0);
    stAB(0);
    __syncthreads();
    for (int kb = 0; kb < nkb; kb++) {
        int cur = kb & 1;
        if (kb + 1 < nkb) ldAB(kb + 1);
        domma(cur);
        if (kb + 1 < nkb) stAB(cur ^ 1);
        __syncthreads();
    }

    if (EPI == 0) {
        #pragma unroll
        for (int mt = 0; mt < 2; mt++) {
            size_t row = m0 + wm + mt * 16 + g;
            #pragma unroll
            for (int nt = 0; nt < NT; nt++) {
                size_t col = n0 + wn + nt * 8 + tg * 2;
                *(float2*)(C + row * ldc + col)       = make_float2(acc[mt][nt][0], acc[mt][nt][1]);
                *(float2*)(C + (row + 8) * ldc + col) = make_float2(acc[mt][nt][2], acc[mt][nt][3]);
            }
        }
    } else {
        constexpr int Lofs = (EPI == 3) ? 0 : Dd;
        float* sa1 = (float*)sm;
        if (EPI == 3) {
            for (int i = t; i < 4 * BN; i += 256) {
                int h = i / BN, c = i % BN;
                sa1[i] = a1v[(size_t)h * Dd + n0 + c];
            }
            __syncthreads();
        }
        float qp[4][Hh];
        if (EPI == 3) {
            #pragma unroll
            for (int j = 0; j < 4; j++)
                #pragma unroll
                for (int h = 0; h < Hh; h++) qp[j][h] = 0.f;
        }
        #pragma unroll
        for (int mt = 0; mt < 2; mt++) {
            #pragma unroll
            for (int rp = 0; rp < 2; rp++) {
                size_t grow = m0 + wm + mt * 16 + g + rp * 8;
                #pragma unroll
                for (int nt = 0; nt < NT; nt++) {
                    int cloc = wn + nt * 8 + tg * 2;
                    size_t gc = n0 + cloc;
                    float2 np = *(const float2*)(NPp + grow * Dd + gc);
                    float r0 = elu1(acc[mt][nt][rp * 2 + 0] + np.x);
                    float r1 = elu1(acc[mt][nt][rp * 2 + 1] + np.y);
                    *(float2*)(outp + grow * (DEPTHc * Dd) + Lofs + gc) = make_float2(r0, r1);
                    if (EPI == 3) {
                        *(float2*)(xoutp + grow * Dd + gc) = make_float2(r0, r1);
                        #pragma unroll
                        for (int h = 0; h < Hh; h++)
                            qp[mt * 2 + rp][h] += r0 * sa1[h * BN + cloc] + r1 * sa1[h * BN + cloc + 1];
                    }
                }
            }
        }
        if (EPI == 3) {
            #pragma unroll
            for (int j = 0; j < 4; j++)
                #pragma unroll
                for (int h = 0; h < Hh; h++) {
                    qp[j][h] += __shfl_xor_sync(0xffffffffu, qp[j][h], 1);
                    qp[j][h] += __shfl_xor_sync(0xffffffffu, qp[j][h], 2);
                }
            if (tg == 0) {
                #pragma unroll
                for (int mt = 0; mt < 2; mt++)
                    #pragma unroll
                    for (int rp = 0; rp < 2; rp++) {
                        size_t grow = m0 + wm + mt * 16 + g + rp * 8;
                        #pragma unroll
                        for (int h = 0; h < Hh; h++)
                            atomicAdd(&psout[grow * Hh + h], qp[mt * 2 + rp][h]);
                    }
            }
        }
    }
}

// ---------------- packing / folding ----------------
__global__ void pack2d2(const float* __restrict__ s0, const float* __restrict__ s1,
                        float* __restrict__ dst) {
    int z = blockIdx.z;
    const float* src = z ? s1 : s0;
    int id = blockIdx.x * 256 + threadIdx.x;
    int c = id % Dd, k = id / Dd;
    dst[(size_t)z * Dd * Dd + (size_t)c * Dd + k] = src[id];
}

__global__ void pack_hdp5(const float* __restrict__ s0, const float* __restrict__ s1,
                          const float* __restrict__ s2, const float* __restrict__ s3,
                          const float* __restrict__ s4, float* __restrict__ dst) {
    int z = blockIdx.z;
    const float* src = (z == 0) ? s0 : (z == 1) ? s1 : (z == 2) ? s2 : (z == 3) ? s3 : s4;
    int id = blockIdx.x * 256 + threadIdx.x;
    int p = id % PHp, d = (id / PHp) % Dd, h = id / (PHp * Dd);
    dst[(size_t)z * Dd * Dd + (size_t)(h * PHp + p) * Dd + d] = src[id];
}

__global__ __launch_bounds__(256) void foldW2(const float* __restrict__ Wep,
                                              const float* __restrict__ Bt5,
                                              float* __restrict__ Wc)
{
    __shared__ float sb[256];
    __shared__ float sred[4][64];
    int z = blockIdx.z;
    const float* BtW = Bt5 + (size_t)(z == 0 ? 0 : 2) * Dd * Dd;
    float* dst = Wc + (size_t)z * Dd * EDd;
    int c = blockIdx.x, t = threadIdx.x;
    sb[t] = BtW[(size_t)c * 256 + t];
    __syncthreads();
    int j = t & 63, q = t >> 6;
    const float* wr  = Wep + (size_t)j * 256 + q * 64;
    const float* sbp = sb + q * 64;
    float acc = 0.f;
    #pragma unroll 16
    for (int d = 0; d < 64; d++) acc += wr[d] * sbp[d];
    sred[q][j] = acc;
    __syncthreads();
    if (t < 64) dst[(size_t)c * 64 + t] = sred[0][t] + sred[1][t] + sred[2][t] + sred[3][t];
}

__global__ __launch_bounds__(256) void foldW256_2(const float* __restrict__ WpT,
                                                  const float* __restrict__ Bt5,
                                                  float* __restrict__ Wf)
{
    __shared__ float sb[256];
    int z = blockIdx.z;
    const float* WpTz = WpT + (size_t)(z == 0 ? 1 : 0) * Dd * Dd;
    const float* BtW = Bt5 + (size_t)z * Dd * Dd;
    float* dst = Wf + (size_t)z * Dd * Dd;
    int c = blockIdx.x, d = threadIdx.x;
    sb[d] = BtW[(size_t)c * 256 + d];
    __syncthreads();
    float acc = 0.f;
    #pragma unroll 4
    for (int dp = 0; dp < 256; dp++) acc += WpTz[(size_t)dp * 256 + d] * sb[dp];
    dst[(size_t)c * 256 + d] = acc;
}

__global__ __launch_bounds__(256) void foldA256_2(const float* __restrict__ WpT,
                                                  const float* __restrict__ an,
                                                  const float* __restrict__ as,
                                                  float* __restrict__ outp)
{
    __shared__ float sa[256];
    int z = blockIdx.z;
    const float* WpTz = WpT + (size_t)(z == 0 ? 1 : 0) * Dd * Dd;
    const float* a = (z == 0) ? an : as;
    int h = blockIdx.x, d = threadIdx.x;
    sa[d] = a[(size_t)h * 256 + d];
    __syncthreads();
    float acc = 0.f;
    #pragma unroll 4
    for (int dp = 0; dp < 256; dp++) acc += WpTz[(size_t)dp * 256 + d] * sa[dp];
    outp[(size_t)z * Hh * Dd + (size_t)h * 256 + d] = acc;
}

__global__ __launch_bounds__(256) void foldA2p(const float* __restrict__ Wep,
                                               const float* __restrict__ a1,
                                               const float* __restrict__ a2,
                                               float* __restrict__ outp)
{
    __shared__ float s1[256], s2[256];
    __shared__ float r1[4][64], r2[4][64];
    int h = blockIdx.x, t = threadIdx.x;
    s1[t] = a1[(size_t)h * 256 + t];
    s2[t] = a2[(size_t)h * 256 + t];
    __syncthreads();
    int j = t & 63, q = t >> 6;
    const float* wr = Wep + (size_t)j * 256 + q * 64;
    float A = 0.f, B = 0.f;
    #pragma unroll 16
    for (int d = 0; d < 64; d++) { float w = wr[d]; A += w * s1[q * 64 + d]; B += w * s2[q * 64 + d]; }
    r1[q][j] = A; r2[q][j] = B;
    __syncthreads();
    if (t < 64) outp[h * 64 + t] = r1[0][t] + r1[1][t] + r1[2][t] + r1[3][t];
    else if (t < 128) {
        int j2 = t - 64;
        outp[Hh * 64 + h * 64 + j2] = r2[0][j2] + r2[1][j2] + r2[2][j2] + r2[3][j2];
    }
}

// ---------------- dual row-dot (D=256) ----------------
__global__ __launch_bounds__(256) void rowdot2(const float* __restrict__ X,
                                               const float* __restrict__ avec1,
                                               const float* __restrict__ avec2,
                                               float* __restrict__ P1,
                                               float* __restrict__ P2)
{
    __shared__ float sa[2 * Hh * Dd];
    int t = threadIdx.x;
    for (int i = t; i < Hh * Dd; i += 256) { sa[i] = avec1[i]; sa[Hh * Dd + i] = avec2[i]; }
    __syncthreads();
    int row = blockIdx.x * 8 + (t >> 5);
    int lane = t & 31;
    const float* xr = X + (size_t)row * Dd;
    float a1[Hh] = {}, a2[Hh] = {};
    #pragma unroll
    for (int j = 0; j < 8; j++) {
        float xv = xr[lane + 32 * j];
        #pragma unroll
        for (int h = 0; h < Hh; h++) {
            a1[h] += sa[h * Dd + lane + 32 * j] * xv;
            a2[h] += sa[Hh * Dd + h * Dd + lane + 32 * j] * xv;
        }
    }
    #pragma unroll
    for (int h = 0; h < Hh; h++) {
        #pragma unroll
        for (int o = 16; o > 0; o >>= 1) {
            a1[h] += __shfl_down_sync(0xffffffffu, a1[h], o);
            a2[h] += __shfl_down_sync(0xffffffffu, a2[h], o);
        }
    }
    if (lane == 0) {
        #pragma unroll
        for (int h = 0; h < Hh; h++) {
            P1[(size_t)row * Hh + h] = a1[h];
            P2[(size_t)row * Hh + h] = a2[h];
        }
    }
}

// ---------------- dual row-dot over D=64 rows (edge_emb) ----------------
__global__ __launch_bounds__(256) void rowdot2_64(const float* __restrict__ X,
                                                  const float* __restrict__ avf,
                                                  float* __restrict__ P1,
                                                  float* __restrict__ P2)
{
    __shared__ float sa[2 * Hh * 64];
    int t = threadIdx.x;
    for (int i = t; i < 2 * Hh * 64; i += 256) sa[i] = avf[i];
    __syncthreads();
    int row = blockIdx.x * 8 + (t >> 5);
    int lane = t & 31;
    const float* xr = X + (size_t)row * 64;
    float x0 = xr[lane], x1 = xr[lane + 32];
    float a1[Hh], a2[Hh];
    #pragma unroll
    for (int h = 0; h < Hh; h++) {
        a1[h] = sa[h * 64 + lane] * x0 + sa[h * 64 + lane + 32] * x1;
        a2[h] = sa[256 + h * 64 + lane] * x0 + sa[256 + h * 64 + lane + 32] * x1;
    }
    #pragma unroll
    for (int h = 0; h < Hh; h++) {
        #pragma unroll
        for (int o = 16; o > 0; o >>= 1) {
            a1[h] += __shfl_down_sync(0xffffffffu, a1[h], o);
            a2[h] += __shfl_down_sync(0xffffffffu, a2[h], o);
        }
    }
    if (lane == 0) {
        #pragma unroll
        for (int h = 0; h < Hh; h++) {
            P1[(size_t)row * Hh + h] = a1[h];
            P2[(size_t)row * Hh + h] = a2[h];
        }
    }
}

// ---------------- edge combine + fused qe1 ----------------
__global__ __launch_bounds__(256) void edge_comb_q(const int* __restrict__ ena,
                                                   const float* __restrict__ pn,
                                                   const float* __restrict__ be,
                                                   const float* __restrict__ EW,
                                                   const float* __restrict__ Y,
                                                   const float* __restrict__ a1v,
                                                   float* __restrict__ eout,
                                                   float* __restrict__ qe1)
{
    __shared__ float sa1[Hh * Dd];
    __shared__ float sred[4][2][Hh];
    int t = threadIdx.x;
    for (int i = t; i < Hh * Dd; i += 256) sa1[i] = a1v[i];
    __syncthreads();

    int e0 = blockIdx.x * 4;
    int el = t >> 6, c4 = t & 63, h = c4 >> 4;
    int e = e0 + el;
    int u = ena[2 * e], v = ena[2 * e + 1];
    float b = be[(size_t)e * Hh + h];
    float s0 = pn[(size_t)u * Hh + h] + b;
    float s1 = pn[(size_t)v * Hh + h] + b;
    s0 = s0 > 0.f ? s0 : 0.2f * s0;
    s1 = s1 > 0.f ? s1 : 0.2f * s1;
    float m = fmaxf(s0, s1);
    float x0 = __expf(s0 - m), x1 = __expf(s1 - m);
    float inv = 1.f / (x0 + x1);
    float al0 = x0 * inv, al1 = x1 * inv;
    float4 ew = *(const float4*)(EW + (size_t)e * Dd + c4 * 4);
    float4 yu = *(const float4*)(Y + (size_t)u * Dd + c4 * 4);
    float4 yv = *(const float4*)(Y + (size_t)v * Dd + c4 * 4);
    float4 r;
    r.x = elu1(ew.x + al0 * yu.x + al1 * yv.x);
    r.y = elu1(ew.y + al0 * yu.y + al1 * yv.y);
    r.z = elu1(ew.z + al0 * yu.z + al1 * yv.z);
    r.w = elu1(ew.w + al0 * yu.w + al1 * yv.w);
    *(float4*)(eout + (size_t)e * Dd + c4 * 4) = r;

    float p[Hh];
    #pragma unroll
    for (int hh = 0; hh < Hh; hh++) {
        const float* av = sa1 + hh * Dd + c4 * 4;
        p[hh] = r.x * av[0] + r.y * av[1] + r.z * av[2] + r.w * av[3];
    }
    #pragma unroll
    for (int hh = 0; hh < Hh; hh++) {
        #pragma unroll
        for (int o = 16; o > 0; o >>= 1) p[hh] += __shfl_down_sync(0xffffffffu, p[hh], o);
    }
    int wl = t & 31, whalf = (t >> 5) & 1;
    if (wl == 0) {
        #pragma unroll
        for (int hh = 0; hh < Hh; hh++) sred[el][whalf][hh] = p[hh];
    }
    __syncthreads();
    if (t < 16) {
        int ee = t >> 2, hh = t & 3;
        qe1[(size_t)(e0 + ee) * Hh + hh] = sred[ee][0][hh] + sred[ee][1][hh];
    }
}

// ---------------- L0 node agg in 64-dim embedding space: nagE[n, h*64+j] ----------------
__global__ __launch_bounds__(256) void nag64_kernel(const int* __restrict__ n2e,
                                                    const float* __restrict__ ps,
                                                    const float* __restrict__ qe,
                                                    const float* __restrict__ emb,
                                                    float* __restrict__ nagE)
{
    int t = threadIdx.x, w = t >> 5, lane = t & 31;
    int n = blockIdx.x * 8 + w;
    int idx[Kk];
    #pragma unroll
    for (int k = 0; k < Kk; k++) idx[k] = n2e[(size_t)n * Kk + k];
    float al[Hh][Kk];
    #pragma unroll
    for (int h = 0; h < Hh; h++) {
        float bs = ps[(size_t)n * Hh + h];
        float s[Kk]; float m = -1e30f;
        #pragma unroll
        for (int k = 0; k < Kk; k++) {
            float sv = bs + qe[(size_t)idx[k] * Hh + h];
            sv = sv > 0.f ? sv : 0.2f * sv;
            s[k] = sv; m = fmaxf(m, sv);
        }
        float sum = 0.f;
        #pragma unroll
        for (int k = 0; k < Kk; k++) { s[k] = __expf(s[k] - m); sum += s[k]; }
        float inv = 1.f / sum;
        #pragma unroll
        for (int k = 0; k < Kk; k++) al[h][k] = s[k] * inv;
    }
    float2 acc[Hh];
    #pragma unroll
    for (int h = 0; h < Hh; h++) acc[h] = make_float2(0.f, 0.f);
    #pragma unroll
    for (int k = 0; k < Kk; k++) {
        float2 e = *(const float2*)(emb + (size_t)idx[k] * EDd + lane * 2);
        #pragma unroll
        for (int h = 0; h < Hh; h++) {
            acc[h].x += al[h][k] * e.x;
            acc[h].y += al[h][k] * e.y;
        }
    }
    #pragma unroll
    for (int h = 0; h < Hh; h++)
        *(float2*)(nagE + (size_t)n * Dd + h * EDd + lane * 2) = acc[h];
}

// ---------------- L1 node aggregation (full, 256-dim eB) ----------------
__global__ __launch_bounds__(256) void nag_kernel(const int* __restrict__ n2e,
                                                  const float* __restrict__ ps,
                                                  const float* __restrict__ qe,
                                                  const float* __restrict__ edges,
                                                  float* __restrict__ nag)
{
    int t = threadIdx.x, w = t >> 5, lane = t & 31;
    int n = blockIdx.x * 8 + w;
    int idx[Kk];
    #pragma unroll
    for (int k = 0; k < Kk; k++) idx[k] = n2e[(size_t)n * Kk + k];
    float al[Hh][Kk];
    #pragma unroll
    for (int h = 0; h < Hh; h++) {
        float bs = ps[(size_t)n * Hh + h];
        float s[Kk]; float m = -1e30f;
        #pragma unroll
        for (int k = 0; k < Kk; k++) {
            float sv = bs + qe[(size_t)idx[k] * Hh + h];
            sv = sv > 0.f ? sv : 0.2f * sv;
            s[k] = sv; m = fmaxf(m, sv);
        }
        float sum = 0.f;
        #pragma unroll
        for (int k = 0; k < Kk; k++) { s[k] = __expf(s[k] - m); sum += s[k]; }
        float inv = 1.f / sum;
        #pragma unroll
        for (int k = 0; k < Kk; k++) al[h][k] = s[k] * inv;
    }
    float4 a0[Hh] = {}, a1[Hh] = {};
    #pragma unroll
    for (int k = 0; k < Kk; k++) {
        const float4* er = (const float4*)(edges + (size_t)idx[k] * Dd);
        float4 ea = er[lane], eb = er[32 + lane];
        #pragma unroll
        for (int h = 0; h < Hh; h++) {
            float a = al[h][k];
            a0[h].x += a * ea.x; a0[h].y += a * ea.y; a0[h].z += a * ea.z; a0[h].w += a * ea.w;
            a1[h].x += a * eb.x; a1[h].y += a * eb.y; a1[h].z += a * eb.z; a1[h].w += a * eb.w;
        }
    }
    #pragma unroll
    for (int h = 0; h < Hh; h++) {
        float* dst = nag + ((size_t)h * Nn + n) * Dd;
        *(float4*)(dst + lane * 4) = a0[h];
        *(float4*)(dst + 128 + lane * 4) = a1[h];
    }
}

// ---------------- launcher ----------------
extern "C" void kernel_launch(void* const* d_in, const int* in_sizes, int n_in,
                              void* d_out, int out_size)
{
    (void)in_sizes; (void)n_in; (void)out_size;
    const float* feats    = (const float*)d_in[0];
    const float* edge_emb = (const float*)d_in[1];
    const int*   ena      = (const int*)d_in[2];
    const int*   n2e      = (const int*)d_in[3];
    const float* Wp0      = (const float*)d_in[4];
    const float* Wp1      = (const float*)d_in[5];
    const float* Wep      = (const float*)d_in[6];
    const float* a_e      = (const float*)d_in[7];
    const float* a_n      = (const float*)d_in[8];
    const float* W_e      = (const float*)d_in[9];
    const float* a_s      = (const float*)d_in[10];
    const float* a_edge   = (const float*)d_in[11];
    const float* W_self   = (const float*)d_in[12];
    const float* W_nb     = (const float*)d_in[13];
    float* out = (float*)d_out;

    float *xB, *YB, *NPB, *nagEB, *EWB, *eBB, *nagB, *pnB, *beB, *psB, *qeB;
    float *WpT, *Bt5B, *WfYSB, *WcB, *avfB, *av256B;
    cudaGetSymbolAddress((void**)&xB,     g_x);
    cudaGetSymbolAddress((void**)&YB,     g_Y);
    cudaGetSymbolAddress((void**)&NPB,    g_NP);
    cudaGetSymbolAddress((void**)&nagEB,  g_nagE);
    cudaGetSymbolAddress((void**)&EWB,    g_EW);
    cudaGetSymbolAddress((void**)&eBB,    g_eB);
    cudaGetSymbolAddress((void**)&nagB,   g_nag);
    cudaGetSymbolAddress((void**)&pnB,    g_pn);
    cudaGetSymbolAddress((void**)&beB,    g_be);
    cudaGetSymbolAddress((void**)&psB,    g_ps);
    cudaGetSymbolAddress((void**)&qeB,    g_qe);
    cudaGetSymbolAddress((void**)&WpT,    g_WpT);
    cudaGetSymbolAddress((void**)&Bt5B,   g_Bt5);
    cudaGetSymbolAddress((void**)&WfYSB,  g_WfYS);
    cudaGetSymbolAddress((void**)&WcB,    g_Wc);
    cudaGetSymbolAddress((void**)&avfB,   g_avf);
    cudaGetSymbolAddress((void**)&av256B, g_av256);

    constexpr int SM_64_128 = (2 * 64 * 40 + 2 * 128 * 40) * 2 * 2;  // 61440
    constexpr int SM_64_64  = (2 * 64 * 40 + 2 * 64 * 40) * 2 * 2;   // 40960
    cudaFuncSetAttribute((void*)gemm_mma<64, 128, 0>, cudaFuncAttributeMaxDynamicSharedMemorySize, SM_64_128);
    cudaFuncSetAttribute((void*)gemm_mma<64, 128, 2>, cudaFuncAttributeMaxDynamicSharedMemorySize, SM_64_128);
    cudaFuncSetAttribute((void*)gemm_mma<64, 128, 3>, cudaFuncAttributeMaxDynamicSharedMemorySize, SM_64_128);
    cudaFuncSetAttribute((void*)gemm_mma<64, 64, 0>,  cudaFuncAttributeMaxDynamicSharedMemorySize, SM_64_64);

    dim3 blk(256);
    dim3 gN(Nn / 64, 2);
    dim3 gE(Ee / 64, 2);          // EW only (z=1)
    dim3 gH(Nn / 64, 1, Hh);      // L1 per-head (K=256)
    dim3 gH2(Nn / 64, 1, Hh);     // L0 per-head (K=64)

    cudaStream_t ms = 0;
    cudaStream_t s2 = g_ss.s;

    auto Bt5_   = [&](int mp) { return Bt5B   + (size_t)mp * 5 * Dd * Dd; };
    auto Wc_    = [&](int mp) { return WcB    + (size_t)mp * 2 * Dd * EDd; };
    auto WfYS_  = [&](int mp) { return WfYSB  + (size_t)mp * 2 * Dd * Dd; };
    auto avf_   = [&](int mp) { return avfB   + (size_t)mp * 2 * Hh * EDd; };
    auto av256_ = [&](int mp) { return av256B + (size_t)mp * 2 * Hh * Dd; };
    auto pn_    = [&](int mp) { return pnB + (size_t)mp * Nn * Hh; };
    auto ps_    = [&](int mp) { return psB + (size_t)mp * Nn * Hh; };
    auto be_    = [&](int mp) { return beB + (size_t)mp * Ee * Hh; };
    auto qe_    = [&](int mp) { return qeB + (size_t)mp * Ee * Hh; };
    auto Y_     = [&](int mp) { return YB + (size_t)mp * Nn * Dd; };
    auto EW_    = [&](int mp) { return EWB + (size_t)mp * Ee * Dd; };
    auto eB_    = [&](int mp) { return eBB + (size_t)mp * Ee * Dd; };
    auto nag_   = [&](int mp) { return nagB + (size_t)mp * Hh * Nn * Dd; };
    auto nagE_  = [&](int mp) { return nagEB + (size_t)mp * Nn * Dd; };
    auto NP_    = [&](int mp) { return NPB + (size_t)mp * Nn * Dd; };
    auto xb_    = [&](int mp) { return xB + (size_t)mp * Nn * Dd; };

    // full per-mp tail chain (all buffers per-mp => chains independent)
    auto chain = [&](int mp, cudaStream_t st) {
        const int* ena_mp = ena + (size_t)mp * Ee * 2;
        const int* n2e_mp = n2e + (size_t)mp * Nn * Kk;
        const float* emb_mp = edge_emb + (size_t)mp * Ee * EDd;
        float* outmp = out + (size_t)mp * Nn * DEPTHc * Dd;
        size_t pl1 = (size_t)(mp * DEPTHc + 1);

        edge_comb_q<<<Ee / 4, blk, 0, st>>>(ena_mp, pn_(mp), be_(mp), EW_(mp), Y_(mp),
                                            a_edge + pl1 * Hh * Dd, eB_(mp), be_(mp));
        // L0 node agg in embedding space + per-head projection GEMM
        nag64_kernel<<<Nn / 8, blk, 0, st>>>(n2e_mp, ps_(mp), qe_(mp), emb_mp, nagE_(mp));
        gemm_mma<64, 64, 0><<<gH2, blk, SM_64_64, st>>>(nagE_(mp), Wc_(mp) + (size_t)Dd * EDd, NP_(mp),
                                                        EDd, Dd, Dd,
                                                        (size_t)EDd, (size_t)PHp * EDd, (size_t)PHp,
                                                        nullptr, nullptr, nullptr, nullptr, nullptr);
        cudaMemsetAsync(ps_(mp), 0, (size_t)Nn * Hh * sizeof(float), st);
        gemm_mma<64, 128, 3><<<gN, blk, SM_64_128, st>>>(feats, WfYS_(mp) + Dd * Dd, nullptr,
                                                         Dd, Dd, Dd, 0, 0, 0,
                                                         a_s + pl1 * Hh * Dd, NP_(mp), outmp, xb_(mp), ps_(mp));
        nag_kernel<<<Nn / 8, blk, 0, st>>>(n2e_mp, ps_(mp), be_(mp), eB_(mp), nag_(mp));
        gemm_mma<64, 64, 0><<<gH, blk, SM_64_64, st>>>(nag_(mp), Bt5_(mp) + (size_t)4 * Dd * Dd, NP_(mp),
                                                       Dd, Dd, Dd,
                                                       (size_t)Nn * Dd, (size_t)PHp * Dd, (size_t)PHp,
                                                       nullptr, nullptr, nullptr, nullptr, nullptr);
        gemm_mma<64, 128, 2><<<gN, blk, SM_64_128, st>>>(xb_(mp), Bt5_(mp) + (size_t)3 * Dd * Dd, nullptr,
                                                         Dd, Dd, Dd, 0, 0, 0,
                                                         nullptr, NP_(mp), outmp, nullptr, nullptr);
    };

    // ---- s2: input-only folds first (no deps) ----
    for (int mp = 0; mp < NMPc; mp++) {
        size_t pl0 = (size_t)(mp * DEPTHc + 0);
        foldA2p<<<Hh, blk, 0, s2>>>(Wep + (size_t)mp * EDd * Dd,
                                    a_e + pl0 * Hh * Dd, a_edge + pl0 * Hh * Dd, avf_(mp));
    }

    // ---- ms: WpT -> mp0 weight folds -> mp0 front GEMMs ----
    pack2d2<<<dim3(256, 1, 2), blk, 0, ms>>>(Wp0, Wp1, WpT);
    cudaEventRecord(g_ss.evWpT, ms);

    pack_hdp5<<<dim3(256, 1, 5), blk, 0, ms>>>(W_e    + 0 * Hh * Dd * PHp,
                                               W_self + 0 * Hh * Dd * PHp,
                                               W_nb   + 0 * Hh * Dd * PHp,
                                               W_self + 1 * Hh * Dd * PHp,
                                               W_nb   + 1 * Hh * Dd * PHp, Bt5_(0));
    foldW256_2<<<dim3(256, 1, 2), blk, 0, ms>>>(WpT, Bt5_(0), WfYS_(0));
    foldW2<<<dim3(256, 1, 2), blk, 0, ms>>>(Wep, Bt5_(0), Wc_(0));

    gemm_mma<64, 128, 0><<<gN, blk, SM_64_128, ms>>>(feats, WfYS_(0), Y_(0), Dd, Dd, Dd, 0, 0, 0,
                                                     nullptr, nullptr, nullptr, nullptr, nullptr);
    gemm_mma<64, 128, 0><<<gE, blk, SM_64_128, ms>>>(edge_emb, Wc_(0), EW_(0), EDd, EDd, Dd, 0, 0, 0,
                                                     nullptr, nullptr, nullptr, nullptr, nullptr);
    cudaEventRecord(g_ss.evMS0, ms);

    // ---- s2: attention-vector folds + rowdots + mp1 weight folds + mp1 front GEMMs + mp1 chain ----
    cudaStreamWaitEvent(s2, g_ss.evWpT, 0);
    {
        size_t pl0m0 = 0, pl0m1 = (size_t)DEPTHc;
        foldA256_2<<<dim3(Hh, 1, 2), blk, 0, s2>>>(WpT, a_n + pl0m0 * Hh * Dd, a_s + pl0m0 * Hh * Dd, av256_(0));
        rowdot2<<<Nn / 8, blk, 0, s2>>>(feats, av256_(0), av256_(0) + Hh * Dd, pn_(0), ps_(0));
        rowdot2_64<<<Ee / 8, blk, 0, s2>>>(edge_emb, avf_(0), be_(0), qe_(0));
        cudaEventRecord(g_ss.evRD0, s2);

        foldA256_2<<<dim3(Hh, 1, 2), blk, 0, s2>>>(WpT, a_n + pl0m1 * Hh * Dd, a_s + pl0m1 * Hh * Dd, av256_(1));
        rowdot2<<<Nn / 8, blk, 0, s2>>>(feats, av256_(1), av256_(1) + Hh * Dd, pn_(1), ps_(1));
        rowdot2_64<<<Ee / 8, blk, 0, s2>>>(edge_emb + (size_t)Ee * EDd, avf_(1), be_(1), qe_(1));

        size_t pl0 = (size_t)DEPTHc, pl1 = (size_t)DEPTHc + 1;
        pack_hdp5<<<dim3(256, 1, 5), blk, 0, s2>>>(W_e    + pl0 * Hh * Dd * PHp,
                                                   W_self + pl0 * Hh * Dd * PHp,
                                                   W_nb   + pl0 * Hh * Dd * PHp,
                                                   W_self + pl1 * Hh * Dd * PHp,
                                                   W_nb   + pl1 * Hh * Dd * PHp, Bt5_(1));
        foldW256_2<<<dim3(256, 1, 2), blk, 0, s2>>>(WpT, Bt5_(1), WfYS_(1));
        foldW2<<<dim3(256, 1, 2), blk, 0, s2>>>(Wep + (size_t)EDd * Dd, Bt5_(1), Wc_(1));

        cudaStreamWaitEvent(s2, g_ss.evMS0, 0);
        gemm_mma<64, 128, 0><<<gN, blk, SM_64_128, s2>>>(feats, WfYS_(1), Y_(1), Dd, Dd, Dd, 0, 0, 0,
                                                         nullptr, nullptr, nullptr, nullptr, nullptr);
        gemm_mma<64, 128, 0><<<gE, blk, SM_64_128, s2>>>(edge_emb + (size_t)Ee * EDd, Wc_(1), EW_(1),
                                                         EDd, EDd, Dd, 0, 0, 0,
                                                         nullptr, nullptr, nullptr, nullptr, nullptr);
        // entire mp1 tail on s2 (co-runs with mp0 tail on ms)
        chain(1, s2);
        cudaEventRecord(g_ss.evEnd, s2);
    }

    // ---- ms: mp0 tail ----
    cudaStreamWaitEvent(ms, g_ss.evRD0, 0);
    chain(0, ms);

    // join s2 back into ms before capture ends
    cudaStreamWaitEvent(ms, g_ss.evEnd, 0);
}